// round 1
// baseline (speedup 1.0000x reference)
#include <cuda_runtime.h>
#include <math.h>

// ---------------- problem constants ----------------
#define B_    32
#define N_    64
#define T_    50
#define WD_   200
#define H_    128
#define G4_   512          // 4*H
#define D2_   256          // 2*H
#define BN_   2048         // B*N
#define MA_   102400       // BN*T  (stage-A GEMM rows)
#define C_    8

// ---------------- scratch (static __device__; no allocation allowed) ----------------
__device__ float g_sent_buf[2u * 52428800u];   // [dir][bn*T + t][512]   419 MB
__device__ float whhT_sent_buf[2 * 128 * 512]; // [dir][k][g]
__device__ float whhT_tag_buf[2 * 128 * 512];
__device__ float sentpres_buf[BN_ * D2_];
__device__ float q_buf[BN_ * D2_];
__device__ float k_buf[BN_ * D2_];
__device__ float sentFt_buf[BN_ * 15];
__device__ float roleFt_buf[BN_ * 15];
__device__ float g_tag_buf[2 * BN_ * G4_];     // [dir][n*32 + b][512]
__device__ float h_tag_buf[4 * 32 * 128];      // [buf(2)][dir(2)][32][128]
__device__ float c_tag_buf[2 * 32 * 128];      // [dir][32][128]
__device__ float tag_out_buf[BN_ * D2_];       // [b][n][256]
__device__ float agg_buf[BN_ * D2_];

__device__ __forceinline__ float sigf(float x) { return 1.0f / (1.0f + expf(-x)); }

// ================== generic tiled SGEMM: C[M,G] = A @ W^T + bias ==================
// A: row-major, row length K (amode=1: row m -> sentpres row (b*64+n), m = n*32+b)
// W: [G,K] row-major. BM=BG=64, BK=8. 256 threads, 4x4 per thread.
__global__ void sgemm_k(const float* __restrict__ A, const float* __restrict__ W,
                        const float* __restrict__ bias, float* __restrict__ C,
                        int M, int K, int G, int amode, int relu)
{
    __shared__ float As[8][64];
    __shared__ float Ws[8][64];
    int tid = threadIdx.x;
    int mb = blockIdx.y << 6;
    int gb = blockIdx.x << 6;
    int tx = tid & 15, ty = tid >> 4;
    int mi = tid & 63;
    int kh = (tid >> 6) << 1;

    int m = mb + mi;
    long arow;
    if (amode == 0) arow = (long)m * K;
    else { int b = m & 31; int n = m >> 5; arow = (long)((b << 6) + n) * K; }
    long wrow = (long)(gb + mi) * K;

    float acc[4][4];
#pragma unroll
    for (int i = 0; i < 4; i++)
#pragma unroll
        for (int j = 0; j < 4; j++) acc[i][j] = 0.0f;

    for (int k0 = 0; k0 < K; k0 += 8) {
        float2 av = *(const float2*)(A + arow + k0 + kh);
        float2 wv = *(const float2*)(W + wrow + k0 + kh);
        __syncthreads();
        As[kh][mi] = av.x; As[kh + 1][mi] = av.y;
        Ws[kh][mi] = wv.x; Ws[kh + 1][mi] = wv.y;
        __syncthreads();
#pragma unroll
        for (int kk = 0; kk < 8; kk++) {
            float4 a = *(float4*)(&As[kk][ty << 2]);
            float4 w = *(float4*)(&Ws[kk][tx << 2]);
            float aa[4] = {a.x, a.y, a.z, a.w};
            float ww[4] = {w.x, w.y, w.z, w.w};
#pragma unroll
            for (int i = 0; i < 4; i++)
#pragma unroll
                for (int j = 0; j < 4; j++) acc[i][j] += aa[i] * ww[j];
        }
    }

    float4 b4 = *(const float4*)(bias + gb + (tx << 2));
    float bb[4] = {b4.x, b4.y, b4.z, b4.w};
#pragma unroll
    for (int i = 0; i < 4; i++) {
        float4 r;
        r.x = acc[i][0] + bb[0];
        r.y = acc[i][1] + bb[1];
        r.z = acc[i][2] + bb[2];
        r.w = acc[i][3] + bb[3];
        if (relu) {
            r.x = fmaxf(r.x, 0.f); r.y = fmaxf(r.y, 0.f);
            r.z = fmaxf(r.z, 0.f); r.w = fmaxf(r.w, 0.f);
        }
        *(float4*)(C + (size_t)(mb + (ty << 2) + i) * G + gb + (tx << 2)) = r;
    }
}

// ================== transpose W_hh (512x128) -> W_hh^T (128x512), 2 dirs ==================
__global__ void transpose_whh(const float* __restrict__ wf, const float* __restrict__ wb,
                              float* __restrict__ outT)
{
    int dir = blockIdx.y;
    const float* w = dir ? wb : wf;
    float* o = outT + dir * 65536;
    for (int i = blockIdx.x * 256 + threadIdx.x; i < 65536; i += 64 * 256) {
        int k = i >> 9, g = i & 511;
        o[i] = w[g * 128 + k];
    }
}

// ================== sentence BiLSTM recurrence (persistent per block) ==================
// grid (64, 2): 32 batch rows per block, dir = blockIdx.y. 256 threads.
// smem: hT[128][36] + w_chunk[16][512] + gates[32][512]
#define LSTM_SMEM ((128 * 36 + 16 * 512 + 32 * 512) * 4)
__global__ void lstm_sent(const float* __restrict__ Gall, const float* __restrict__ whhT,
                          float* __restrict__ sentpres)
{
    extern __shared__ float sm[];
    float* sh_h = sm;                   // [k][r] padded: k*36 + r
    float* sh_w = sm + 128 * 36;        // [kk][g]: kk*512 + g
    float* sh_g = sh_w + 16 * 512;      // [r][g]: r*512 + g

    int dir = blockIdx.y;
    int r0 = blockIdx.x << 5;
    const float* Gd = Gall + (size_t)dir * 52428800u;
    const float* wT = whhT + dir * 65536;

    int tid = threadIdx.x;
    int tx = tid & 31;       // gate tile: gates tx*16..+15
    int ty = tid >> 5;       // row tile: rows ty*4..+3
    int ur = tid >> 3;       // update row 0..31
    int uj = (tid & 7) << 4; // update j base

    float c_reg[16], hs[16];
#pragma unroll
    for (int i = 0; i < 16; i++) { c_reg[i] = 0.f; hs[i] = 0.f; }
    for (int i = tid; i < 128 * 36; i += 256) sh_h[i] = 0.f;
    __syncthreads();

    for (int s = 0; s < T_; s++) {
        int t = dir ? (T_ - 1 - s) : s;
        float acc[4][16];
#pragma unroll
        for (int i = 0; i < 4; i++) {
            const float4* gp = (const float4*)(Gd + ((size_t)(r0 + (ty << 2) + i) * T_ + t) * 512 + (tx << 4));
#pragma unroll
            for (int q = 0; q < 4; q++) {
                float4 v = gp[q];
                acc[i][q * 4 + 0] = v.x; acc[i][q * 4 + 1] = v.y;
                acc[i][q * 4 + 2] = v.z; acc[i][q * 4 + 3] = v.w;
            }
        }
        for (int kc = 0; kc < 128; kc += 16) {
            // stage 16 rows of W_hh^T
            const float4* src = (const float4*)(wT + kc * 512);
            float4* dst = (float4*)sh_w;
            for (int l = tid; l < 2048; l += 256) dst[l] = src[l];
            __syncthreads();
#pragma unroll
            for (int kk = 0; kk < 16; kk++) {
                float4 hv = *(float4*)&sh_h[(kc + kk) * 36 + (ty << 2)];
                const float* wr = &sh_w[kk * 512 + (tx << 4)];
                float wv[16];
                *(float4*)&wv[0]  = *(const float4*)(wr);
                *(float4*)&wv[4]  = *(const float4*)(wr + 4);
                *(float4*)&wv[8]  = *(const float4*)(wr + 8);
                *(float4*)&wv[12] = *(const float4*)(wr + 12);
                float av[4] = {hv.x, hv.y, hv.z, hv.w};
#pragma unroll
                for (int i = 0; i < 4; i++)
#pragma unroll
                    for (int j = 0; j < 16; j++) acc[i][j] += av[i] * wv[j];
            }
            __syncthreads();
        }
        // gates -> smem
#pragma unroll
        for (int i = 0; i < 4; i++)
#pragma unroll
            for (int q = 0; q < 4; q++) {
                float4 v = make_float4(acc[i][q * 4], acc[i][q * 4 + 1], acc[i][q * 4 + 2], acc[i][q * 4 + 3]);
                *(float4*)&sh_g[((ty << 2) + i) * 512 + (tx << 4) + q * 4] = v;
            }
        __syncthreads();
        // state update (thread owns (ur, uj..uj+15))
#pragma unroll
        for (int jj = 0; jj < 16; jj++) {
            int j = uj + jj;
            float ig = sh_g[ur * 512 + j];
            float fg = sh_g[ur * 512 + 128 + j];
            float gg = sh_g[ur * 512 + 256 + j];
            float og = sh_g[ur * 512 + 384 + j];
            float cv = sigf(fg) * c_reg[jj] + sigf(ig) * tanhf(gg);
            c_reg[jj] = cv;
            float h = sigf(og) * tanhf(cv);
            hs[jj] += h;
            sh_h[j * 36 + ur] = h;
        }
        __syncthreads();
    }
    int bn = r0 + ur;
#pragma unroll
    for (int jj = 0; jj < 16; jj++)
        sentpres[bn * 256 + dir * 128 + uj + jj] = tanhf(hs[jj] * (1.0f / T_));
}

// ================== tag BiLSTM: one step per launch ==================
// grid (8, 2): block owns hidden slice j in [jb, jb+16). 256 threads.
#define TAG_SMEM ((32 * 128 + 128 * 64 + 32 * 64) * 4)
__global__ void lstm_tag_step(const float* __restrict__ Gt, const float* __restrict__ whhT,
                              float* __restrict__ h_buf, float* __restrict__ c_buf,
                              float* __restrict__ tag_out, int s)
{
    extern __shared__ float sm[];
    float* sh_h = sm;                 // [32][128]
    float* sh_w = sm + 32 * 128;      // [k][64]
    float* sh_g = sh_w + 128 * 64;    // [32][64]

    int dir = blockIdx.y;
    int jb = blockIdx.x << 4;
    int n = dir ? (63 - s) : s;
    const float* G = Gt + ((size_t)dir * 2048 + n * 32) * 512;
    const float* wT = whhT + dir * 65536;
    const float* hprev = h_buf + ((s & 1) * 2 + dir) * 4096;
    float* hnext = h_buf + (((s + 1) & 1) * 2 + dir) * 4096;
    float* cb = c_buf + dir * 4096;

    int tid = threadIdx.x;
    for (int i = tid; i < 4096; i += 256) sh_h[i] = (s == 0) ? 0.f : hprev[i];
    for (int i = tid; i < 128 * 64; i += 256) {
        int k = i >> 6; int col = i & 63; int grp = col >> 4; int jj = col & 15;
        sh_w[i] = wT[k * 512 + grp * 128 + jb + jj];
    }
    __syncthreads();

    int r = tid >> 3;
    int c0 = (tid & 7) << 3;
    float acc[8];
#pragma unroll
    for (int q = 0; q < 8; q++) {
        int col = c0 + q; int grp = col >> 4; int jj = col & 15;
        acc[q] = G[r * 512 + grp * 128 + jb + jj];
    }
    for (int k = 0; k < 128; k++) {
        float hv = sh_h[r * 128 + k];
        float4 wa = *(float4*)&sh_w[k * 64 + c0];
        float4 wb4 = *(float4*)&sh_w[k * 64 + c0 + 4];
        acc[0] += hv * wa.x;  acc[1] += hv * wa.y;
        acc[2] += hv * wa.z;  acc[3] += hv * wa.w;
        acc[4] += hv * wb4.x; acc[5] += hv * wb4.y;
        acc[6] += hv * wb4.z; acc[7] += hv * wb4.w;
    }
#pragma unroll
    for (int q = 0; q < 8; q++) sh_g[r * 64 + c0 + q] = acc[q];
    __syncthreads();

#pragma unroll
    for (int u = 0; u < 2; u++) {
        int e = tid * 2 + u;
        int ru = e >> 4; int jj = e & 15; int j = jb + jj;
        float ig = sh_g[ru * 64 + jj];
        float fg = sh_g[ru * 64 + 16 + jj];
        float gg = sh_g[ru * 64 + 32 + jj];
        float og = sh_g[ru * 64 + 48 + jj];
        float cp = (s == 0) ? 0.f : cb[ru * 128 + j];
        float cn = sigf(fg) * cp + sigf(ig) * tanhf(gg);
        cb[ru * 128 + j] = cn;
        float h = sigf(og) * tanhf(cn);
        hnext[ru * 128 + j] = h;
        tag_out[(size_t)(ru * 64 + n) * 256 + dir * 128 + j] = tanhf(h);
    }
}

// ================== SPP: scaled QK^T + pyramid max-pool -> 15 feats ==================
__global__ void spp_kernel(const float* __restrict__ q, const float* __restrict__ k,
                           float* __restrict__ out)
{
    int bn = blockIdx.x;
    int b = bn >> 6;
    __shared__ float shq[256];
    __shared__ float att[64];
    __shared__ float e8[8];
    int tid = threadIdx.x; // 64
    for (int l = tid; l < 256; l += 64) shq[l] = q[(size_t)bn * 256 + l];
    __syncthreads();
    const float* kr = k + (size_t)(b * 64 + tid) * 256;
    float s = 0.f;
    for (int l = 0; l < 256; l += 4) {
        float4 qa = *(float4*)&shq[l];
        float4 ka = *(const float4*)&kr[l];
        s += qa.x * ka.x + qa.y * ka.y + qa.z * ka.z + qa.w * ka.w;
    }
    att[tid] = s * 0.0625f; // 1/sqrt(256)
    __syncthreads();
    if (tid < 8) {
        float m = att[tid * 8];
#pragma unroll
        for (int l = 1; l < 8; l++) m = fmaxf(m, att[tid * 8 + l]);
        e8[tid] = m;
    }
    __syncthreads();
    if (tid == 0) {
        float q4[4];
#pragma unroll
        for (int l = 0; l < 4; l++) q4[l] = fmaxf(e8[2 * l], e8[2 * l + 1]);
        float h2a = fmaxf(q4[0], q4[1]);
        float h2b = fmaxf(q4[2], q4[3]);
        float* o = out + bn * 15;
        o[0] = fmaxf(h2a, h2b);
        o[1] = h2a; o[2] = h2b;
        o[3] = q4[0]; o[4] = q4[1]; o[5] = q4[2]; o[6] = q4[3];
#pragma unroll
        for (int l = 0; l < 8; l++) o[7 + l] = e8[l];
    }
}

// ================== GCN: cosine adjacency + aggregate ==================
#define GCN_SMEM ((64 * 256 + 64 * 64 + 64) * 4)
__global__ void gcn_kernel(const float* __restrict__ x, float* __restrict__ agg)
{
    extern __shared__ float gs[];
    float* shx = gs;            // [64][256]
    float* shc = gs + 16384;    // [64][64]
    float* shn = gs + 20480;    // [64]
    int b = blockIdx.x;
    int tid = threadIdx.x; // 256
    for (int l = tid; l < 16384; l += 256) shx[l] = x[(size_t)b * 16384 + l];
    __syncthreads();
    if (tid < 64) {
        float s = 0.f;
        for (int l = 0; l < 256; l++) { float v = shx[tid * 256 + l]; s += v * v; }
        shn[tid] = sqrtf(s) + 1e-8f;
    }
    __syncthreads();
    for (int p = tid; p < 4096; p += 256) {
        int i = p >> 6, j = p & 63;
        float s = 0.f;
        for (int l = 0; l < 256; l++) s += shx[i * 256 + l] * shx[j * 256 + l];
        shc[p] = s / (shn[i] * shn[j]);
    }
    __syncthreads();
    for (int p = tid; p < 16384; p += 256) {
        int i = p >> 8, d = p & 255;
        float s = 2.0f * shx[i * 256 + d];
        for (int j = 0; j < 64; j++) s += shc[i * 64 + j] * shx[j * 256 + d];
        agg[(size_t)b * 16384 + p] = s * (1.0f / 66.0f);
    }
}

// ================== classifier + log_softmax ==================
__global__ void cls_kernel(const float* __restrict__ tago, const float* __restrict__ sFt,
                           const float* __restrict__ rFt, const float* __restrict__ W,
                           const float* __restrict__ bias, float* __restrict__ out)
{
    int bn = blockIdx.x;
    int c = threadIdx.x; // 32 threads, 8 active
    __shared__ float sh[8];
    if (c < 8) {
        const float* w = W + c * 286;
        float s = bias[c];
        const float* t = tago + (size_t)bn * 256;
        for (int l = 0; l < 256; l++) s += t[l] * w[l];
        const float* sf = sFt + bn * 15;
        for (int l = 0; l < 15; l++) s += sf[l] * w[256 + l];
        const float* rf = rFt + bn * 15;
        for (int l = 0; l < 15; l++) s += rf[l] * w[271 + l];
        sh[c] = s;
    }
    __syncthreads();
    if (c < 8) {
        float m = sh[0];
#pragma unroll
        for (int l = 1; l < 8; l++) m = fmaxf(m, sh[l]);
        float se = 0.f;
#pragma unroll
        for (int l = 0; l < 8; l++) se += expf(sh[l] - m);
        out[bn * 8 + c] = sh[c] - m - logf(se);
    }
}

// ================== launch ==================
extern "C" void kernel_launch(void* const* d_in, const int* in_sizes, int n_in,
                              void* d_out, int out_size)
{
    const float* documents = (const float*)d_in[0];
    const float* sw_ih_f = (const float*)d_in[1];
    const float* sw_hh_f = (const float*)d_in[2];
    const float* sb_f    = (const float*)d_in[3];
    const float* sw_ih_b = (const float*)d_in[4];
    const float* sw_hh_b = (const float*)d_in[5];
    const float* sb_b    = (const float*)d_in[6];
    const float* sf_Wq = (const float*)d_in[7];
    const float* sf_bq = (const float*)d_in[8];
    const float* sf_Wk = (const float*)d_in[9];
    const float* sf_bk = (const float*)d_in[10];
    const float* rf_Wq = (const float*)d_in[11];
    const float* rf_bq = (const float*)d_in[12];
    const float* rf_Wk = (const float*)d_in[13];
    const float* rf_bk = (const float*)d_in[14];
    const float* tw_ih_f = (const float*)d_in[15];
    const float* tw_hh_f = (const float*)d_in[16];
    const float* tb_f    = (const float*)d_in[17];
    const float* tw_ih_b = (const float*)d_in[18];
    const float* tw_hh_b = (const float*)d_in[19];
    const float* tb_b    = (const float*)d_in[20];
    const float* sage_W = (const float*)d_in[21];
    const float* sage_b = (const float*)d_in[22];
    const float* cls_W  = (const float*)d_in[23];
    const float* cls_b  = (const float*)d_in[24];

    float* out = (float*)d_out;
    float* result_out = out;                 // (32,64,8)
    float* gcn_out = out + B_ * N_ * C_;     // (32,64,256)

    float *g_sent, *whhT_s, *whhT_t, *sentpres, *qb, *kb, *sFt, *rFt, *gtag, *htag, *ctag, *tago, *agg;
    cudaGetSymbolAddress((void**)&g_sent, g_sent_buf);
    cudaGetSymbolAddress((void**)&whhT_s, whhT_sent_buf);
    cudaGetSymbolAddress((void**)&whhT_t, whhT_tag_buf);
    cudaGetSymbolAddress((void**)&sentpres, sentpres_buf);
    cudaGetSymbolAddress((void**)&qb, q_buf);
    cudaGetSymbolAddress((void**)&kb, k_buf);
    cudaGetSymbolAddress((void**)&sFt, sentFt_buf);
    cudaGetSymbolAddress((void**)&rFt, roleFt_buf);
    cudaGetSymbolAddress((void**)&gtag, g_tag_buf);
    cudaGetSymbolAddress((void**)&htag, h_tag_buf);
    cudaGetSymbolAddress((void**)&ctag, c_tag_buf);
    cudaGetSymbolAddress((void**)&tago, tag_out_buf);
    cudaGetSymbolAddress((void**)&agg, agg_buf);

    cudaFuncSetAttribute(lstm_sent, cudaFuncAttributeMaxDynamicSharedMemorySize, LSTM_SMEM);
    cudaFuncSetAttribute(lstm_tag_step, cudaFuncAttributeMaxDynamicSharedMemorySize, TAG_SMEM);
    cudaFuncSetAttribute(gcn_kernel, cudaFuncAttributeMaxDynamicSharedMemorySize, GCN_SMEM);

    // Stage A: input projections for sentence LSTM (both dirs)
    sgemm_k<<<dim3(8, 1600), 256>>>(documents, sw_ih_f, sb_f, g_sent,            MA_, WD_, G4_, 0, 0);
    sgemm_k<<<dim3(8, 1600), 256>>>(documents, sw_ih_b, sb_b, g_sent + 52428800u, MA_, WD_, G4_, 0, 0);

    transpose_whh<<<dim3(64, 2), 256>>>(sw_hh_f, sw_hh_b, whhT_s);
    transpose_whh<<<dim3(64, 2), 256>>>(tw_hh_f, tw_hh_b, whhT_t);

    // Sentence BiLSTM recurrence -> sentpres
    lstm_sent<<<dim3(64, 2), 256, LSTM_SMEM>>>(g_sent, whhT_s, sentpres);

    // sentFt SPP
    sgemm_k<<<dim3(4, 32), 256>>>(sentpres, sf_Wq, sf_bq, qb, BN_, D2_, D2_, 0, 0);
    sgemm_k<<<dim3(4, 32), 256>>>(sentpres, sf_Wk, sf_bk, kb, BN_, D2_, D2_, 0, 0);
    spp_kernel<<<2048, 64>>>(qb, kb, sFt);

    // Tag LSTM input projections (rows m = n*32 + b, gathered from sentpres)
    sgemm_k<<<dim3(8, 32), 256>>>(sentpres, tw_ih_f, tb_f, gtag,              BN_, D2_, G4_, 1, 0);
    sgemm_k<<<dim3(8, 32), 256>>>(sentpres, tw_ih_b, tb_b, gtag + BN_ * G4_,  BN_, D2_, G4_, 1, 0);

    // Tag BiLSTM recurrence: 64 sequential step launches (both dirs per launch)
    for (int s = 0; s < 64; s++)
        lstm_tag_step<<<dim3(8, 2), 256, TAG_SMEM>>>(gtag, whhT_t, htag, ctag, tago, s);

    // GCN
    gcn_kernel<<<32, 256, GCN_SMEM>>>(tago, agg);
    sgemm_k<<<dim3(4, 32), 256>>>(agg, sage_W, sage_b, gcn_out, BN_, D2_, D2_, 0, 1);

    // roleFt SPP
    sgemm_k<<<dim3(4, 32), 256>>>(tago, rf_Wq, rf_bq, qb, BN_, D2_, D2_, 0, 0);
    sgemm_k<<<dim3(4, 32), 256>>>(tago, rf_Wk, rf_bk, kb, BN_, D2_, D2_, 0, 0);
    spp_kernel<<<2048, 64>>>(qb, kb, rFt);

    // classifier + log_softmax
    cls_kernel<<<2048, 32>>>(tago, sFt, rFt, cls_W, cls_b, result_out);

    (void)in_sizes; (void)n_in; (void)out_size;
}

// round 3
// speedup vs baseline: 1.6884x; 1.6884x over previous
#include <cuda_runtime.h>
#include <cuda_bf16.h>
#include <stdint.h>
#include <math.h>

// ---------------- problem constants ----------------
#define B_    32
#define N_    64
#define T_    50
#define WD_   200
#define H_    128
#define G4_   512          // 4*H
#define D2_   256          // 2*H
#define BN_   2048         // B*N
#define MA_   102400       // BN*T  (stage-A GEMM rows)
#define C_    8
#define KP_   208          // padded K for stage-A (13*16)

// ---------------- scratch (static __device__; no allocation allowed) ----------------
__device__ float g_sent_buf[2u * 52428800u];   // [dir][bn*T + t][512]
__device__ __nv_bfloat16 a_hi_buf[(size_t)MA_ * KP_];
__device__ __nv_bfloat16 a_lo_buf[(size_t)MA_ * KP_];
__device__ __nv_bfloat16 w_hi_buf[2 * G4_ * KP_];
__device__ __nv_bfloat16 w_lo_buf[2 * G4_ * KP_];
__device__ float whhT_sent_buf[2 * 128 * 512]; // [dir][k][g]
__device__ float whhT_tag_buf[2 * 128 * 512];
__device__ float sentpres_buf[BN_ * D2_];
__device__ float q_buf[BN_ * D2_];
__device__ float k_buf[BN_ * D2_];
__device__ float sentFt_buf[BN_ * 15];
__device__ float roleFt_buf[BN_ * 15];
__device__ float g_tag_buf[2 * BN_ * G4_];
__device__ float h_tag_buf[4 * 32 * 128];
__device__ float c_tag_buf[2 * 32 * 128];
__device__ float tag_out_buf[BN_ * D2_];
__device__ float agg_buf[BN_ * D2_];

__device__ __forceinline__ float sigf(float x) { return 1.0f / (1.0f + expf(-x)); }

// ================== hi/lo bf16 split conversions ==================
__global__ void cvt_split_doc(const float* __restrict__ A,
                              __nv_bfloat16* __restrict__ hi, __nv_bfloat16* __restrict__ lo)
{
    size_t i = (size_t)blockIdx.x * 256 + threadIdx.x; // over MA_*KP_
    int m = (int)(i / KP_), k = (int)(i % KP_);
    float x = (k < WD_) ? A[(size_t)m * WD_ + k] : 0.f;
    __nv_bfloat16 h = __float2bfloat16(x);
    hi[i] = h;
    lo[i] = __float2bfloat16(x - __bfloat162float(h));
}

__global__ void cvt_split_w(const float* __restrict__ wf, const float* __restrict__ wb,
                            __nv_bfloat16* __restrict__ hi, __nv_bfloat16* __restrict__ lo)
{
    int i = blockIdx.x * 256 + threadIdx.x;
    if (i >= 2 * G4_ * KP_) return;
    int dir = i / (G4_ * KP_); int rem = i - dir * (G4_ * KP_);
    int g = rem / KP_, k = rem % KP_;
    const float* w = dir ? wb : wf;
    float x = (k < WD_) ? w[g * WD_ + k] : 0.f;
    __nv_bfloat16 h = __float2bfloat16(x);
    hi[i] = h;
    lo[i] = __float2bfloat16(x - __bfloat162float(h));
}

// ================== stage-A GEMM on tensor cores (bf16 hi/lo) ==================
// C[M,512] = A[M,208] @ W^T[208,512] + bias.  BM=128, BN=128, BK=16, 256 thr / 8 warps.
#define MMA_OP(d, a, b) \
    asm volatile("mma.sync.aligned.m16n8k16.row.col.f32.bf16.bf16.f32 " \
                 "{%0,%1,%2,%3},{%4,%5,%6,%7},{%8,%9},{%0,%1,%2,%3};\n" \
                 : "+f"(d[0]), "+f"(d[1]), "+f"(d[2]), "+f"(d[3]) \
                 : "r"(a[0]), "r"(a[1]), "r"(a[2]), "r"(a[3]), "r"(b[0]), "r"(b[1]))

__global__ void mma_gemmA(const __nv_bfloat16* __restrict__ ahi, const __nv_bfloat16* __restrict__ alo,
                          const __nv_bfloat16* __restrict__ whi, const __nv_bfloat16* __restrict__ wlo,
                          const float* __restrict__ bias, float* __restrict__ C)
{
    __shared__ __nv_bfloat16 sA[2][128 * 16];
    __shared__ __nv_bfloat16 sB[2][128 * 16];
    int tid = threadIdx.x;
    int lane = tid & 31, wid = tid >> 5;
    int wm = wid & 3, wn = wid >> 2;
    int mb = blockIdx.y << 7, nb = blockIdx.x << 7;
    int lr = tid >> 1, lk = (tid & 1) << 3;
    int r = lane >> 2, c2 = (lane & 3) << 1;

    float acc[2][8][4];
#pragma unroll
    for (int mi = 0; mi < 2; mi++)
#pragma unroll
        for (int ni = 0; ni < 8; ni++)
#pragma unroll
            for (int e = 0; e < 4; e++) acc[mi][ni][e] = 0.f;

    for (int kb = 0; kb < KP_; kb += 16) {
        __syncthreads();
        *(uint4*)&sA[0][lr * 16 + lk] = *(const uint4*)(ahi + (size_t)(mb + lr) * KP_ + kb + lk);
        *(uint4*)&sA[1][lr * 16 + lk] = *(const uint4*)(alo + (size_t)(mb + lr) * KP_ + kb + lk);
        *(uint4*)&sB[0][lr * 16 + lk] = *(const uint4*)(whi + (size_t)(nb + lr) * KP_ + kb + lk);
        *(uint4*)&sB[1][lr * 16 + lk] = *(const uint4*)(wlo + (size_t)(nb + lr) * KP_ + kb + lk);
        __syncthreads();

        unsigned ah[2][4], al[2][4];
#pragma unroll
        for (int mi = 0; mi < 2; mi++) {
            int rb = (wm * 32 + mi * 16 + r) * 16;
            ah[mi][0] = *(unsigned*)&sA[0][rb + c2];
            ah[mi][1] = *(unsigned*)&sA[0][rb + 128 + c2];
            ah[mi][2] = *(unsigned*)&sA[0][rb + c2 + 8];
            ah[mi][3] = *(unsigned*)&sA[0][rb + 128 + c2 + 8];
            al[mi][0] = *(unsigned*)&sA[1][rb + c2];
            al[mi][1] = *(unsigned*)&sA[1][rb + 128 + c2];
            al[mi][2] = *(unsigned*)&sA[1][rb + c2 + 8];
            al[mi][3] = *(unsigned*)&sA[1][rb + 128 + c2 + 8];
        }
#pragma unroll
        for (int ni = 0; ni < 8; ni++) {
            int nbase = (wn * 64 + ni * 8 + r) * 16;
            unsigned bh[2], bl[2];
            bh[0] = *(unsigned*)&sB[0][nbase + c2];
            bh[1] = *(unsigned*)&sB[0][nbase + c2 + 8];
            bl[0] = *(unsigned*)&sB[1][nbase + c2];
            bl[1] = *(unsigned*)&sB[1][nbase + c2 + 8];
#pragma unroll
            for (int mi = 0; mi < 2; mi++) {
                MMA_OP(acc[mi][ni], ah[mi], bh);
                MMA_OP(acc[mi][ni], al[mi], bh);
                MMA_OP(acc[mi][ni], ah[mi], bl);
            }
        }
    }
    // epilogue
#pragma unroll
    for (int mi = 0; mi < 2; mi++) {
#pragma unroll
        for (int ni = 0; ni < 8; ni++) {
            int grow = mb + wm * 32 + mi * 16 + r;
            int gcol = nb + wn * 64 + ni * 8 + c2;
            float b0 = bias[gcol], b1 = bias[gcol + 1];
            float2 v0 = make_float2(acc[mi][ni][0] + b0, acc[mi][ni][1] + b1);
            float2 v1 = make_float2(acc[mi][ni][2] + b0, acc[mi][ni][3] + b1);
            *(float2*)&C[(size_t)grow * 512 + gcol] = v0;
            *(float2*)&C[(size_t)(grow + 8) * 512 + gcol] = v1;
        }
    }
}

// ================== generic tiled SGEMM (small GEMMs) ==================
__global__ void sgemm_k(const float* __restrict__ A, const float* __restrict__ W,
                        const float* __restrict__ bias, float* __restrict__ C,
                        int M, int K, int G, int amode, int relu)
{
    __shared__ float As[8][64];
    __shared__ float Ws[8][64];
    int tid = threadIdx.x;
    int mb = blockIdx.y << 6;
    int gb = blockIdx.x << 6;
    int tx = tid & 15, ty = tid >> 4;
    int mi = tid & 63;
    int kh = (tid >> 6) << 1;

    int m = mb + mi;
    long arow;
    if (amode == 0) arow = (long)m * K;
    else { int b = m & 31; int n = m >> 5; arow = (long)((b << 6) + n) * K; }
    long wrow = (long)(gb + mi) * K;

    float acc[4][4];
#pragma unroll
    for (int i = 0; i < 4; i++)
#pragma unroll
        for (int j = 0; j < 4; j++) acc[i][j] = 0.0f;

    for (int k0 = 0; k0 < K; k0 += 8) {
        float2 av = *(const float2*)(A + arow + k0 + kh);
        float2 wv = *(const float2*)(W + wrow + k0 + kh);
        __syncthreads();
        As[kh][mi] = av.x; As[kh + 1][mi] = av.y;
        Ws[kh][mi] = wv.x; Ws[kh + 1][mi] = wv.y;
        __syncthreads();
#pragma unroll
        for (int kk = 0; kk < 8; kk++) {
            float4 a = *(float4*)(&As[kk][ty << 2]);
            float4 w = *(float4*)(&Ws[kk][tx << 2]);
            float aa[4] = {a.x, a.y, a.z, a.w};
            float ww[4] = {w.x, w.y, w.z, w.w};
#pragma unroll
            for (int i = 0; i < 4; i++)
#pragma unroll
                for (int j = 0; j < 4; j++) acc[i][j] += aa[i] * ww[j];
        }
    }

    float4 b4 = *(const float4*)(bias + gb + (tx << 2));
    float bb[4] = {b4.x, b4.y, b4.z, b4.w};
#pragma unroll
    for (int i = 0; i < 4; i++) {
        float4 r;
        r.x = acc[i][0] + bb[0];
        r.y = acc[i][1] + bb[1];
        r.z = acc[i][2] + bb[2];
        r.w = acc[i][3] + bb[3];
        if (relu) {
            r.x = fmaxf(r.x, 0.f); r.y = fmaxf(r.y, 0.f);
            r.z = fmaxf(r.z, 0.f); r.w = fmaxf(r.w, 0.f);
        }
        *(float4*)(C + (size_t)(mb + (ty << 2) + i) * G + gb + (tx << 2)) = r;
    }
}

// ================== transpose W_hh (512x128) -> W_hh^T (128x512), 2 dirs ==================
__global__ void transpose_whh(const float* __restrict__ wf, const float* __restrict__ wb,
                              float* __restrict__ outT)
{
    int dir = blockIdx.y;
    const float* w = dir ? wb : wf;
    float* o = outT + dir * 65536;
    for (int i = blockIdx.x * 256 + threadIdx.x; i < 65536; i += 64 * 256) {
        int k = i >> 9, g = i & 511;
        o[i] = w[g * 128 + k];
    }
}

// ================== sentence BiLSTM recurrence v2 (conflict-free, reg-resident gates) ==================
// grid (64, 2): 32 batch rows per block. 256 threads: ty=tid>>5 (4 rows), tx=tid&31 (cols tx*4+128q)
#define LSTM2_SMEM ((32 * 132 + 2 * 16 * 512) * 4)
__global__ void lstm_sent2(const float* __restrict__ Gall, const float* __restrict__ whhT,
                           float* __restrict__ sentpres)
{
    extern __shared__ float sm[];
    float* sh_h = sm;                 // [32][132]
    float* sh_w = sm + 32 * 132;      // [2][16][512] double-buffered chunks

    int dir = blockIdx.y;
    int r0 = blockIdx.x << 5;
    const float* Gd = Gall + (size_t)dir * 52428800u;
    const float* wT = whhT + dir * 65536;

    int tid = threadIdx.x;
    int tx = tid & 31;
    int ty = tid >> 5;

    float c_reg[4][4], hs[4][4];
#pragma unroll
    for (int i = 0; i < 4; i++)
#pragma unroll
        for (int e = 0; e < 4; e++) { c_reg[i][e] = 0.f; hs[i][e] = 0.f; }

    for (int i = tid; i < 32 * 132; i += 256) sh_h[i] = 0.f;
    // prefetch W chunk 0 into buffer 0
    {
        const float4* src = (const float4*)wT;
        float4* dst = (float4*)sh_w;
        for (int l = tid; l < 2048; l += 256) dst[l] = src[l];
    }
    __syncthreads();

    for (int s = 0; s < T_; s++) {
        int t = dir ? (T_ - 1 - s) : s;
        float acc[4][16];
#pragma unroll
        for (int i = 0; i < 4; i++) {
            const float* gp = Gd + ((size_t)(r0 + ty * 4 + i) * T_ + t) * 512 + tx * 4;
#pragma unroll
            for (int q = 0; q < 4; q++) {
                float4 v = *(const float4*)(gp + 128 * q);
                acc[i][q * 4 + 0] = v.x; acc[i][q * 4 + 1] = v.y;
                acc[i][q * 4 + 2] = v.z; acc[i][q * 4 + 3] = v.w;
            }
        }
#pragma unroll 1
        for (int ch = 0; ch < 8; ch++) {
            int buf = ch & 1;
            // prefetch next chunk (wraps: chunk 0 for next step)
            {
                int nch = (ch + 1) & 7;
                const float4* src = (const float4*)(wT + nch * 16 * 512);
                float4* dst = (float4*)(sh_w + (buf ^ 1) * 8192);
#pragma unroll
                for (int l = 0; l < 8; l++) dst[tid + l * 256] = src[tid + l * 256];
            }
            int kc = ch * 16;
            const float* wbase = sh_w + buf * 8192;
#pragma unroll
            for (int kk4 = 0; kk4 < 16; kk4 += 4) {
                float4 hv4[4];
#pragma unroll
                for (int i = 0; i < 4; i++)
                    hv4[i] = *(float4*)&sh_h[(ty * 4 + i) * 132 + kc + kk4];
#pragma unroll
                for (int kk = 0; kk < 4; kk++) {
                    float wv[16];
                    const float* wr = wbase + (kk4 + kk) * 512 + tx * 4;
                    *(float4*)&wv[0]  = *(const float4*)(wr);
                    *(float4*)&wv[4]  = *(const float4*)(wr + 128);
                    *(float4*)&wv[8]  = *(const float4*)(wr + 256);
                    *(float4*)&wv[12] = *(const float4*)(wr + 384);
                    float hv[4] = {(&hv4[0].x)[kk], (&hv4[1].x)[kk], (&hv4[2].x)[kk], (&hv4[3].x)[kk]};
#pragma unroll
                    for (int i = 0; i < 4; i++)
#pragma unroll
                        for (int j = 0; j < 16; j++) acc[i][j] += hv[i] * wv[j];
                }
            }
            __syncthreads();
        }
        // state update, all in registers; h -> sh_h (row-major, conflict-free STS.128)
#pragma unroll
        for (int i = 0; i < 4; i++) {
            float hrow[4];
#pragma unroll
            for (int e = 0; e < 4; e++) {
                float ig = acc[i][e];
                float fg = acc[i][4 + e];
                float gg = acc[i][8 + e];
                float og = acc[i][12 + e];
                float cv = sigf(fg) * c_reg[i][e] + sigf(ig) * tanhf(gg);
                c_reg[i][e] = cv;
                float h = sigf(og) * tanhf(cv);
                hs[i][e] += h;
                hrow[e] = h;
            }
            *(float4*)&sh_h[(ty * 4 + i) * 132 + tx * 4] = make_float4(hrow[0], hrow[1], hrow[2], hrow[3]);
        }
        __syncthreads();
    }
#pragma unroll
    for (int i = 0; i < 4; i++) {
        int bn = r0 + ty * 4 + i;
        float4 o;
        o.x = tanhf(hs[i][0] * (1.0f / T_));
        o.y = tanhf(hs[i][1] * (1.0f / T_));
        o.z = tanhf(hs[i][2] * (1.0f / T_));
        o.w = tanhf(hs[i][3] * (1.0f / T_));
        *(float4*)&sentpres[bn * 256 + dir * 128 + tx * 4] = o;
    }
}

// ================== tag BiLSTM: one step per launch ==================
#define TAG_SMEM ((32 * 128 + 128 * 64 + 32 * 64) * 4)
__global__ void lstm_tag_step(const float* __restrict__ Gt, const float* __restrict__ whhT,
                              float* __restrict__ h_buf, float* __restrict__ c_buf,
                              float* __restrict__ tag_out, int s)
{
    extern __shared__ float sm[];
    float* sh_h = sm;
    float* sh_w = sm + 32 * 128;
    float* sh_g = sh_w + 128 * 64;

    int dir = blockIdx.y;
    int jb = blockIdx.x << 4;
    int n = dir ? (63 - s) : s;
    const float* G = Gt + ((size_t)dir * 2048 + n * 32) * 512;
    const float* wT = whhT + dir * 65536;
    const float* hprev = h_buf + ((s & 1) * 2 + dir) * 4096;
    float* hnext = h_buf + (((s + 1) & 1) * 2 + dir) * 4096;
    float* cb = c_buf + dir * 4096;

    int tid = threadIdx.x;
    for (int i = tid; i < 4096; i += 256) sh_h[i] = (s == 0) ? 0.f : hprev[i];
    for (int i = tid; i < 128 * 64; i += 256) {
        int k = i >> 6; int col = i & 63; int grp = col >> 4; int jj = col & 15;
        sh_w[i] = wT[k * 512 + grp * 128 + jb + jj];
    }
    __syncthreads();

    int r = tid >> 3;
    int c0 = (tid & 7) << 3;
    float acc[8];
#pragma unroll
    for (int q = 0; q < 8; q++) {
        int col = c0 + q; int grp = col >> 4; int jj = col & 15;
        acc[q] = G[r * 512 + grp * 128 + jb + jj];
    }
    for (int k = 0; k < 128; k++) {
        float hv = sh_h[r * 128 + k];
        float4 wa = *(float4*)&sh_w[k * 64 + c0];
        float4 wb4 = *(float4*)&sh_w[k * 64 + c0 + 4];
        acc[0] += hv * wa.x;  acc[1] += hv * wa.y;
        acc[2] += hv * wa.z;  acc[3] += hv * wa.w;
        acc[4] += hv * wb4.x; acc[5] += hv * wb4.y;
        acc[6] += hv * wb4.z; acc[7] += hv * wb4.w;
    }
#pragma unroll
    for (int q = 0; q < 8; q++) sh_g[r * 64 + c0 + q] = acc[q];
    __syncthreads();

#pragma unroll
    for (int u = 0; u < 2; u++) {
        int e = tid * 2 + u;
        int ru = e >> 4; int jj = e & 15; int j = jb + jj;
        float ig = sh_g[ru * 64 + jj];
        float fg = sh_g[ru * 64 + 16 + jj];
        float gg = sh_g[ru * 64 + 32 + jj];
        float og = sh_g[ru * 64 + 48 + jj];
        float cp = (s == 0) ? 0.f : cb[ru * 128 + j];
        float cn = sigf(fg) * cp + sigf(ig) * tanhf(gg);
        cb[ru * 128 + j] = cn;
        float h = sigf(og) * tanhf(cn);
        hnext[ru * 128 + j] = h;
        tag_out[(size_t)(ru * 64 + n) * 256 + dir * 128 + j] = tanhf(h);
    }
}

// ================== SPP ==================
__global__ void spp_kernel(const float* __restrict__ q, const float* __restrict__ k,
                           float* __restrict__ out)
{
    int bn = blockIdx.x;
    int b = bn >> 6;
    __shared__ float shq[256];
    __shared__ float att[64];
    __shared__ float e8[8];
    int tid = threadIdx.x;
    for (int l = tid; l < 256; l += 64) shq[l] = q[(size_t)bn * 256 + l];
    __syncthreads();
    const float* kr = k + (size_t)(b * 64 + tid) * 256;
    float s = 0.f;
    for (int l = 0; l < 256; l += 4) {
        float4 qa = *(float4*)&shq[l];
        float4 ka = *(const float4*)&kr[l];
        s += qa.x * ka.x + qa.y * ka.y + qa.z * ka.z + qa.w * ka.w;
    }
    att[tid] = s * 0.0625f;
    __syncthreads();
    if (tid < 8) {
        float m = att[tid * 8];
#pragma unroll
        for (int l = 1; l < 8; l++) m = fmaxf(m, att[tid * 8 + l]);
        e8[tid] = m;
    }
    __syncthreads();
    if (tid == 0) {
        float q4[4];
#pragma unroll
        for (int l = 0; l < 4; l++) q4[l] = fmaxf(e8[2 * l], e8[2 * l + 1]);
        float h2a = fmaxf(q4[0], q4[1]);
        float h2b = fmaxf(q4[2], q4[3]);
        float* o = out + bn * 15;
        o[0] = fmaxf(h2a, h2b);
        o[1] = h2a; o[2] = h2b;
        o[3] = q4[0]; o[4] = q4[1]; o[5] = q4[2]; o[6] = q4[3];
#pragma unroll
        for (int l = 0; l < 8; l++) o[7 + l] = e8[l];
    }
}

// ================== GCN ==================
#define GCN_SMEM ((64 * 256 + 64 * 64 + 64) * 4)
__global__ void gcn_kernel(const float* __restrict__ x, float* __restrict__ agg)
{
    extern __shared__ float gs[];
    float* shx = gs;
    float* shc = gs + 16384;
    float* shn = gs + 20480;
    int b = blockIdx.x;
    int tid = threadIdx.x;
    for (int l = tid; l < 16384; l += 256) shx[l] = x[(size_t)b * 16384 + l];
    __syncthreads();
    if (tid < 64) {
        float s = 0.f;
        for (int l = 0; l < 256; l++) { float v = shx[tid * 256 + l]; s += v * v; }
        shn[tid] = sqrtf(s) + 1e-8f;
    }
    __syncthreads();
    for (int p = tid; p < 4096; p += 256) {
        int i = p >> 6, j = p & 63;
        float s = 0.f;
        for (int l = 0; l < 256; l++) s += shx[i * 256 + l] * shx[j * 256 + l];
        shc[p] = s / (shn[i] * shn[j]);
    }
    __syncthreads();
    for (int p = tid; p < 16384; p += 256) {
        int i = p >> 8, d = p & 255;
        float s = 2.0f * shx[i * 256 + d];
        for (int j = 0; j < 64; j++) s += shc[i * 64 + j] * shx[j * 256 + d];
        agg[(size_t)b * 16384 + p] = s * (1.0f / 66.0f);
    }
}

// ================== classifier + log_softmax ==================
__global__ void cls_kernel(const float* __restrict__ tago, const float* __restrict__ sFt,
                           const float* __restrict__ rFt, const float* __restrict__ W,
                           const float* __restrict__ bias, float* __restrict__ out)
{
    int bn = blockIdx.x;
    int c = threadIdx.x;
    __shared__ float sh[8];
    if (c < 8) {
        const float* w = W + c * 286;
        float s = bias[c];
        const float* t = tago + (size_t)bn * 256;
        for (int l = 0; l < 256; l++) s += t[l] * w[l];
        const float* sf = sFt + bn * 15;
        for (int l = 0; l < 15; l++) s += sf[l] * w[256 + l];
        const float* rf = rFt + bn * 15;
        for (int l = 0; l < 15; l++) s += rf[l] * w[271 + l];
        sh[c] = s;
    }
    __syncthreads();
    if (c < 8) {
        float m = sh[0];
#pragma unroll
        for (int l = 1; l < 8; l++) m = fmaxf(m, sh[l]);
        float se = 0.f;
#pragma unroll
        for (int l = 0; l < 8; l++) se += expf(sh[l] - m);
        out[bn * 8 + c] = sh[c] - m - logf(se);
    }
}

// ================== launch ==================
extern "C" void kernel_launch(void* const* d_in, const int* in_sizes, int n_in,
                              void* d_out, int out_size)
{
    const float* documents = (const float*)d_in[0];
    const float* sw_ih_f = (const float*)d_in[1];
    const float* sw_hh_f = (const float*)d_in[2];
    const float* sb_f    = (const float*)d_in[3];
    const float* sw_ih_b = (const float*)d_in[4];
    const float* sw_hh_b = (const float*)d_in[5];
    const float* sb_b    = (const float*)d_in[6];
    const float* sf_Wq = (const float*)d_in[7];
    const float* sf_bq = (const float*)d_in[8];
    const float* sf_Wk = (const float*)d_in[9];
    const float* sf_bk = (const float*)d_in[10];
    const float* rf_Wq = (const float*)d_in[11];
    const float* rf_bq = (const float*)d_in[12];
    const float* rf_Wk = (const float*)d_in[13];
    const float* rf_bk = (const float*)d_in[14];
    const float* tw_ih_f = (const float*)d_in[15];
    const float* tw_hh_f = (const float*)d_in[16];
    const float* tb_f    = (const float*)d_in[17];
    const float* tw_ih_b = (const float*)d_in[18];
    const float* tw_hh_b = (const float*)d_in[19];
    const float* tb_b    = (const float*)d_in[20];
    const float* sage_W = (const float*)d_in[21];
    const float* sage_b = (const float*)d_in[22];
    const float* cls_W  = (const float*)d_in[23];
    const float* cls_b  = (const float*)d_in[24];

    float* out = (float*)d_out;
    float* result_out = out;
    float* gcn_out = out + B_ * N_ * C_;

    float *g_sent, *whhT_s, *whhT_t, *sentpres, *qb, *kb, *sFt, *rFt, *gtag, *htag, *ctag, *tago, *agg;
    __nv_bfloat16 *ahi, *alo, *whi, *wlo;
    cudaGetSymbolAddress((void**)&g_sent, g_sent_buf);
    cudaGetSymbolAddress((void**)&ahi, a_hi_buf);
    cudaGetSymbolAddress((void**)&alo, a_lo_buf);
    cudaGetSymbolAddress((void**)&whi, w_hi_buf);
    cudaGetSymbolAddress((void**)&wlo, w_lo_buf);
    cudaGetSymbolAddress((void**)&whhT_s, whhT_sent_buf);
    cudaGetSymbolAddress((void**)&whhT_t, whhT_tag_buf);
    cudaGetSymbolAddress((void**)&sentpres, sentpres_buf);
    cudaGetSymbolAddress((void**)&qb, q_buf);
    cudaGetSymbolAddress((void**)&kb, k_buf);
    cudaGetSymbolAddress((void**)&sFt, sentFt_buf);
    cudaGetSymbolAddress((void**)&rFt, roleFt_buf);
    cudaGetSymbolAddress((void**)&gtag, g_tag_buf);
    cudaGetSymbolAddress((void**)&htag, h_tag_buf);
    cudaGetSymbolAddress((void**)&ctag, c_tag_buf);
    cudaGetSymbolAddress((void**)&tago, tag_out_buf);
    cudaGetSymbolAddress((void**)&agg, agg_buf);

    cudaFuncSetAttribute(lstm_sent2, cudaFuncAttributeMaxDynamicSharedMemorySize, LSTM2_SMEM);
    cudaFuncSetAttribute(lstm_tag_step, cudaFuncAttributeMaxDynamicSharedMemorySize, TAG_SMEM);
    cudaFuncSetAttribute(gcn_kernel, cudaFuncAttributeMaxDynamicSharedMemorySize, GCN_SMEM);

    // hi/lo conversions
    cvt_split_doc<<<(int)(((size_t)MA_ * KP_) / 256), 256>>>(documents, ahi, alo);
    cvt_split_w<<<(2 * G4_ * KP_ + 255) / 256, 256>>>(sw_ih_f, sw_ih_b, whi, wlo);

    transpose_whh<<<dim3(64, 2), 256>>>(sw_hh_f, sw_hh_b, whhT_s);
    transpose_whh<<<dim3(64, 2), 256>>>(tw_hh_f, tw_hh_b, whhT_t);

    // Stage A on tensor cores (both dirs)
    mma_gemmA<<<dim3(4, 800), 256>>>(ahi, alo, whi, wlo, sb_f, g_sent);
    mma_gemmA<<<dim3(4, 800), 256>>>(ahi, alo, whi + G4_ * KP_, wlo + G4_ * KP_, sb_b, g_sent + 52428800u);

    // Sentence BiLSTM recurrence -> sentpres
    lstm_sent2<<<dim3(64, 2), 256, LSTM2_SMEM>>>(g_sent, whhT_s, sentpres);

    // sentFt SPP
    sgemm_k<<<dim3(4, 32), 256>>>(sentpres, sf_Wq, sf_bq, qb, BN_, D2_, D2_, 0, 0);
    sgemm_k<<<dim3(4, 32), 256>>>(sentpres, sf_Wk, sf_bk, kb, BN_, D2_, D2_, 0, 0);
    spp_kernel<<<2048, 64>>>(qb, kb, sFt);

    // Tag LSTM input projections
    sgemm_k<<<dim3(8, 32), 256>>>(sentpres, tw_ih_f, tb_f, gtag,             BN_, D2_, G4_, 1, 0);
    sgemm_k<<<dim3(8, 32), 256>>>(sentpres, tw_ih_b, tb_b, gtag + BN_ * G4_, BN_, D2_, G4_, 1, 0);

    // Tag BiLSTM recurrence
    for (int s = 0; s < 64; s++)
        lstm_tag_step<<<dim3(8, 2), 256, TAG_SMEM>>>(gtag, whhT_t, htag, ctag, tago, s);

    // GCN
    gcn_kernel<<<32, 256, GCN_SMEM>>>(tago, agg);
    sgemm_k<<<dim3(4, 32), 256>>>(agg, sage_W, sage_b, gcn_out, BN_, D2_, D2_, 0, 1);

    // roleFt SPP
    sgemm_k<<<dim3(4, 32), 256>>>(tago, rf_Wq, rf_bq, qb, BN_, D2_, D2_, 0, 0);
    sgemm_k<<<dim3(4, 32), 256>>>(tago, rf_Wk, rf_bk, kb, BN_, D2_, D2_, 0, 0);
    spp_kernel<<<2048, 64>>>(qb, kb, rFt);

    cls_kernel<<<2048, 32>>>(tago, sFt, rFt, cls_W, cls_b, result_out);

    (void)in_sizes; (void)n_in; (void)out_size;
}

// round 4
// speedup vs baseline: 1.8780x; 1.1123x over previous
#include <cuda_runtime.h>
#include <cuda_bf16.h>
#include <stdint.h>
#include <math.h>

// ---------------- problem constants ----------------
#define B_    32
#define N_    64
#define T_    50
#define WD_   200
#define H_    128
#define G4_   512
#define D2_   256
#define BN_   2048
#define MA_   102400
#define C_    8
#define KP_   208

// ---------------- scratch ----------------
__device__ float g_sent_buf[2u * 52428800u];   // [dir][bn*T + t][512]
__device__ __nv_bfloat16 a_hi_buf[(size_t)MA_ * KP_];
__device__ __nv_bfloat16 a_lo_buf[(size_t)MA_ * KP_];
__device__ __nv_bfloat16 w_hi_buf[2 * G4_ * KP_];
__device__ __nv_bfloat16 w_lo_buf[2 * G4_ * KP_];
__device__ uint4 wpk_buf[2 * 8 * 64 * 32];     // packed W_hh B-fragments [dir][kt][ng][lane]
__device__ float whhT_tag_buf[2 * 128 * 512];
__device__ float sentpres_buf[BN_ * D2_];
__device__ float q_buf[BN_ * D2_];
__device__ float k_buf[BN_ * D2_];
__device__ float sentFt_buf[BN_ * 15];
__device__ float roleFt_buf[BN_ * 15];
__device__ float g_tag_buf[2 * BN_ * G4_];
__device__ float h_tag_buf[4 * 32 * 128];
__device__ float tag_out_buf[BN_ * D2_];
__device__ float agg_buf[BN_ * D2_];
__device__ int tag_bar[2];

__device__ __forceinline__ float sigf(float x) { return 1.0f / (1.0f + expf(-x)); }

// ================== hi/lo bf16 split conversions ==================
__global__ void cvt_split_doc(const float* __restrict__ A,
                              __nv_bfloat16* __restrict__ hi, __nv_bfloat16* __restrict__ lo)
{
    size_t i = (size_t)blockIdx.x * 256 + threadIdx.x;
    int m = (int)(i / KP_), k = (int)(i % KP_);
    float x = (k < WD_) ? A[(size_t)m * WD_ + k] : 0.f;
    __nv_bfloat16 h = __float2bfloat16(x);
    hi[i] = h;
    lo[i] = __float2bfloat16(x - __bfloat162float(h));
}

__global__ void cvt_split_w(const float* __restrict__ wf, const float* __restrict__ wb,
                            __nv_bfloat16* __restrict__ hi, __nv_bfloat16* __restrict__ lo)
{
    int i = blockIdx.x * 256 + threadIdx.x;
    if (i >= 2 * G4_ * KP_) return;
    int dir = i / (G4_ * KP_); int rem = i - dir * (G4_ * KP_);
    int g = rem / KP_, k = rem % KP_;
    const float* w = dir ? wb : wf;
    float x = (k < WD_) ? w[g * WD_ + k] : 0.f;
    __nv_bfloat16 h = __float2bfloat16(x);
    hi[i] = h;
    lo[i] = __float2bfloat16(x - __bfloat162float(h));
}

__device__ __forceinline__ unsigned pack_bf2(float x0, float x1)
{
    __nv_bfloat162 t;
    t.x = __float2bfloat16(x0);
    t.y = __float2bfloat16(x1);
    return *(unsigned*)&t;
}

// pack W_hh (512x128 fp32, [g][k]) into B-fragment order: [dir][kt(8)][ng(64)][lane(32)] uint4
// uint4 = { b_hi0, b_hi1, b_lo0, b_lo1 }
__global__ void pack_whh(const float* __restrict__ wf, const float* __restrict__ wb,
                         uint4* __restrict__ out)
{
    int i = blockIdx.x * 256 + threadIdx.x;
    if (i >= 2 * 8 * 64 * 32) return;
    int lane = i & 31;
    int ng = (i >> 5) & 63;
    int kt = (i >> 11) & 7;
    int dir = i >> 14;
    const float* w = dir ? wb : wf;
    int n = ng * 8 + (lane >> 2);
    int k = kt * 16 + (lane & 3) * 2;
    float x0 = w[n * 128 + k],     x1 = w[n * 128 + k + 1];
    float x2 = w[n * 128 + k + 8], x3 = w[n * 128 + k + 9];
    float h0 = __bfloat162float(__float2bfloat16(x0));
    float h1 = __bfloat162float(__float2bfloat16(x1));
    float h2 = __bfloat162float(__float2bfloat16(x2));
    float h3 = __bfloat162float(__float2bfloat16(x3));
    uint4 v;
    v.x = pack_bf2(x0, x1);
    v.y = pack_bf2(x2, x3);
    v.z = pack_bf2(x0 - h0, x1 - h1);
    v.w = pack_bf2(x2 - h2, x3 - h3);
    out[i] = v;
}

// ================== stage-A GEMM on tensor cores ==================
#define MMA_OP(d, a, b) \
    asm volatile("mma.sync.aligned.m16n8k16.row.col.f32.bf16.bf16.f32 " \
                 "{%0,%1,%2,%3},{%4,%5,%6,%7},{%8,%9},{%0,%1,%2,%3};\n" \
                 : "+f"(d[0]), "+f"(d[1]), "+f"(d[2]), "+f"(d[3]) \
                 : "r"(a[0]), "r"(a[1]), "r"(a[2]), "r"(a[3]), "r"(b[0]), "r"(b[1]))

__global__ void mma_gemmA(const __nv_bfloat16* __restrict__ ahi, const __nv_bfloat16* __restrict__ alo,
                          const __nv_bfloat16* __restrict__ whi, const __nv_bfloat16* __restrict__ wlo,
                          const float* __restrict__ bias, float* __restrict__ C)
{
    __shared__ __align__(16) unsigned char smem_u[16384];
    __nv_bfloat16* sA0 = (__nv_bfloat16*)smem_u;
    __nv_bfloat16* sA1 = sA0 + 2048;
    __nv_bfloat16* sB0 = sA1 + 2048;
    __nv_bfloat16* sB1 = sB0 + 2048;
    float* sC = (float*)smem_u;   // alias, used after main loop

    int tid = threadIdx.x;
    int lane = tid & 31, wid = tid >> 5;
    int wm = wid & 3, wn = wid >> 2;
    int mb = blockIdx.y << 7, nb = blockIdx.x << 7;
    int lr = tid >> 1, lk = (tid & 1) << 3;
    int r = lane >> 2, c2 = (lane & 3) << 1;

    float acc[2][8][4];
#pragma unroll
    for (int mi = 0; mi < 2; mi++)
#pragma unroll
        for (int ni = 0; ni < 8; ni++)
#pragma unroll
            for (int e = 0; e < 4; e++) acc[mi][ni][e] = 0.f;

    for (int kb = 0; kb < KP_; kb += 16) {
        __syncthreads();
        *(uint4*)&sA0[lr * 16 + lk] = *(const uint4*)(ahi + (size_t)(mb + lr) * KP_ + kb + lk);
        *(uint4*)&sA1[lr * 16 + lk] = *(const uint4*)(alo + (size_t)(mb + lr) * KP_ + kb + lk);
        *(uint4*)&sB0[lr * 16 + lk] = *(const uint4*)(whi + (size_t)(nb + lr) * KP_ + kb + lk);
        *(uint4*)&sB1[lr * 16 + lk] = *(const uint4*)(wlo + (size_t)(nb + lr) * KP_ + kb + lk);
        __syncthreads();

        unsigned ah[2][4], al[2][4];
#pragma unroll
        for (int mi = 0; mi < 2; mi++) {
            int rb = (wm * 32 + mi * 16 + r) * 16;
            ah[mi][0] = *(unsigned*)&sA0[rb + c2];
            ah[mi][1] = *(unsigned*)&sA0[rb + 128 + c2];
            ah[mi][2] = *(unsigned*)&sA0[rb + c2 + 8];
            ah[mi][3] = *(unsigned*)&sA0[rb + 128 + c2 + 8];
            al[mi][0] = *(unsigned*)&sA1[rb + c2];
            al[mi][1] = *(unsigned*)&sA1[rb + 128 + c2];
            al[mi][2] = *(unsigned*)&sA1[rb + c2 + 8];
            al[mi][3] = *(unsigned*)&sA1[rb + 128 + c2 + 8];
        }
#pragma unroll
        for (int ni = 0; ni < 8; ni++) {
            int nbase = (wn * 64 + ni * 8 + r) * 16;
            unsigned bh[2], bl[2];
            bh[0] = *(unsigned*)&sB0[nbase + c2];
            bh[1] = *(unsigned*)&sB0[nbase + c2 + 8];
            bl[0] = *(unsigned*)&sB1[nbase + c2];
            bl[1] = *(unsigned*)&sB1[nbase + c2 + 8];
#pragma unroll
            for (int mi = 0; mi < 2; mi++) {
                MMA_OP(acc[mi][ni], ah[mi], bh);
                MMA_OP(acc[mi][ni], al[mi], bh);
                MMA_OP(acc[mi][ni], ah[mi], bl);
            }
        }
    }
    // staged, coalesced epilogue: 4 chunks of 32 rows
    for (int wmc = 0; wmc < 4; wmc++) {
        __syncthreads();
        if (wm == wmc) {
#pragma unroll
            for (int mi = 0; mi < 2; mi++)
#pragma unroll
                for (int ni = 0; ni < 8; ni++) {
                    int lrow = mi * 16 + r;
                    int col = wn * 64 + ni * 8 + c2;
                    float b0 = bias[nb + col], b1 = bias[nb + col + 1];
                    *(float2*)&sC[lrow * 128 + col] =
                        make_float2(acc[mi][ni][0] + b0, acc[mi][ni][1] + b1);
                    *(float2*)&sC[(lrow + 8) * 128 + col] =
                        make_float2(acc[mi][ni][2] + b0, acc[mi][ni][3] + b1);
                }
        }
        __syncthreads();
#pragma unroll
        for (int l = 0; l < 4; l++) {
            int idx = tid + l * 256;
            int row = idx >> 5, c4 = idx & 31;
            *(float4*)&C[(size_t)(mb + wmc * 32 + row) * 512 + nb + c4 * 4] =
                ((float4*)sC)[idx];
        }
    }
}

// ================== generic tiled SGEMM (small GEMMs) ==================
__global__ void sgemm_k(const float* __restrict__ A, const float* __restrict__ W,
                        const float* __restrict__ bias, float* __restrict__ C,
                        int M, int K, int G, int amode, int relu)
{
    __shared__ float As[8][64];
    __shared__ float Ws[8][64];
    int tid = threadIdx.x;
    int mb = blockIdx.y << 6;
    int gb = blockIdx.x << 6;
    int tx = tid & 15, ty = tid >> 4;
    int mi = tid & 63;
    int kh = (tid >> 6) << 1;

    int m = mb + mi;
    long arow;
    if (amode == 0) arow = (long)m * K;
    else { int b = m & 31; int n = m >> 5; arow = (long)((b << 6) + n) * K; }
    long wrow = (long)(gb + mi) * K;

    float acc[4][4];
#pragma unroll
    for (int i = 0; i < 4; i++)
#pragma unroll
        for (int j = 0; j < 4; j++) acc[i][j] = 0.0f;

    for (int k0 = 0; k0 < K; k0 += 8) {
        float2 av = *(const float2*)(A + arow + k0 + kh);
        float2 wv = *(const float2*)(W + wrow + k0 + kh);
        __syncthreads();
        As[kh][mi] = av.x; As[kh + 1][mi] = av.y;
        Ws[kh][mi] = wv.x; Ws[kh + 1][mi] = wv.y;
        __syncthreads();
#pragma unroll
        for (int kk = 0; kk < 8; kk++) {
            float4 a = *(float4*)(&As[kk][ty << 2]);
            float4 w = *(float4*)(&Ws[kk][tx << 2]);
            float aa[4] = {a.x, a.y, a.z, a.w};
            float ww[4] = {w.x, w.y, w.z, w.w};
#pragma unroll
            for (int i = 0; i < 4; i++)
#pragma unroll
                for (int j = 0; j < 4; j++) acc[i][j] += aa[i] * ww[j];
        }
    }

    float4 b4 = *(const float4*)(bias + gb + (tx << 2));
    float bb[4] = {b4.x, b4.y, b4.z, b4.w};
#pragma unroll
    for (int i = 0; i < 4; i++) {
        float4 r;
        r.x = acc[i][0] + bb[0];
        r.y = acc[i][1] + bb[1];
        r.z = acc[i][2] + bb[2];
        r.w = acc[i][3] + bb[3];
        if (relu) {
            r.x = fmaxf(r.x, 0.f); r.y = fmaxf(r.y, 0.f);
            r.z = fmaxf(r.z, 0.f); r.w = fmaxf(r.w, 0.f);
        }
        *(float4*)(C + (size_t)(mb + (ty << 2) + i) * G + gb + (tx << 2)) = r;
    }
}

// ================== transpose W_hh (512x128) -> (128x512) for tag LSTM ==================
__global__ void transpose_whh(const float* __restrict__ wf, const float* __restrict__ wb,
                              float* __restrict__ outT)
{
    int dir = blockIdx.y;
    const float* w = dir ? wb : wf;
    float* o = outT + dir * 65536;
    for (int i = blockIdx.x * 256 + threadIdx.x; i < 65536; i += 64 * 256) {
        int k = i >> 9, g = i & 511;
        o[i] = w[g * 128 + k];
    }
}

// ================== sentence BiLSTM recurrence on tensor cores ==================
// grid (64,2), 256 threads (8 warps). Per block: 32 batch rows, full 512 gates, K=128.
// h kept in smem as bf16 hi/lo planes; W_hh streamed from L2 in packed B-frag order.
#define SENT3_SMEM (17408 + 66560)
__global__ void lstm_sent3(const float* __restrict__ Gall, const uint4* __restrict__ wpk,
                           float* __restrict__ sentpres)
{
    extern __shared__ __align__(16) unsigned char sm8[];
    __nv_bfloat16* sh_hb = (__nv_bfloat16*)sm8;     // [2][32][136]
    float* sh_g = (float*)(sm8 + 17408);            // [32][520]

    int dir = blockIdx.y;
    int r0 = blockIdx.x << 5;
    const float* Gd = Gall + (size_t)dir * 52428800u;
    const uint4* wp0 = wpk + dir * 8 * 64 * 32;

    int tid = threadIdx.x, lane = tid & 31, w = tid >> 5;
    int gid = lane >> 2, qk = (lane & 3) << 1;
    int ur = tid >> 3, uj = (tid & 7) << 4;

    float c_reg[16], hs[16];
#pragma unroll
    for (int i = 0; i < 16; i++) { c_reg[i] = 0.f; hs[i] = 0.f; }
    for (int i = tid; i < 4352; i += 256) ((unsigned*)sh_hb)[i] = 0u;
    __syncthreads();

    for (int s = 0; s < T_; s++) {
        int t = dir ? (T_ - 1 - s) : s;
        float acc[2][8][4];
        // init accumulators from input projection g
#pragma unroll
        for (int mt = 0; mt < 2; mt++) {
            int row = r0 + mt * 16 + gid;
            const float* gr  = Gd + ((size_t)row * T_ + t) * 512;
            const float* gr8 = Gd + ((size_t)(row + 8) * T_ + t) * 512;
#pragma unroll
            for (int nt = 0; nt < 8; nt++) {
                int col = w * 64 + nt * 8 + qk;
                float2 v0 = *(const float2*)(gr + col);
                float2 v1 = *(const float2*)(gr8 + col);
                acc[mt][nt][0] = v0.x; acc[mt][nt][1] = v0.y;
                acc[mt][nt][2] = v1.x; acc[mt][nt][3] = v1.y;
            }
        }
        // mma over K=128 (8 k-tiles)
#pragma unroll 1
        for (int kt = 0; kt < 8; kt++) {
            uint4 wv[8];
            const uint4* wpt = wp0 + (kt * 64 + w * 8) * 32 + lane;
#pragma unroll
            for (int nt = 0; nt < 8; nt++) wv[nt] = wpt[nt * 32];

            unsigned ah[2][4], al[2][4];
#pragma unroll
            for (int mt = 0; mt < 2; mt++) {
                const __nv_bfloat16* hp = sh_hb + (mt * 16 + gid) * 136 + kt * 16 + qk;
                ah[mt][0] = *(unsigned*)hp;
                ah[mt][1] = *(unsigned*)(hp + 1088);
                ah[mt][2] = *(unsigned*)(hp + 8);
                ah[mt][3] = *(unsigned*)(hp + 1096);
                const __nv_bfloat16* lp = hp + 4352;
                al[mt][0] = *(unsigned*)lp;
                al[mt][1] = *(unsigned*)(lp + 1088);
                al[mt][2] = *(unsigned*)(lp + 8);
                al[mt][3] = *(unsigned*)(lp + 1096);
            }
#pragma unroll
            for (int nt = 0; nt < 8; nt++) {
                unsigned bh[2], bl[2];
                bh[0] = wv[nt].x; bh[1] = wv[nt].y;
                bl[0] = wv[nt].z; bl[1] = wv[nt].w;
#pragma unroll
                for (int mt = 0; mt < 2; mt++) {
                    MMA_OP(acc[mt][nt], ah[mt], bh);
                    MMA_OP(acc[mt][nt], al[mt], bh);
                    MMA_OP(acc[mt][nt], ah[mt], bl);
                }
            }
        }
        // scatter gates to smem for cross-warp exchange
#pragma unroll
        for (int mt = 0; mt < 2; mt++)
#pragma unroll
            for (int nt = 0; nt < 8; nt++) {
                int lrow = mt * 16 + gid;
                int col = w * 64 + nt * 8 + qk;
                *(float2*)&sh_g[lrow * 520 + col] = make_float2(acc[mt][nt][0], acc[mt][nt][1]);
                *(float2*)&sh_g[(lrow + 8) * 520 + col] = make_float2(acc[mt][nt][2], acc[mt][nt][3]);
            }
        __syncthreads();
        // state update
#pragma unroll
        for (int jj = 0; jj < 16; jj++) {
            int j = uj + jj;
            float ig = sh_g[ur * 520 + j];
            float fg = sh_g[ur * 520 + 128 + j];
            float gg = sh_g[ur * 520 + 256 + j];
            float og = sh_g[ur * 520 + 384 + j];
            float cv = sigf(fg) * c_reg[jj] + sigf(ig) * tanhf(gg);
            c_reg[jj] = cv;
            float h = sigf(og) * tanhf(cv);
            hs[jj] += h;
            __nv_bfloat16 hh = __float2bfloat16(h);
            sh_hb[ur * 136 + j] = hh;
            sh_hb[4352 + ur * 136 + j] = __float2bfloat16(h - __bfloat162float(hh));
        }
        __syncthreads();
    }
#pragma unroll
    for (int jj = 0; jj < 16; jj++)
        sentpres[(r0 + ur) * 256 + dir * 128 + uj + jj] = tanhf(hs[jj] * (1.0f / T_));
}

// ================== persistent tag BiLSTM (one launch, spin barrier) ==================
#define TAGP_SMEM ((4096 + 8192 + 2048) * 4)
__global__ void lstm_tag_pers(const float* __restrict__ Gt, const float* __restrict__ whhT,
                              float* __restrict__ h_buf, float* __restrict__ tag_out)
{
    extern __shared__ float sm[];
    float* sh_h = sm;               // [32][128]
    float* sh_w = sm + 4096;        // [128][64]
    float* sh_g = sh_w + 8192;      // [32][64]

    int dir = blockIdx.y;
    int jb = blockIdx.x << 4;
    const float* wT = whhT + dir * 65536;
    int tid = threadIdx.x;

    // stage W slice once
    for (int i = tid; i < 8192; i += 256) {
        int k = i >> 6; int col = i & 63; int grp = col >> 4; int jj = col & 15;
        sh_w[i] = wT[k * 512 + grp * 128 + jb + jj];
    }
    int r = tid >> 3;
    int c0 = (tid & 7) << 3;
    float creg[2] = {0.f, 0.f};

    for (int s = 0; s < 64; s++) {
        int n = dir ? (63 - s) : s;
        const float* G = Gt + ((size_t)dir * 2048 + n * 32) * 512;
        const float* hprev = h_buf + ((s & 1) * 2 + dir) * 4096;
        float* hnext = h_buf + (((s + 1) & 1) * 2 + dir) * 4096;

        if (s == 0) {
            for (int i = tid; i < 4096; i += 256) sh_h[i] = 0.f;
        } else {
            for (int i = tid; i < 4096; i += 256) sh_h[i] = __ldcg(&hprev[i]);
        }
        __syncthreads();

        float acc[8];
#pragma unroll
        for (int q = 0; q < 8; q++) {
            int col = c0 + q; int grp = col >> 4; int jj = col & 15;
            acc[q] = G[r * 512 + grp * 128 + jb + jj];
        }
        for (int k = 0; k < 128; k++) {
            float hv = sh_h[r * 128 + k];
            float4 wa = *(float4*)&sh_w[k * 64 + c0];
            float4 wb4 = *(float4*)&sh_w[k * 64 + c0 + 4];
            acc[0] += hv * wa.x;  acc[1] += hv * wa.y;
            acc[2] += hv * wa.z;  acc[3] += hv * wa.w;
            acc[4] += hv * wb4.x; acc[5] += hv * wb4.y;
            acc[6] += hv * wb4.z; acc[7] += hv * wb4.w;
        }
#pragma unroll
        for (int q = 0; q < 8; q++) sh_g[r * 64 + c0 + q] = acc[q];
        __syncthreads();

#pragma unroll
        for (int u = 0; u < 2; u++) {
            int e = tid * 2 + u;
            int ru = e >> 4; int jj = e & 15; int j = jb + jj;
            float ig = sh_g[ru * 64 + jj];
            float fg = sh_g[ru * 64 + 16 + jj];
            float gg = sh_g[ru * 64 + 32 + jj];
            float og = sh_g[ru * 64 + 48 + jj];
            float cn = sigf(fg) * creg[u] + sigf(ig) * tanhf(gg);
            creg[u] = cn;
            float h = sigf(og) * tanhf(cn);
            hnext[ru * 128 + j] = h;
            tag_out[(size_t)(ru * 64 + n) * 256 + dir * 128 + j] = tanhf(h);
        }

        if (s < 63) {
            __threadfence();
            __syncthreads();
            if (tid == 0) {
                atomicAdd(&tag_bar[dir], 1);
                while (atomicAdd(&tag_bar[dir], 0) < 8 * (s + 1)) { }
            }
            __syncthreads();
        }
    }
}

// ================== SPP ==================
__global__ void spp_kernel(const float* __restrict__ q, const float* __restrict__ k,
                           float* __restrict__ out)
{
    int bn = blockIdx.x;
    int b = bn >> 6;
    __shared__ float shq[256];
    __shared__ float att[64];
    __shared__ float e8[8];
    int tid = threadIdx.x;
    for (int l = tid; l < 256; l += 64) shq[l] = q[(size_t)bn * 256 + l];
    __syncthreads();
    const float* kr = k + (size_t)(b * 64 + tid) * 256;
    float s = 0.f;
    for (int l = 0; l < 256; l += 4) {
        float4 qa = *(float4*)&shq[l];
        float4 ka = *(const float4*)&kr[l];
        s += qa.x * ka.x + qa.y * ka.y + qa.z * ka.z + qa.w * ka.w;
    }
    att[tid] = s * 0.0625f;
    __syncthreads();
    if (tid < 8) {
        float m = att[tid * 8];
#pragma unroll
        for (int l = 1; l < 8; l++) m = fmaxf(m, att[tid * 8 + l]);
        e8[tid] = m;
    }
    __syncthreads();
    if (tid == 0) {
        float q4[4];
#pragma unroll
        for (int l = 0; l < 4; l++) q4[l] = fmaxf(e8[2 * l], e8[2 * l + 1]);
        float h2a = fmaxf(q4[0], q4[1]);
        float h2b = fmaxf(q4[2], q4[3]);
        float* o = out + bn * 15;
        o[0] = fmaxf(h2a, h2b);
        o[1] = h2a; o[2] = h2b;
        o[3] = q4[0]; o[4] = q4[1]; o[5] = q4[2]; o[6] = q4[3];
#pragma unroll
        for (int l = 0; l < 8; l++) o[7 + l] = e8[l];
    }
}

// ================== GCN ==================
#define GCN_SMEM ((64 * 256 + 64 * 64 + 64) * 4)
__global__ void gcn_kernel(const float* __restrict__ x, float* __restrict__ agg)
{
    extern __shared__ float gs[];
    float* shx = gs;
    float* shc = gs + 16384;
    float* shn = gs + 20480;
    int b = blockIdx.x;
    int tid = threadIdx.x;
    for (int l = tid; l < 16384; l += 256) shx[l] = x[(size_t)b * 16384 + l];
    __syncthreads();
    if (tid < 64) {
        float s = 0.f;
        for (int l = 0; l < 256; l++) { float v = shx[tid * 256 + l]; s += v * v; }
        shn[tid] = sqrtf(s) + 1e-8f;
    }
    __syncthreads();
    for (int p = tid; p < 4096; p += 256) {
        int i = p >> 6, j = p & 63;
        float s = 0.f;
        for (int l = 0; l < 256; l++) s += shx[i * 256 + l] * shx[j * 256 + l];
        shc[p] = s / (shn[i] * shn[j]);
    }
    __syncthreads();
    for (int p = tid; p < 16384; p += 256) {
        int i = p >> 8, d = p & 255;
        float s = 2.0f * shx[i * 256 + d];
        for (int j = 0; j < 64; j++) s += shc[i * 64 + j] * shx[j * 256 + d];
        agg[(size_t)b * 16384 + p] = s * (1.0f / 66.0f);
    }
}

// ================== classifier + log_softmax ==================
__global__ void cls_kernel(const float* __restrict__ tago, const float* __restrict__ sFt,
                           const float* __restrict__ rFt, const float* __restrict__ W,
                           const float* __restrict__ bias, float* __restrict__ out)
{
    int bn = blockIdx.x;
    int c = threadIdx.x;
    __shared__ float sh[8];
    if (c < 8) {
        const float* w = W + c * 286;
        float s = bias[c];
        const float* t = tago + (size_t)bn * 256;
        for (int l = 0; l < 256; l++) s += t[l] * w[l];
        const float* sf = sFt + bn * 15;
        for (int l = 0; l < 15; l++) s += sf[l] * w[256 + l];
        const float* rf = rFt + bn * 15;
        for (int l = 0; l < 15; l++) s += rf[l] * w[271 + l];
        sh[c] = s;
    }
    __syncthreads();
    if (c < 8) {
        float m = sh[0];
#pragma unroll
        for (int l = 1; l < 8; l++) m = fmaxf(m, sh[l]);
        float se = 0.f;
#pragma unroll
        for (int l = 0; l < 8; l++) se += expf(sh[l] - m);
        out[bn * 8 + c] = sh[c] - m - logf(se);
    }
}

// ================== launch ==================
extern "C" void kernel_launch(void* const* d_in, const int* in_sizes, int n_in,
                              void* d_out, int out_size)
{
    const float* documents = (const float*)d_in[0];
    const float* sw_ih_f = (const float*)d_in[1];
    const float* sw_hh_f = (const float*)d_in[2];
    const float* sb_f    = (const float*)d_in[3];
    const float* sw_ih_b = (const float*)d_in[4];
    const float* sw_hh_b = (const float*)d_in[5];
    const float* sb_b    = (const float*)d_in[6];
    const float* sf_Wq = (const float*)d_in[7];
    const float* sf_bq = (const float*)d_in[8];
    const float* sf_Wk = (const float*)d_in[9];
    const float* sf_bk = (const float*)d_in[10];
    const float* rf_Wq = (const float*)d_in[11];
    const float* rf_bq = (const float*)d_in[12];
    const float* rf_Wk = (const float*)d_in[13];
    const float* rf_bk = (const float*)d_in[14];
    const float* tw_ih_f = (const float*)d_in[15];
    const float* tw_hh_f = (const float*)d_in[16];
    const float* tb_f    = (const float*)d_in[17];
    const float* tw_ih_b = (const float*)d_in[18];
    const float* tw_hh_b = (const float*)d_in[19];
    const float* tb_b    = (const float*)d_in[20];
    const float* sage_W = (const float*)d_in[21];
    const float* sage_b = (const float*)d_in[22];
    const float* cls_W  = (const float*)d_in[23];
    const float* cls_b  = (const float*)d_in[24];

    float* out = (float*)d_out;
    float* result_out = out;
    float* gcn_out = out + B_ * N_ * C_;

    float *g_sent, *whhT_t, *sentpres, *qb, *kb, *sFt, *rFt, *gtag, *htag, *tago, *agg;
    __nv_bfloat16 *ahi, *alo, *whi, *wlo;
    uint4* wpk;
    int* barp;
    cudaGetSymbolAddress((void**)&g_sent, g_sent_buf);
    cudaGetSymbolAddress((void**)&ahi, a_hi_buf);
    cudaGetSymbolAddress((void**)&alo, a_lo_buf);
    cudaGetSymbolAddress((void**)&whi, w_hi_buf);
    cudaGetSymbolAddress((void**)&wlo, w_lo_buf);
    cudaGetSymbolAddress((void**)&wpk, wpk_buf);
    cudaGetSymbolAddress((void**)&whhT_t, whhT_tag_buf);
    cudaGetSymbolAddress((void**)&sentpres, sentpres_buf);
    cudaGetSymbolAddress((void**)&qb, q_buf);
    cudaGetSymbolAddress((void**)&kb, k_buf);
    cudaGetSymbolAddress((void**)&sFt, sentFt_buf);
    cudaGetSymbolAddress((void**)&rFt, roleFt_buf);
    cudaGetSymbolAddress((void**)&gtag, g_tag_buf);
    cudaGetSymbolAddress((void**)&htag, h_tag_buf);
    cudaGetSymbolAddress((void**)&tago, tag_out_buf);
    cudaGetSymbolAddress((void**)&agg, agg_buf);
    cudaGetSymbolAddress((void**)&barp, tag_bar);

    cudaFuncSetAttribute(lstm_sent3, cudaFuncAttributeMaxDynamicSharedMemorySize, SENT3_SMEM);
    cudaFuncSetAttribute(lstm_tag_pers, cudaFuncAttributeMaxDynamicSharedMemorySize, TAGP_SMEM);
    cudaFuncSetAttribute(gcn_kernel, cudaFuncAttributeMaxDynamicSharedMemorySize, GCN_SMEM);

    // conversions / packing
    cvt_split_doc<<<(int)(((size_t)MA_ * KP_) / 256), 256>>>(documents, ahi, alo);
    cvt_split_w<<<(2 * G4_ * KP_ + 255) / 256, 256>>>(sw_ih_f, sw_ih_b, whi, wlo);
    pack_whh<<<128, 256>>>(sw_hh_f, sw_hh_b, wpk);
    transpose_whh<<<dim3(64, 2), 256>>>(tw_hh_f, tw_hh_b, whhT_t);

    // Stage A on tensor cores (both dirs)
    mma_gemmA<<<dim3(4, 800), 256>>>(ahi, alo, whi, wlo, sb_f, g_sent);
    mma_gemmA<<<dim3(4, 800), 256>>>(ahi, alo, whi + G4_ * KP_, wlo + G4_ * KP_, sb_b, g_sent + 52428800u);

    // Sentence BiLSTM recurrence on tensor cores
    lstm_sent3<<<dim3(64, 2), 256, SENT3_SMEM>>>(g_sent, wpk, sentpres);

    // sentFt SPP
    sgemm_k<<<dim3(4, 32), 256>>>(sentpres, sf_Wq, sf_bq, qb, BN_, D2_, D2_, 0, 0);
    sgemm_k<<<dim3(4, 32), 256>>>(sentpres, sf_Wk, sf_bk, kb, BN_, D2_, D2_, 0, 0);
    spp_kernel<<<2048, 64>>>(qb, kb, sFt);

    // Tag LSTM input projections
    sgemm_k<<<dim3(8, 32), 256>>>(sentpres, tw_ih_f, tb_f, gtag,             BN_, D2_, G4_, 1, 0);
    sgemm_k<<<dim3(8, 32), 256>>>(sentpres, tw_ih_b, tb_b, gtag + BN_ * G4_, BN_, D2_, G4_, 1, 0);

    // Persistent tag BiLSTM (reset barrier each launch for graph replay determinism)
    cudaMemsetAsync(barp, 0, 2 * sizeof(int));
    lstm_tag_pers<<<dim3(8, 2), 256, TAGP_SMEM>>>(gtag, whhT_t, htag, tago);

    // GCN
    gcn_kernel<<<32, 256, GCN_SMEM>>>(tago, agg);
    sgemm_k<<<dim3(4, 32), 256>>>(agg, sage_W, sage_b, gcn_out, BN_, D2_, D2_, 0, 1);

    // roleFt SPP
    sgemm_k<<<dim3(4, 32), 256>>>(tago, rf_Wq, rf_bq, qb, BN_, D2_, D2_, 0, 0);
    sgemm_k<<<dim3(4, 32), 256>>>(tago, rf_Wk, rf_bk, kb, BN_, D2_, D2_, 0, 0);
    spp_kernel<<<2048, 64>>>(qb, kb, rFt);

    cls_kernel<<<2048, 32>>>(tago, sFt, rFt, cls_W, cls_b, result_out);

    (void)in_sizes; (void)n_in; (void)out_size;
}

// round 5
// speedup vs baseline: 2.0611x; 1.0975x over previous
#include <cuda_runtime.h>
#include <cuda_bf16.h>
#include <stdint.h>
#include <math.h>

// ---------------- problem constants ----------------
#define B_    32
#define N_    64
#define T_    50
#define WD_   200
#define H_    128
#define G4_   512
#define D2_   256
#define BN_   2048
#define MA_   102400
#define C_    8

// ---------------- scratch ----------------
__device__ float g_sent_buf[2u * 52428800u];   // [dir][bn*T + t][512]
__device__ uint4 wpk_buf[2 * 8 * 64 * 32];     // packed W_hh tf32 B-fragments [dir][kt][ng][lane]
__device__ float whhT_tag_buf[2 * 128 * 512];
__device__ float sentpres_buf[BN_ * D2_];
__device__ float q_buf[BN_ * D2_];
__device__ float k_buf[BN_ * D2_];
__device__ float sentFt_buf[BN_ * 15];
__device__ float roleFt_buf[BN_ * 15];
__device__ float g_tag_buf[2 * BN_ * G4_];
__device__ float h_tag_buf[4 * 32 * 128];
__device__ float tag_out_buf[BN_ * D2_];
__device__ float agg_buf[BN_ * D2_];
__device__ int tag_bar[2];

__device__ __forceinline__ float sigf(float x) { return 1.0f / (1.0f + expf(-x)); }

#define MMA_TF32(d, a, b) \
    asm volatile("mma.sync.aligned.m16n8k8.row.col.f32.tf32.tf32.f32 " \
                 "{%0,%1,%2,%3},{%4,%5,%6,%7},{%8,%9},{%0,%1,%2,%3};\n" \
                 : "+f"(d[0]), "+f"(d[1]), "+f"(d[2]), "+f"(d[3]) \
                 : "r"(a[0]), "r"(a[1]), "r"(a[2]), "r"(a[3]), "r"(b[0]), "r"(b[1]))

// pack W_hh (512x128 fp32, [g][k]) into tf32 B-fragments: [dir][kt(8)][ng(64)][lane(32)]
// uint4 = fp32 bits of { W[n][k], W[n][k+4], W[n][k+8], W[n][k+12] }, n=ng*8+lane/4, k=kt*16+lane%4
__global__ void pack_whh_tf32(const float* __restrict__ wf, const float* __restrict__ wb,
                              uint4* __restrict__ out)
{
    int i = blockIdx.x * 256 + threadIdx.x;
    if (i >= 2 * 8 * 64 * 32) return;
    int lane = i & 31;
    int ng = (i >> 5) & 63;
    int kt = (i >> 11) & 7;
    int dir = i >> 14;
    const float* w = dir ? wb : wf;
    int n = ng * 8 + (lane >> 2);
    int k = kt * 16 + (lane & 3);
    uint4 v;
    v.x = __float_as_uint(w[n * 128 + k]);
    v.y = __float_as_uint(w[n * 128 + k + 4]);
    v.z = __float_as_uint(w[n * 128 + k + 8]);
    v.w = __float_as_uint(w[n * 128 + k + 12]);
    out[i] = v;
}

// ================== stage-A GEMM, tf32 tensor cores, fp32 in/out ==================
// C[102400,512] = A[102400,200] @ W^T[200,512] + bias. BM=128,BN=128,BK=16.
__global__ __launch_bounds__(256, 2)
void mma_gemmA_tf32(const float* __restrict__ A, const float* __restrict__ W,
                    const float* __restrict__ bias, float* __restrict__ C)
{
    __shared__ __align__(16) float smf[5120];   // sA[128][20] | sB[128][20]; aliased by sC[32][128]
    float* sA = smf;
    float* sB = smf + 2560;
    float* sC = smf;

    int tid = threadIdx.x;
    int lane = tid & 31, wid = tid >> 5;
    int wm = wid & 3, wn = wid >> 2;
    int mb = blockIdx.y << 7, nb = blockIdx.x << 7;
    int lrow = tid >> 1, lhalf = tid & 1;
    int r = lane >> 2, tc = lane & 3, c2 = tc << 1;

    float acc[2][8][4];
#pragma unroll
    for (int mi = 0; mi < 2; mi++)
#pragma unroll
        for (int ni = 0; ni < 8; ni++)
#pragma unroll
            for (int e = 0; e < 4; e++) acc[mi][ni][e] = 0.f;

    for (int kb = 0; kb < 208; kb += 16) {
        int kg = kb + lhalf * 8;
        float4 va0, va1, vb0, vb1;
        if (kg < WD_) {
            const float* ap = A + (size_t)(mb + lrow) * WD_ + kg;
            const float* bp = W + (size_t)(nb + lrow) * WD_ + kg;
            va0 = *(const float4*)ap;  va1 = *(const float4*)(ap + 4);
            vb0 = *(const float4*)bp;  vb1 = *(const float4*)(bp + 4);
        } else {
            va0 = va1 = vb0 = vb1 = make_float4(0.f, 0.f, 0.f, 0.f);
        }
        __syncthreads();
        *(float4*)&sA[lrow * 20 + lhalf * 8]     = va0;
        *(float4*)&sA[lrow * 20 + lhalf * 8 + 4] = va1;
        *(float4*)&sB[lrow * 20 + lhalf * 8]     = vb0;
        *(float4*)&sB[lrow * 20 + lhalf * 8 + 4] = vb1;
        __syncthreads();

        unsigned af[2][2][4];
#pragma unroll
        for (int mi = 0; mi < 2; mi++) {
            int rb = (wm * 32 + mi * 16 + r) * 20;
#pragma unroll
            for (int kh = 0; kh < 2; kh++) {
                af[mi][kh][0] = __float_as_uint(sA[rb + kh * 8 + tc]);
                af[mi][kh][1] = __float_as_uint(sA[rb + 160 + kh * 8 + tc]);
                af[mi][kh][2] = __float_as_uint(sA[rb + kh * 8 + tc + 4]);
                af[mi][kh][3] = __float_as_uint(sA[rb + 160 + kh * 8 + tc + 4]);
            }
        }
#pragma unroll
        for (int ni = 0; ni < 8; ni++) {
            int nrb = (wn * 64 + ni * 8 + r) * 20;
#pragma unroll
            for (int kh = 0; kh < 2; kh++) {
                unsigned bf[2];
                bf[0] = __float_as_uint(sB[nrb + kh * 8 + tc]);
                bf[1] = __float_as_uint(sB[nrb + kh * 8 + tc + 4]);
#pragma unroll
                for (int mi = 0; mi < 2; mi++)
                    MMA_TF32(acc[mi][ni], af[mi][kh], bf);
            }
        }
    }
    // staged coalesced epilogue: 4 chunks of 32 rows
    for (int wmc = 0; wmc < 4; wmc++) {
        __syncthreads();
        if (wm == wmc) {
#pragma unroll
            for (int mi = 0; mi < 2; mi++)
#pragma unroll
                for (int ni = 0; ni < 8; ni++) {
                    int lr2 = mi * 16 + r;
                    int col = wn * 64 + ni * 8 + c2;
                    float b0 = bias[nb + col], b1 = bias[nb + col + 1];
                    *(float2*)&sC[lr2 * 128 + col] =
                        make_float2(acc[mi][ni][0] + b0, acc[mi][ni][1] + b1);
                    *(float2*)&sC[(lr2 + 8) * 128 + col] =
                        make_float2(acc[mi][ni][2] + b0, acc[mi][ni][3] + b1);
                }
        }
        __syncthreads();
#pragma unroll
        for (int l = 0; l < 4; l++) {
            int idx = tid + l * 256;
            int row = idx >> 5, c4 = idx & 31;
            *(float4*)&C[(size_t)(mb + wmc * 32 + row) * 512 + nb + c4 * 4] =
                ((float4*)sC)[idx];
        }
    }
}

// ================== generic tiled SGEMM (small GEMMs, fp32) ==================
__global__ void sgemm_k(const float* __restrict__ A, const float* __restrict__ W,
                        const float* __restrict__ bias, float* __restrict__ C,
                        int M, int K, int G, int amode, int relu)
{
    __shared__ float As[8][64];
    __shared__ float Ws[8][64];
    int tid = threadIdx.x;
    int mb = blockIdx.y << 6;
    int gb = blockIdx.x << 6;
    int tx = tid & 15, ty = tid >> 4;
    int mi = tid & 63;
    int kh = (tid >> 6) << 1;

    int m = mb + mi;
    long arow;
    if (amode == 0) arow = (long)m * K;
    else { int b = m & 31; int n = m >> 5; arow = (long)((b << 6) + n) * K; }
    long wrow = (long)(gb + mi) * K;

    float acc[4][4];
#pragma unroll
    for (int i = 0; i < 4; i++)
#pragma unroll
        for (int j = 0; j < 4; j++) acc[i][j] = 0.0f;

    for (int k0 = 0; k0 < K; k0 += 8) {
        float2 av = *(const float2*)(A + arow + k0 + kh);
        float2 wv = *(const float2*)(W + wrow + k0 + kh);
        __syncthreads();
        As[kh][mi] = av.x; As[kh + 1][mi] = av.y;
        Ws[kh][mi] = wv.x; Ws[kh + 1][mi] = wv.y;
        __syncthreads();
#pragma unroll
        for (int kk = 0; kk < 8; kk++) {
            float4 a = *(float4*)(&As[kk][ty << 2]);
            float4 w = *(float4*)(&Ws[kk][tx << 2]);
            float aa[4] = {a.x, a.y, a.z, a.w};
            float ww[4] = {w.x, w.y, w.z, w.w};
#pragma unroll
            for (int i = 0; i < 4; i++)
#pragma unroll
                for (int j = 0; j < 4; j++) acc[i][j] += aa[i] * ww[j];
        }
    }

    float4 b4 = *(const float4*)(bias + gb + (tx << 2));
    float bb[4] = {b4.x, b4.y, b4.z, b4.w};
#pragma unroll
    for (int i = 0; i < 4; i++) {
        float4 r;
        r.x = acc[i][0] + bb[0];
        r.y = acc[i][1] + bb[1];
        r.z = acc[i][2] + bb[2];
        r.w = acc[i][3] + bb[3];
        if (relu) {
            r.x = fmaxf(r.x, 0.f); r.y = fmaxf(r.y, 0.f);
            r.z = fmaxf(r.z, 0.f); r.w = fmaxf(r.w, 0.f);
        }
        *(float4*)(C + (size_t)(mb + (ty << 2) + i) * G + gb + (tx << 2)) = r;
    }
}

// ================== transpose W_hh (512x128) -> (128x512) for tag LSTM ==================
__global__ void transpose_whh(const float* __restrict__ wf, const float* __restrict__ wb,
                              float* __restrict__ outT)
{
    int dir = blockIdx.y;
    const float* w = dir ? wb : wf;
    float* o = outT + dir * 65536;
    for (int i = blockIdx.x * 256 + threadIdx.x; i < 65536; i += 64 * 256) {
        int k = i >> 9, g = i & 511;
        o[i] = w[g * 128 + k];
    }
}

// ================== sentence BiLSTM recurrence, tf32 tensor cores ==================
// grid (64,2), 256 threads (8 warps). Per block: 32 batch rows, 512 gates, K=128.
#define SENT3_SMEM (16896 + 66560)
__global__ void lstm_sent3(const float* __restrict__ Gall, const uint4* __restrict__ wpk,
                           float* __restrict__ sentpres)
{
    extern __shared__ __align__(16) unsigned char sm8[];
    float* sh_h = (float*)sm8;                      // [32][132] fp32
    float* sh_g = (float*)(sm8 + 16896);            // [32][520]

    int dir = blockIdx.y;
    int r0 = blockIdx.x << 5;
    const float* Gd = Gall + (size_t)dir * 52428800u;
    const uint4* wp0 = wpk + dir * 8 * 64 * 32;

    int tid = threadIdx.x, lane = tid & 31, w = tid >> 5;
    int gid = lane >> 2, tc = lane & 3, qk = tc << 1;
    int ur = tid >> 3, uj = (tid & 7) << 4;

    float c_reg[16], hs[16];
#pragma unroll
    for (int i = 0; i < 16; i++) { c_reg[i] = 0.f; hs[i] = 0.f; }
    for (int i = tid; i < 4224; i += 256) sh_h[i] = 0.f;
    __syncthreads();

    for (int s = 0; s < T_; s++) {
        int t = dir ? (T_ - 1 - s) : s;
        float acc[2][8][4];
#pragma unroll
        for (int mt = 0; mt < 2; mt++) {
            int row = r0 + mt * 16 + gid;
            const float* gr  = Gd + ((size_t)row * T_ + t) * 512;
            const float* gr8 = Gd + ((size_t)(row + 8) * T_ + t) * 512;
#pragma unroll
            for (int nt = 0; nt < 8; nt++) {
                int col = w * 64 + nt * 8 + qk;
                float2 v0 = *(const float2*)(gr + col);
                float2 v1 = *(const float2*)(gr8 + col);
                acc[mt][nt][0] = v0.x; acc[mt][nt][1] = v0.y;
                acc[mt][nt][2] = v1.x; acc[mt][nt][3] = v1.y;
            }
        }
#pragma unroll 1
        for (int kt = 0; kt < 8; kt++) {
            uint4 wv[8];
            const uint4* wpt = wp0 + (kt * 64 + w * 8) * 32 + lane;
#pragma unroll
            for (int nt = 0; nt < 8; nt++) wv[nt] = wpt[nt * 32];

            unsigned af[2][2][4];
#pragma unroll
            for (int mt = 0; mt < 2; mt++) {
                int rb = (mt * 16 + gid) * 132 + kt * 16;
#pragma unroll
                for (int kh = 0; kh < 2; kh++) {
                    af[mt][kh][0] = __float_as_uint(sh_h[rb + kh * 8 + tc]);
                    af[mt][kh][1] = __float_as_uint(sh_h[rb + 1056 + kh * 8 + tc]);
                    af[mt][kh][2] = __float_as_uint(sh_h[rb + kh * 8 + tc + 4]);
                    af[mt][kh][3] = __float_as_uint(sh_h[rb + 1056 + kh * 8 + tc + 4]);
                }
            }
#pragma unroll
            for (int nt = 0; nt < 8; nt++) {
                unsigned b0[2] = { wv[nt].x, wv[nt].y };
                unsigned b1[2] = { wv[nt].z, wv[nt].w };
#pragma unroll
                for (int mt = 0; mt < 2; mt++) {
                    MMA_TF32(acc[mt][nt], af[mt][0], b0);
                    MMA_TF32(acc[mt][nt], af[mt][1], b1);
                }
            }
        }
        // scatter gates for cross-warp exchange
#pragma unroll
        for (int mt = 0; mt < 2; mt++)
#pragma unroll
            for (int nt = 0; nt < 8; nt++) {
                int lrow = mt * 16 + gid;
                int col = w * 64 + nt * 8 + qk;
                *(float2*)&sh_g[lrow * 520 + col] = make_float2(acc[mt][nt][0], acc[mt][nt][1]);
                *(float2*)&sh_g[(lrow + 8) * 520 + col] = make_float2(acc[mt][nt][2], acc[mt][nt][3]);
            }
        __syncthreads();
        // state update
#pragma unroll
        for (int jj = 0; jj < 16; jj++) {
            int j = uj + jj;
            float ig = sh_g[ur * 520 + j];
            float fg = sh_g[ur * 520 + 128 + j];
            float gg = sh_g[ur * 520 + 256 + j];
            float og = sh_g[ur * 520 + 384 + j];
            float cv = sigf(fg) * c_reg[jj] + sigf(ig) * tanhf(gg);
            c_reg[jj] = cv;
            float h = sigf(og) * tanhf(cv);
            hs[jj] += h;
            sh_h[ur * 132 + j] = h;
        }
        __syncthreads();
    }
#pragma unroll
    for (int jj = 0; jj < 16; jj++)
        sentpres[(r0 + ur) * 256 + dir * 128 + uj + jj] = tanhf(hs[jj] * (1.0f / T_));
}

// ================== persistent tag BiLSTM ==================
#define TAGP_SMEM ((4096 + 8192 + 2048) * 4)
__global__ void lstm_tag_pers(const float* __restrict__ Gt, const float* __restrict__ whhT,
                              float* __restrict__ h_buf, float* __restrict__ tag_out)
{
    extern __shared__ float sm[];
    float* sh_h = sm;
    float* sh_w = sm + 4096;
    float* sh_g = sh_w + 8192;

    int dir = blockIdx.y;
    int jb = blockIdx.x << 4;
    const float* wT = whhT + dir * 65536;
    int tid = threadIdx.x;

    for (int i = tid; i < 8192; i += 256) {
        int k = i >> 6; int col = i & 63; int grp = col >> 4; int jj = col & 15;
        sh_w[i] = wT[k * 512 + grp * 128 + jb + jj];
    }
    int r = tid >> 3;
    int c0 = (tid & 7) << 3;
    float creg[2] = {0.f, 0.f};

    for (int s = 0; s < 64; s++) {
        int n = dir ? (63 - s) : s;
        const float* G = Gt + ((size_t)dir * 2048 + n * 32) * 512;
        const float* hprev = h_buf + ((s & 1) * 2 + dir) * 4096;
        float* hnext = h_buf + (((s + 1) & 1) * 2 + dir) * 4096;

        if (s == 0) {
            for (int i = tid; i < 4096; i += 256) sh_h[i] = 0.f;
        } else {
            for (int i = tid; i < 4096; i += 256) sh_h[i] = __ldcg(&hprev[i]);
        }
        __syncthreads();

        float acc[8];
#pragma unroll
        for (int q = 0; q < 8; q++) {
            int col = c0 + q; int grp = col >> 4; int jj = col & 15;
            acc[q] = G[r * 512 + grp * 128 + jb + jj];
        }
        for (int k = 0; k < 128; k++) {
            float hv = sh_h[r * 128 + k];
            float4 wa = *(float4*)&sh_w[k * 64 + c0];
            float4 wb4 = *(float4*)&sh_w[k * 64 + c0 + 4];
            acc[0] += hv * wa.x;  acc[1] += hv * wa.y;
            acc[2] += hv * wa.z;  acc[3] += hv * wa.w;
            acc[4] += hv * wb4.x; acc[5] += hv * wb4.y;
            acc[6] += hv * wb4.z; acc[7] += hv * wb4.w;
        }
#pragma unroll
        for (int q = 0; q < 8; q++) sh_g[r * 64 + c0 + q] = acc[q];
        __syncthreads();

#pragma unroll
        for (int u = 0; u < 2; u++) {
            int e = tid * 2 + u;
            int ru = e >> 4; int jj = e & 15; int j = jb + jj;
            float ig = sh_g[ru * 64 + jj];
            float fg = sh_g[ru * 64 + 16 + jj];
            float gg = sh_g[ru * 64 + 32 + jj];
            float og = sh_g[ru * 64 + 48 + jj];
            float cn = sigf(fg) * creg[u] + sigf(ig) * tanhf(gg);
            creg[u] = cn;
            float h = sigf(og) * tanhf(cn);
            hnext[ru * 128 + j] = h;
            tag_out[(size_t)(ru * 64 + n) * 256 + dir * 128 + j] = tanhf(h);
        }

        if (s < 63) {
            __threadfence();
            __syncthreads();
            if (tid == 0) {
                atomicAdd(&tag_bar[dir], 1);
                while (atomicAdd(&tag_bar[dir], 0) < 8 * (s + 1)) { }
            }
            __syncthreads();
        }
    }
}

// ================== SPP ==================
__global__ void spp_kernel(const float* __restrict__ q, const float* __restrict__ k,
                           float* __restrict__ out)
{
    int bn = blockIdx.x;
    int b = bn >> 6;
    __shared__ float shq[256];
    __shared__ float att[64];
    __shared__ float e8[8];
    int tid = threadIdx.x;
    for (int l = tid; l < 256; l += 64) shq[l] = q[(size_t)bn * 256 + l];
    __syncthreads();
    const float* kr = k + (size_t)(b * 64 + tid) * 256;
    float s = 0.f;
    for (int l = 0; l < 256; l += 4) {
        float4 qa = *(float4*)&shq[l];
        float4 ka = *(const float4*)&kr[l];
        s += qa.x * ka.x + qa.y * ka.y + qa.z * ka.z + qa.w * ka.w;
    }
    att[tid] = s * 0.0625f;
    __syncthreads();
    if (tid < 8) {
        float m = att[tid * 8];
#pragma unroll
        for (int l = 1; l < 8; l++) m = fmaxf(m, att[tid * 8 + l]);
        e8[tid] = m;
    }
    __syncthreads();
    if (tid == 0) {
        float q4[4];
#pragma unroll
        for (int l = 0; l < 4; l++) q4[l] = fmaxf(e8[2 * l], e8[2 * l + 1]);
        float h2a = fmaxf(q4[0], q4[1]);
        float h2b = fmaxf(q4[2], q4[3]);
        float* o = out + bn * 15;
        o[0] = fmaxf(h2a, h2b);
        o[1] = h2a; o[2] = h2b;
        o[3] = q4[0]; o[4] = q4[1]; o[5] = q4[2]; o[6] = q4[3];
#pragma unroll
        for (int l = 0; l < 8; l++) o[7 + l] = e8[l];
    }
}

// ================== GCN ==================
#define GCN_SMEM ((64 * 256 + 64 * 64 + 64) * 4)
__global__ void gcn_kernel(const float* __restrict__ x, float* __restrict__ agg)
{
    extern __shared__ float gs[];
    float* shx = gs;
    float* shc = gs + 16384;
    float* shn = gs + 20480;
    int b = blockIdx.x;
    int tid = threadIdx.x;
    for (int l = tid; l < 16384; l += 256) shx[l] = x[(size_t)b * 16384 + l];
    __syncthreads();
    if (tid < 64) {
        float s = 0.f;
        for (int l = 0; l < 256; l++) { float v = shx[tid * 256 + l]; s += v * v; }
        shn[tid] = sqrtf(s) + 1e-8f;
    }
    __syncthreads();
    for (int p = tid; p < 4096; p += 256) {
        int i = p >> 6, j = p & 63;
        float s = 0.f;
        for (int l = 0; l < 256; l++) s += shx[i * 256 + l] * shx[j * 256 + l];
        shc[p] = s / (shn[i] * shn[j]);
    }
    __syncthreads();
    for (int p = tid; p < 16384; p += 256) {
        int i = p >> 8, d = p & 255;
        float s = 2.0f * shx[i * 256 + d];
        for (int j = 0; j < 64; j++) s += shc[i * 64 + j] * shx[j * 256 + d];
        agg[(size_t)b * 16384 + p] = s * (1.0f / 66.0f);
    }
}

// ================== classifier + log_softmax ==================
__global__ void cls_kernel(const float* __restrict__ tago, const float* __restrict__ sFt,
                           const float* __restrict__ rFt, const float* __restrict__ W,
                           const float* __restrict__ bias, float* __restrict__ out)
{
    int bn = blockIdx.x;
    int c = threadIdx.x;
    __shared__ float sh[8];
    if (c < 8) {
        const float* w = W + c * 286;
        float s = bias[c];
        const float* t = tago + (size_t)bn * 256;
        for (int l = 0; l < 256; l++) s += t[l] * w[l];
        const float* sf = sFt + bn * 15;
        for (int l = 0; l < 15; l++) s += sf[l] * w[256 + l];
        const float* rf = rFt + bn * 15;
        for (int l = 0; l < 15; l++) s += rf[l] * w[271 + l];
        sh[c] = s;
    }
    __syncthreads();
    if (c < 8) {
        float m = sh[0];
#pragma unroll
        for (int l = 1; l < 8; l++) m = fmaxf(m, sh[l]);
        float se = 0.f;
#pragma unroll
        for (int l = 0; l < 8; l++) se += expf(sh[l] - m);
        out[bn * 8 + c] = sh[c] - m - logf(se);
    }
}

// ================== launch ==================
extern "C" void kernel_launch(void* const* d_in, const int* in_sizes, int n_in,
                              void* d_out, int out_size)
{
    const float* documents = (const float*)d_in[0];
    const float* sw_ih_f = (const float*)d_in[1];
    const float* sw_hh_f = (const float*)d_in[2];
    const float* sb_f    = (const float*)d_in[3];
    const float* sw_ih_b = (const float*)d_in[4];
    const float* sw_hh_b = (const float*)d_in[5];
    const float* sb_b    = (const float*)d_in[6];
    const float* sf_Wq = (const float*)d_in[7];
    const float* sf_bq = (const float*)d_in[8];
    const float* sf_Wk = (const float*)d_in[9];
    const float* sf_bk = (const float*)d_in[10];
    const float* rf_Wq = (const float*)d_in[11];
    const float* rf_bq = (const float*)d_in[12];
    const float* rf_Wk = (const float*)d_in[13];
    const float* rf_bk = (const float*)d_in[14];
    const float* tw_ih_f = (const float*)d_in[15];
    const float* tw_hh_f = (const float*)d_in[16];
    const float* tb_f    = (const float*)d_in[17];
    const float* tw_ih_b = (const float*)d_in[18];
    const float* tw_hh_b = (const float*)d_in[19];
    const float* tb_b    = (const float*)d_in[20];
    const float* sage_W = (const float*)d_in[21];
    const float* sage_b = (const float*)d_in[22];
    const float* cls_W  = (const float*)d_in[23];
    const float* cls_b  = (const float*)d_in[24];

    float* out = (float*)d_out;
    float* result_out = out;
    float* gcn_out = out + B_ * N_ * C_;

    float *g_sent, *whhT_t, *sentpres, *qb, *kb, *sFt, *rFt, *gtag, *htag, *tago, *agg;
    uint4* wpk;
    int* barp;
    cudaGetSymbolAddress((void**)&g_sent, g_sent_buf);
    cudaGetSymbolAddress((void**)&wpk, wpk_buf);
    cudaGetSymbolAddress((void**)&whhT_t, whhT_tag_buf);
    cudaGetSymbolAddress((void**)&sentpres, sentpres_buf);
    cudaGetSymbolAddress((void**)&qb, q_buf);
    cudaGetSymbolAddress((void**)&kb, k_buf);
    cudaGetSymbolAddress((void**)&sFt, sentFt_buf);
    cudaGetSymbolAddress((void**)&rFt, roleFt_buf);
    cudaGetSymbolAddress((void**)&gtag, g_tag_buf);
    cudaGetSymbolAddress((void**)&htag, h_tag_buf);
    cudaGetSymbolAddress((void**)&tago, tag_out_buf);
    cudaGetSymbolAddress((void**)&agg, agg_buf);
    cudaGetSymbolAddress((void**)&barp, tag_bar);

    cudaFuncSetAttribute(lstm_sent3, cudaFuncAttributeMaxDynamicSharedMemorySize, SENT3_SMEM);
    cudaFuncSetAttribute(lstm_tag_pers, cudaFuncAttributeMaxDynamicSharedMemorySize, TAGP_SMEM);
    cudaFuncSetAttribute(gcn_kernel, cudaFuncAttributeMaxDynamicSharedMemorySize, GCN_SMEM);

    // prep (slots 1-2)
    pack_whh_tf32<<<128, 256>>>(sw_hh_f, sw_hh_b, wpk);
    transpose_whh<<<dim3(64, 2), 256>>>(tw_hh_f, tw_hh_b, whhT_t);

    // Stage A, tf32 tensor cores (slots 3-4 — target of the ncu capture window)
    mma_gemmA_tf32<<<dim3(4, 800), 256>>>(documents, sw_ih_f, sb_f, g_sent);
    mma_gemmA_tf32<<<dim3(4, 800), 256>>>(documents, sw_ih_b, sb_b, g_sent + 52428800u);

    // Sentence BiLSTM recurrence (tf32)
    lstm_sent3<<<dim3(64, 2), 256, SENT3_SMEM>>>(g_sent, wpk, sentpres);

    // sentFt SPP
    sgemm_k<<<dim3(4, 32), 256>>>(sentpres, sf_Wq, sf_bq, qb, BN_, D2_, D2_, 0, 0);
    sgemm_k<<<dim3(4, 32), 256>>>(sentpres, sf_Wk, sf_bk, kb, BN_, D2_, D2_, 0, 0);
    spp_kernel<<<2048, 64>>>(qb, kb, sFt);

    // Tag LSTM input projections
    sgemm_k<<<dim3(8, 32), 256>>>(sentpres, tw_ih_f, tb_f, gtag,             BN_, D2_, G4_, 1, 0);
    sgemm_k<<<dim3(8, 32), 256>>>(sentpres, tw_ih_b, tb_b, gtag + BN_ * G4_, BN_, D2_, G4_, 1, 0);

    // Persistent tag BiLSTM
    cudaMemsetAsync(barp, 0, 2 * sizeof(int));
    lstm_tag_pers<<<dim3(8, 2), 256, TAGP_SMEM>>>(gtag, whhT_t, htag, tago);

    // GCN
    gcn_kernel<<<32, 256, GCN_SMEM>>>(tago, agg);
    sgemm_k<<<dim3(4, 32), 256>>>(agg, sage_W, sage_b, gcn_out, BN_, D2_, D2_, 0, 1);

    // roleFt SPP
    sgemm_k<<<dim3(4, 32), 256>>>(tago, rf_Wq, rf_bq, qb, BN_, D2_, D2_, 0, 0);
    sgemm_k<<<dim3(4, 32), 256>>>(tago, rf_Wk, rf_bk, kb, BN_, D2_, D2_, 0, 0);
    spp_kernel<<<2048, 64>>>(qb, kb, rFt);

    cls_kernel<<<2048, 32>>>(tago, sFt, rFt, cls_W, cls_b, result_out);

    (void)in_sizes; (void)n_in; (void)out_size;
}

// round 6
// speedup vs baseline: 2.6780x; 1.2993x over previous
#include <cuda_runtime.h>
#include <cuda_bf16.h>
#include <stdint.h>
#include <math.h>

// ---------------- problem constants ----------------
#define B_    32
#define N_    64
#define T_    50
#define WD_   200
#define H_    128
#define G4_   512
#define D2_   256
#define BN_   2048
#define C_    8

// ---------------- scratch ----------------
__device__ uint4 wih_pk_buf[2 * 13 * 64 * 32];  // packed W_ih tf32 B-frags [dir][kt][ng][lane]
__device__ uint4 whh_pk_buf[2 * 8 * 64 * 32];   // packed W_hh tf32 B-frags
__device__ float whhT_tag_buf[2 * 128 * 512];
__device__ float sentpres_buf[BN_ * D2_];
__device__ float q_buf[BN_ * D2_];
__device__ float k_buf[BN_ * D2_];
__device__ float sentFt_buf[BN_ * 15];
__device__ float roleFt_buf[BN_ * 15];
__device__ float g_tag_buf[2 * BN_ * G4_];
__device__ float h_tag_buf[4 * 32 * 128];
__device__ float tag_out_buf[BN_ * D2_];
__device__ float agg_buf[BN_ * D2_];
__device__ int tag_bar[2];

__device__ __forceinline__ float sigf(float x) { return 1.0f / (1.0f + expf(-x)); }

#define MMA_TF32(d, a, b) \
    asm volatile("mma.sync.aligned.m16n8k8.row.col.f32.tf32.tf32.f32 " \
                 "{%0,%1,%2,%3},{%4,%5,%6,%7},{%8,%9},{%0,%1,%2,%3};\n" \
                 : "+f"(d[0]), "+f"(d[1]), "+f"(d[2]), "+f"(d[3]) \
                 : "r"(a[0]), "r"(a[1]), "r"(a[2]), "r"(a[3]), "r"(b[0]), "r"(b[1]))

__device__ __forceinline__ void ldsm_x4(unsigned& r0, unsigned& r1, unsigned& r2, unsigned& r3,
                                        const float* p)
{
    unsigned addr = (unsigned)__cvta_generic_to_shared(p);
    asm volatile("ldmatrix.sync.aligned.m8n8.x4.shared.b16 {%0,%1,%2,%3}, [%4];"
                 : "=r"(r0), "=r"(r1), "=r"(r2), "=r"(r3) : "r"(addr));
}

// A-fragment (m16 x k8, tf32) via one ldmatrix.x4. base = smem row-major float matrix.
__device__ __forceinline__ void lda_frag(unsigned af[4], const float* base, int stride,
                                         int mrow0, int kcol0, int lane)
{
    int tile = lane >> 3, rin = lane & 7;
    int row = mrow0 + ((tile & 1) << 3) + rin;
    int col = kcol0 + ((tile >> 1) << 2);
    ldsm_x4(af[0], af[1], af[2], af[3], base + row * stride + col);
}

// ================== pack W_ih (512x200) into tf32 B-fragments ==================
// [dir][kt(13)][ng(64)][lane(32)] uint4 = { W[n][k], W[n][k+4], W[n][k+8], W[n][k+12] }
__global__ void pack_wih_tf32(const float* __restrict__ wf, const float* __restrict__ wb,
                              uint4* __restrict__ out)
{
    int i = blockIdx.x * 256 + threadIdx.x;
    if (i >= 2 * 13 * 64 * 32) return;
    const int per = 13 * 64 * 32;
    int dir = i / per, rem = i % per;
    int kt = rem >> 11, ng = (rem >> 5) & 63, lane = rem & 31;
    const float* w = dir ? wb : wf;
    int n = ng * 8 + (lane >> 2);
    int k = kt * 16 + (lane & 3);
    uint4 v;
    v.x = (k      < WD_) ? __float_as_uint(w[n * WD_ + k])      : 0u;
    v.y = (k + 4  < WD_) ? __float_as_uint(w[n * WD_ + k + 4])  : 0u;
    v.z = (k + 8  < WD_) ? __float_as_uint(w[n * WD_ + k + 8])  : 0u;
    v.w = (k + 12 < WD_) ? __float_as_uint(w[n * WD_ + k + 12]) : 0u;
    out[i] = v;
}

// ================== pack W_hh (512x128) into tf32 B-fragments ==================
__global__ void pack_whh_tf32(const float* __restrict__ wf, const float* __restrict__ wb,
                              uint4* __restrict__ out)
{
    int i = blockIdx.x * 256 + threadIdx.x;
    if (i >= 2 * 8 * 64 * 32) return;
    int lane = i & 31, ng = (i >> 5) & 63, kt = (i >> 11) & 7, dir = i >> 14;
    const float* w = dir ? wb : wf;
    int n = ng * 8 + (lane >> 2);
    int k = kt * 16 + (lane & 3);
    uint4 v;
    v.x = __float_as_uint(w[n * 128 + k]);
    v.y = __float_as_uint(w[n * 128 + k + 4]);
    v.z = __float_as_uint(w[n * 128 + k + 8]);
    v.w = __float_as_uint(w[n * 128 + k + 12]);
    out[i] = v;
}

// ================== transpose W_hh (512x128) -> (128x512) for tag LSTM ==================
__global__ void transpose_whh(const float* __restrict__ wf, const float* __restrict__ wb,
                              float* __restrict__ outT)
{
    int dir = blockIdx.y;
    const float* w = dir ? wb : wf;
    float* o = outT + dir * 65536;
    for (int i = blockIdx.x * 256 + threadIdx.x; i < 65536; i += 64 * 256) {
        int k = i >> 9, g = i & 511;
        o[i] = w[g * 128 + k];
    }
}

// ================== FUSED sentence BiLSTM: input proj + recurrence, tf32 mma ==================
// grid (64, 2), 256 threads / 8 warps. Block: 32 batch rows, 512 gates.
// Per step: gates = bias + x_t[32,208pad] @ W_ih^T + h[32,128] @ W_hh^T, then LSTM cell.
#define SD_STR 212
#define SH_STR 132
#define FUSED_SMEM (66560 + 27136 + 16896 + 2048)
__global__ __launch_bounds__(256, 1)
void lstm_sent_fused(const float* __restrict__ doc,
                     const uint4* __restrict__ wih, const uint4* __restrict__ whh,
                     const float* __restrict__ biasf, const float* __restrict__ biasb,
                     float* __restrict__ sentpres)
{
    extern __shared__ __align__(16) unsigned char sm8[];
    float* sh_g  = (float*)sm8;                          // [32][520]
    float* sd    = (float*)(sm8 + 66560);                // [32][212] doc tile
    float* sh_h  = (float*)(sm8 + 66560 + 27136);        // [32][132] hidden
    float* sbias = (float*)(sm8 + 66560 + 27136 + 16896);// [512]

    int dir = blockIdx.y;
    int r0 = blockIdx.x << 5;
    const uint4* wih0 = wih + dir * 13 * 64 * 32;
    const uint4* whh0 = whh + dir * 8 * 64 * 32;
    const float* bias = dir ? biasb : biasf;

    int tid = threadIdx.x, lane = tid & 31, w = tid >> 5;
    int gid = lane >> 2, qk = (lane & 3) << 1;
    int ur = tid >> 3, uj = (tid & 7) << 4;

    float c_reg[16], hs[16];
#pragma unroll
    for (int i = 0; i < 16; i++) { c_reg[i] = 0.f; hs[i] = 0.f; }
    for (int i = tid; i < 32 * SH_STR; i += 256) sh_h[i] = 0.f;
    for (int i = tid; i < 512; i += 256) sbias[i] = bias[i];
    __syncthreads();

    for (int s = 0; s < T_; s++) {
        int t = dir ? (T_ - 1 - s) : s;
        // stage doc tile [32][208] (pad to 208 with zeros); previous readers done (end-of-loop sync)
        for (int idx = tid; idx < 32 * 52; idx += 256) {
            int rr = idx / 52, c4 = idx - rr * 52;
            int k = c4 << 2;
            float4 v = (k < WD_)
                ? *(const float4*)(doc + ((size_t)(r0 + rr) * T_ + t) * WD_ + k)
                : make_float4(0.f, 0.f, 0.f, 0.f);
            *(float4*)&sd[rr * SD_STR + k] = v;
        }
        __syncthreads();

        // init acc with bias
        float acc[2][8][4];
#pragma unroll
        for (int mt = 0; mt < 2; mt++)
#pragma unroll
            for (int nt = 0; nt < 8; nt++) {
                int col = w * 64 + nt * 8 + qk;
                float b0 = sbias[col], b1 = sbias[col + 1];
                acc[mt][nt][0] = b0; acc[mt][nt][1] = b1;
                acc[mt][nt][2] = b0; acc[mt][nt][3] = b1;
            }

        // x-projection: 13 k-tiles over sd
#pragma unroll 1
        for (int kt = 0; kt < 13; kt++) {
            uint4 wv[8];
            const uint4* wpt = wih0 + (kt * 64 + w * 8) * 32 + lane;
#pragma unroll
            for (int nt = 0; nt < 8; nt++) wv[nt] = wpt[nt * 32];
            unsigned af[2][2][4];
#pragma unroll
            for (int mt = 0; mt < 2; mt++) {
                lda_frag(af[mt][0], sd, SD_STR, mt * 16, kt * 16,     lane);
                lda_frag(af[mt][1], sd, SD_STR, mt * 16, kt * 16 + 8, lane);
            }
#pragma unroll
            for (int nt = 0; nt < 8; nt++) {
                unsigned b0[2] = { wv[nt].x, wv[nt].y };
                unsigned b1[2] = { wv[nt].z, wv[nt].w };
#pragma unroll
                for (int mt = 0; mt < 2; mt++) {
                    MMA_TF32(acc[mt][nt], af[mt][0], b0);
                    MMA_TF32(acc[mt][nt], af[mt][1], b1);
                }
            }
        }

        // h-projection: 8 k-tiles over sh_h
#pragma unroll 1
        for (int kt = 0; kt < 8; kt++) {
            uint4 wv[8];
            const uint4* wpt = whh0 + (kt * 64 + w * 8) * 32 + lane;
#pragma unroll
            for (int nt = 0; nt < 8; nt++) wv[nt] = wpt[nt * 32];
            unsigned af[2][2][4];
#pragma unroll
            for (int mt = 0; mt < 2; mt++) {
                lda_frag(af[mt][0], sh_h, SH_STR, mt * 16, kt * 16,     lane);
                lda_frag(af[mt][1], sh_h, SH_STR, mt * 16, kt * 16 + 8, lane);
            }
#pragma unroll
            for (int nt = 0; nt < 8; nt++) {
                unsigned b0[2] = { wv[nt].x, wv[nt].y };
                unsigned b1[2] = { wv[nt].z, wv[nt].w };
#pragma unroll
                for (int mt = 0; mt < 2; mt++) {
                    MMA_TF32(acc[mt][nt], af[mt][0], b0);
                    MMA_TF32(acc[mt][nt], af[mt][1], b1);
                }
            }
        }

        // scatter gates for cross-warp exchange
#pragma unroll
        for (int mt = 0; mt < 2; mt++)
#pragma unroll
            for (int nt = 0; nt < 8; nt++) {
                int lrow = mt * 16 + gid;
                int col = w * 64 + nt * 8 + qk;
                *(float2*)&sh_g[lrow * 520 + col] = make_float2(acc[mt][nt][0], acc[mt][nt][1]);
                *(float2*)&sh_g[(lrow + 8) * 520 + col] = make_float2(acc[mt][nt][2], acc[mt][nt][3]);
            }
        __syncthreads();

        // LSTM cell update (thread owns row ur, cols uj..uj+15)
#pragma unroll
        for (int jj = 0; jj < 16; jj++) {
            int j = uj + jj;
            float ig = sh_g[ur * 520 + j];
            float fg = sh_g[ur * 520 + 128 + j];
            float gg = sh_g[ur * 520 + 256 + j];
            float og = sh_g[ur * 520 + 384 + j];
            float cv = sigf(fg) * c_reg[jj] + sigf(ig) * tanhf(gg);
            c_reg[jj] = cv;
            float h = sigf(og) * tanhf(cv);
            hs[jj] += h;
            sh_h[ur * SH_STR + j] = h;
        }
        __syncthreads();
    }
#pragma unroll
    for (int jj = 0; jj < 16; jj++)
        sentpres[(r0 + ur) * 256 + dir * 128 + uj + jj] = tanhf(hs[jj] * (1.0f / T_));
}

// ================== generic tiled SGEMM (small GEMMs, fp32) ==================
__global__ void sgemm_k(const float* __restrict__ A, const float* __restrict__ W,
                        const float* __restrict__ bias, float* __restrict__ C,
                        int M, int K, int G, int amode, int relu)
{
    __shared__ float As[8][64];
    __shared__ float Ws[8][64];
    int tid = threadIdx.x;
    int mb = blockIdx.y << 6;
    int gb = blockIdx.x << 6;
    int tx = tid & 15, ty = tid >> 4;
    int mi = tid & 63;
    int kh = (tid >> 6) << 1;

    int m = mb + mi;
    long arow;
    if (amode == 0) arow = (long)m * K;
    else { int b = m & 31; int n = m >> 5; arow = (long)((b << 6) + n) * K; }
    long wrow = (long)(gb + mi) * K;

    float acc[4][4];
#pragma unroll
    for (int i = 0; i < 4; i++)
#pragma unroll
        for (int j = 0; j < 4; j++) acc[i][j] = 0.0f;

    for (int k0 = 0; k0 < K; k0 += 8) {
        float2 av = *(const float2*)(A + arow + k0 + kh);
        float2 wv = *(const float2*)(W + wrow + k0 + kh);
        __syncthreads();
        As[kh][mi] = av.x; As[kh + 1][mi] = av.y;
        Ws[kh][mi] = wv.x; Ws[kh + 1][mi] = wv.y;
        __syncthreads();
#pragma unroll
        for (int kk = 0; kk < 8; kk++) {
            float4 a = *(float4*)(&As[kk][ty << 2]);
            float4 w = *(float4*)(&Ws[kk][tx << 2]);
            float aa[4] = {a.x, a.y, a.z, a.w};
            float ww[4] = {w.x, w.y, w.z, w.w};
#pragma unroll
            for (int i = 0; i < 4; i++)
#pragma unroll
                for (int j = 0; j < 4; j++) acc[i][j] += aa[i] * ww[j];
        }
    }

    float4 b4 = *(const float4*)(bias + gb + (tx << 2));
    float bb[4] = {b4.x, b4.y, b4.z, b4.w};
#pragma unroll
    for (int i = 0; i < 4; i++) {
        float4 r;
        r.x = acc[i][0] + bb[0];
        r.y = acc[i][1] + bb[1];
        r.z = acc[i][2] + bb[2];
        r.w = acc[i][3] + bb[3];
        if (relu) {
            r.x = fmaxf(r.x, 0.f); r.y = fmaxf(r.y, 0.f);
            r.z = fmaxf(r.z, 0.f); r.w = fmaxf(r.w, 0.f);
        }
        *(float4*)(C + (size_t)(mb + (ty << 2) + i) * G + gb + (tx << 2)) = r;
    }
}

// ================== persistent tag BiLSTM ==================
#define TAGP_SMEM ((4096 + 8192 + 2048) * 4)
__global__ void lstm_tag_pers(const float* __restrict__ Gt, const float* __restrict__ whhT,
                              float* __restrict__ h_buf, float* __restrict__ tag_out)
{
    extern __shared__ float sm[];
    float* sh_h = sm;
    float* sh_w = sm + 4096;
    float* sh_g = sh_w + 8192;

    int dir = blockIdx.y;
    int jb = blockIdx.x << 4;
    const float* wT = whhT + dir * 65536;
    int tid = threadIdx.x;

    for (int i = tid; i < 8192; i += 256) {
        int k = i >> 6; int col = i & 63; int grp = col >> 4; int jj = col & 15;
        sh_w[i] = wT[k * 512 + grp * 128 + jb + jj];
    }
    int r = tid >> 3;
    int c0 = (tid & 7) << 3;
    float creg[2] = {0.f, 0.f};

    for (int s = 0; s < 64; s++) {
        int n = dir ? (63 - s) : s;
        const float* G = Gt + ((size_t)dir * 2048 + n * 32) * 512;
        const float* hprev = h_buf + ((s & 1) * 2 + dir) * 4096;
        float* hnext = h_buf + (((s + 1) & 1) * 2 + dir) * 4096;

        if (s == 0) {
            for (int i = tid; i < 4096; i += 256) sh_h[i] = 0.f;
        } else {
            for (int i = tid; i < 4096; i += 256) sh_h[i] = __ldcg(&hprev[i]);
        }
        __syncthreads();

        float acc[8];
#pragma unroll
        for (int q = 0; q < 8; q++) {
            int col = c0 + q; int grp = col >> 4; int jj = col & 15;
            acc[q] = G[r * 512 + grp * 128 + jb + jj];
        }
        for (int k = 0; k < 128; k++) {
            float hv = sh_h[r * 128 + k];
            float4 wa = *(float4*)&sh_w[k * 64 + c0];
            float4 wb4 = *(float4*)&sh_w[k * 64 + c0 + 4];
            acc[0] += hv * wa.x;  acc[1] += hv * wa.y;
            acc[2] += hv * wa.z;  acc[3] += hv * wa.w;
            acc[4] += hv * wb4.x; acc[5] += hv * wb4.y;
            acc[6] += hv * wb4.z; acc[7] += hv * wb4.w;
        }
#pragma unroll
        for (int q = 0; q < 8; q++) sh_g[r * 64 + c0 + q] = acc[q];
        __syncthreads();

#pragma unroll
        for (int u = 0; u < 2; u++) {
            int e = tid * 2 + u;
            int ru = e >> 4; int jj = e & 15; int j = jb + jj;
            float ig = sh_g[ru * 64 + jj];
            float fg = sh_g[ru * 64 + 16 + jj];
            float gg = sh_g[ru * 64 + 32 + jj];
            float og = sh_g[ru * 64 + 48 + jj];
            float cn = sigf(fg) * creg[u] + sigf(ig) * tanhf(gg);
            creg[u] = cn;
            float h = sigf(og) * tanhf(cn);
            hnext[ru * 128 + j] = h;
            tag_out[(size_t)(ru * 64 + n) * 256 + dir * 128 + j] = tanhf(h);
        }

        if (s < 63) {
            __threadfence();
            __syncthreads();
            if (tid == 0) {
                atomicAdd(&tag_bar[dir], 1);
                while (atomicAdd(&tag_bar[dir], 0) < 8 * (s + 1)) { }
            }
            __syncthreads();
        }
    }
}

// ================== SPP ==================
__global__ void spp_kernel(const float* __restrict__ q, const float* __restrict__ k,
                           float* __restrict__ out)
{
    int bn = blockIdx.x;
    int b = bn >> 6;
    __shared__ float shq[256];
    __shared__ float att[64];
    __shared__ float e8[8];
    int tid = threadIdx.x;
    for (int l = tid; l < 256; l += 64) shq[l] = q[(size_t)bn * 256 + l];
    __syncthreads();
    const float* kr = k + (size_t)(b * 64 + tid) * 256;
    float s = 0.f;
    for (int l = 0; l < 256; l += 4) {
        float4 qa = *(float4*)&shq[l];
        float4 ka = *(const float4*)&kr[l];
        s += qa.x * ka.x + qa.y * ka.y + qa.z * ka.z + qa.w * ka.w;
    }
    att[tid] = s * 0.0625f;
    __syncthreads();
    if (tid < 8) {
        float m = att[tid * 8];
#pragma unroll
        for (int l = 1; l < 8; l++) m = fmaxf(m, att[tid * 8 + l]);
        e8[tid] = m;
    }
    __syncthreads();
    if (tid == 0) {
        float q4[4];
#pragma unroll
        for (int l = 0; l < 4; l++) q4[l] = fmaxf(e8[2 * l], e8[2 * l + 1]);
        float h2a = fmaxf(q4[0], q4[1]);
        float h2b = fmaxf(q4[2], q4[3]);
        float* o = out + bn * 15;
        o[0] = fmaxf(h2a, h2b);
        o[1] = h2a; o[2] = h2b;
        o[3] = q4[0]; o[4] = q4[1]; o[5] = q4[2]; o[6] = q4[3];
#pragma unroll
        for (int l = 0; l < 8; l++) o[7 + l] = e8[l];
    }
}

// ================== GCN ==================
#define GCN_SMEM ((64 * 256 + 64 * 64 + 64) * 4)
__global__ void gcn_kernel(const float* __restrict__ x, float* __restrict__ agg)
{
    extern __shared__ float gs[];
    float* shx = gs;
    float* shc = gs + 16384;
    float* shn = gs + 20480;
    int b = blockIdx.x;
    int tid = threadIdx.x;
    for (int l = tid; l < 16384; l += 256) shx[l] = x[(size_t)b * 16384 + l];
    __syncthreads();
    if (tid < 64) {
        float s = 0.f;
        for (int l = 0; l < 256; l++) { float v = shx[tid * 256 + l]; s += v * v; }
        shn[tid] = sqrtf(s) + 1e-8f;
    }
    __syncthreads();
    for (int p = tid; p < 4096; p += 256) {
        int i = p >> 6, j = p & 63;
        float s = 0.f;
        for (int l = 0; l < 256; l++) s += shx[i * 256 + l] * shx[j * 256 + l];
        shc[p] = s / (shn[i] * shn[j]);
    }
    __syncthreads();
    for (int p = tid; p < 16384; p += 256) {
        int i = p >> 8, d = p & 255;
        float s = 2.0f * shx[i * 256 + d];
        for (int j = 0; j < 64; j++) s += shc[i * 64 + j] * shx[j * 256 + d];
        agg[(size_t)b * 16384 + p] = s * (1.0f / 66.0f);
    }
}

// ================== classifier + log_softmax ==================
__global__ void cls_kernel(const float* __restrict__ tago, const float* __restrict__ sFt,
                           const float* __restrict__ rFt, const float* __restrict__ W,
                           const float* __restrict__ bias, float* __restrict__ out)
{
    int bn = blockIdx.x;
    int c = threadIdx.x;
    __shared__ float sh[8];
    if (c < 8) {
        const float* w = W + c * 286;
        float s = bias[c];
        const float* t = tago + (size_t)bn * 256;
        for (int l = 0; l < 256; l++) s += t[l] * w[l];
        const float* sf = sFt + bn * 15;
        for (int l = 0; l < 15; l++) s += sf[l] * w[256 + l];
        const float* rf = rFt + bn * 15;
        for (int l = 0; l < 15; l++) s += rf[l] * w[271 + l];
        sh[c] = s;
    }
    __syncthreads();
    if (c < 8) {
        float m = sh[0];
#pragma unroll
        for (int l = 1; l < 8; l++) m = fmaxf(m, sh[l]);
        float se = 0.f;
#pragma unroll
        for (int l = 0; l < 8; l++) se += expf(sh[l] - m);
        out[bn * 8 + c] = sh[c] - m - logf(se);
    }
}

// ================== launch ==================
extern "C" void kernel_launch(void* const* d_in, const int* in_sizes, int n_in,
                              void* d_out, int out_size)
{
    const float* documents = (const float*)d_in[0];
    const float* sw_ih_f = (const float*)d_in[1];
    const float* sw_hh_f = (const float*)d_in[2];
    const float* sb_f    = (const float*)d_in[3];
    const float* sw_ih_b = (const float*)d_in[4];
    const float* sw_hh_b = (const float*)d_in[5];
    const float* sb_b    = (const float*)d_in[6];
    const float* sf_Wq = (const float*)d_in[7];
    const float* sf_bq = (const float*)d_in[8];
    const float* sf_Wk = (const float*)d_in[9];
    const float* sf_bk = (const float*)d_in[10];
    const float* rf_Wq = (const float*)d_in[11];
    const float* rf_bq = (const float*)d_in[12];
    const float* rf_Wk = (const float*)d_in[13];
    const float* rf_bk = (const float*)d_in[14];
    const float* tw_ih_f = (const float*)d_in[15];
    const float* tw_hh_f = (const float*)d_in[16];
    const float* tb_f    = (const float*)d_in[17];
    const float* tw_ih_b = (const float*)d_in[18];
    const float* tw_hh_b = (const float*)d_in[19];
    const float* tb_b    = (const float*)d_in[20];
    const float* sage_W = (const float*)d_in[21];
    const float* sage_b = (const float*)d_in[22];
    const float* cls_W  = (const float*)d_in[23];
    const float* cls_b  = (const float*)d_in[24];

    float* out = (float*)d_out;
    float* result_out = out;
    float* gcn_out = out + B_ * N_ * C_;

    float *whhT_t, *sentpres, *qb, *kb, *sFt, *rFt, *gtag, *htag, *tago, *agg;
    uint4 *wihp, *whhp;
    int* barp;
    cudaGetSymbolAddress((void**)&wihp, wih_pk_buf);
    cudaGetSymbolAddress((void**)&whhp, whh_pk_buf);
    cudaGetSymbolAddress((void**)&whhT_t, whhT_tag_buf);
    cudaGetSymbolAddress((void**)&sentpres, sentpres_buf);
    cudaGetSymbolAddress((void**)&qb, q_buf);
    cudaGetSymbolAddress((void**)&kb, k_buf);
    cudaGetSymbolAddress((void**)&sFt, sentFt_buf);
    cudaGetSymbolAddress((void**)&rFt, roleFt_buf);
    cudaGetSymbolAddress((void**)&gtag, g_tag_buf);
    cudaGetSymbolAddress((void**)&htag, h_tag_buf);
    cudaGetSymbolAddress((void**)&tago, tag_out_buf);
    cudaGetSymbolAddress((void**)&agg, agg_buf);
    cudaGetSymbolAddress((void**)&barp, tag_bar);

    cudaFuncSetAttribute(lstm_sent_fused, cudaFuncAttributeMaxDynamicSharedMemorySize, FUSED_SMEM);
    cudaFuncSetAttribute(lstm_tag_pers, cudaFuncAttributeMaxDynamicSharedMemorySize, TAGP_SMEM);
    cudaFuncSetAttribute(gcn_kernel, cudaFuncAttributeMaxDynamicSharedMemorySize, GCN_SMEM);

    // prep (launch indices 0-2)
    pack_wih_tf32<<<(2 * 13 * 64 * 32 + 255) / 256, 256>>>(sw_ih_f, sw_ih_b, wihp);
    pack_whh_tf32<<<128, 256>>>(sw_hh_f, sw_hh_b, whhp);
    transpose_whh<<<dim3(64, 2), 256>>>(tw_hh_f, tw_hh_b, whhT_t);

    // FUSED sentence BiLSTM (index 3 — ncu capture slot)
    lstm_sent_fused<<<dim3(64, 2), 256, FUSED_SMEM>>>(documents, wihp, whhp, sb_f, sb_b, sentpres);

    // sentFt SPP
    sgemm_k<<<dim3(4, 32), 256>>>(sentpres, sf_Wq, sf_bq, qb, BN_, D2_, D2_, 0, 0);
    sgemm_k<<<dim3(4, 32), 256>>>(sentpres, sf_Wk, sf_bk, kb, BN_, D2_, D2_, 0, 0);
    spp_kernel<<<2048, 64>>>(qb, kb, sFt);

    // Tag LSTM input projections
    sgemm_k<<<dim3(8, 32), 256>>>(sentpres, tw_ih_f, tb_f, gtag,             BN_, D2_, G4_, 1, 0);
    sgemm_k<<<dim3(8, 32), 256>>>(sentpres, tw_ih_b, tb_b, gtag + BN_ * G4_, BN_, D2_, G4_, 1, 0);

    // Persistent tag BiLSTM
    cudaMemsetAsync(barp, 0, 2 * sizeof(int));
    lstm_tag_pers<<<dim3(8, 2), 256, TAGP_SMEM>>>(gtag, whhT_t, htag, tago);

    // GCN
    gcn_kernel<<<32, 256, GCN_SMEM>>>(tago, agg);
    sgemm_k<<<dim3(4, 32), 256>>>(agg, sage_W, sage_b, gcn_out, BN_, D2_, D2_, 0, 1);

    // roleFt SPP
    sgemm_k<<<dim3(4, 32), 256>>>(tago, rf_Wq, rf_bq, qb, BN_, D2_, D2_, 0, 0);
    sgemm_k<<<dim3(4, 32), 256>>>(tago, rf_Wk, rf_bk, kb, BN_, D2_, D2_, 0, 0);
    spp_kernel<<<2048, 64>>>(qb, kb, rFt);

    cls_kernel<<<2048, 32>>>(tago, sFt, rFt, cls_W, cls_b, result_out);

    (void)in_sizes; (void)n_in; (void)out_size;
}

// round 7
// speedup vs baseline: 2.9350x; 1.0960x over previous
#include <cuda_runtime.h>
#include <cuda_bf16.h>
#include <stdint.h>
#include <math.h>

// ---------------- problem constants ----------------
#define B_    32
#define N_    64
#define T_    50
#define WD_   200
#define H_    128
#define G4_   512
#define D2_   256
#define BN_   2048
#define C_    8

// ---------------- scratch ----------------
__device__ uint4 wih_pk_buf[2 * 13 * 64 * 32];  // packed W_ih tf32 B-frags [dir][kt][ng][lane]
__device__ uint4 whh_pk_buf[2 * 8 * 64 * 32];   // packed W_hh tf32 B-frags
__device__ float whhT_tag_buf[2 * 128 * 512];
__device__ float sentpres_buf[BN_ * D2_];
__device__ float q_buf[BN_ * D2_];
__device__ float k_buf[BN_ * D2_];
__device__ float sentFt_buf[BN_ * 15];
__device__ float roleFt_buf[BN_ * 15];
__device__ float g_tag_buf[2 * BN_ * G4_];
__device__ float h_tag_buf[4 * 32 * 128];
__device__ float tag_out_buf[BN_ * D2_];
__device__ float agg_buf[BN_ * D2_];
__device__ int tag_bar[2];

__device__ __forceinline__ float sigf(float x) { return __fdividef(1.0f, 1.0f + __expf(-x)); }

#define MMA_TF32(d, a, b) \
    asm volatile("mma.sync.aligned.m16n8k8.row.col.f32.tf32.tf32.f32 " \
                 "{%0,%1,%2,%3},{%4,%5,%6,%7},{%8,%9},{%0,%1,%2,%3};\n" \
                 : "+f"(d[0]), "+f"(d[1]), "+f"(d[2]), "+f"(d[3]) \
                 : "r"(a[0]), "r"(a[1]), "r"(a[2]), "r"(a[3]), "r"(b[0]), "r"(b[1]))

__device__ __forceinline__ void ldsm_x4(unsigned& r0, unsigned& r1, unsigned& r2, unsigned& r3,
                                        const float* p)
{
    unsigned addr = (unsigned)__cvta_generic_to_shared(p);
    asm volatile("ldmatrix.sync.aligned.m8n8.x4.shared.b16 {%0,%1,%2,%3}, [%4];"
                 : "=r"(r0), "=r"(r1), "=r"(r2), "=r"(r3) : "r"(addr));
}

__device__ __forceinline__ void lda_frag(unsigned af[4], const float* base, int stride,
                                         int mrow0, int kcol0, int lane)
{
    int tile = lane >> 3, rin = lane & 7;
    int row = mrow0 + ((tile & 1) << 3) + rin;
    int col = kcol0 + ((tile >> 1) << 2);
    ldsm_x4(af[0], af[1], af[2], af[3], base + row * stride + col);
}

// ================== pack W_ih (512x200) into tf32 B-fragments ==================
__global__ void pack_wih_tf32(const float* __restrict__ wf, const float* __restrict__ wb,
                              uint4* __restrict__ out)
{
    int i = blockIdx.x * 256 + threadIdx.x;
    if (i >= 2 * 13 * 64 * 32) return;
    const int per = 13 * 64 * 32;
    int dir = i / per, rem = i % per;
    int kt = rem >> 11, ng = (rem >> 5) & 63, lane = rem & 31;
    const float* w = dir ? wb : wf;
    int n = ng * 8 + (lane >> 2);
    int k = kt * 16 + (lane & 3);
    uint4 v;
    v.x = (k      < WD_) ? __float_as_uint(w[n * WD_ + k])      : 0u;
    v.y = (k + 4  < WD_) ? __float_as_uint(w[n * WD_ + k + 4])  : 0u;
    v.z = (k + 8  < WD_) ? __float_as_uint(w[n * WD_ + k + 8])  : 0u;
    v.w = (k + 12 < WD_) ? __float_as_uint(w[n * WD_ + k + 12]) : 0u;
    out[i] = v;
}

// ================== pack W_hh (512x128) into tf32 B-fragments ==================
__global__ void pack_whh_tf32(const float* __restrict__ wf, const float* __restrict__ wb,
                              uint4* __restrict__ out)
{
    int i = blockIdx.x * 256 + threadIdx.x;
    if (i >= 2 * 8 * 64 * 32) return;
    int lane = i & 31, ng = (i >> 5) & 63, kt = (i >> 11) & 7, dir = i >> 14;
    const float* w = dir ? wb : wf;
    int n = ng * 8 + (lane >> 2);
    int k = kt * 16 + (lane & 3);
    uint4 v;
    v.x = __float_as_uint(w[n * 128 + k]);
    v.y = __float_as_uint(w[n * 128 + k + 4]);
    v.z = __float_as_uint(w[n * 128 + k + 8]);
    v.w = __float_as_uint(w[n * 128 + k + 12]);
    out[i] = v;
}

// ================== transpose W_hh (512x128) -> (128x512) for tag LSTM ==================
__global__ void transpose_whh(const float* __restrict__ wf, const float* __restrict__ wb,
                              float* __restrict__ outT)
{
    int dir = blockIdx.y;
    const float* w = dir ? wb : wf;
    float* o = outT + dir * 65536;
    for (int i = blockIdx.x * 256 + threadIdx.x; i < 65536; i += 64 * 256) {
        int k = i >> 9, g = i & 511;
        o[i] = w[g * 128 + k];
    }
}

// ================== FUSED sentence BiLSTM v2: pipelined tf32 mma ==================
// grid (64, 2), 256 threads / 8 warps. Block: 32 batch rows, 512 gates.
// smem float offsets:
#define SD_STR 212
#define SH_STR 132
#define OFF_SD0   0
#define OFF_SD1   6784
#define OFF_HH    13568
#define OFF_GG    17792
#define OFF_BIAS  34432
#define FUSED_SMEM ((34432 + 512) * 4)

__global__ __launch_bounds__(256, 1)
void lstm_sent_fused(const float* __restrict__ doc,
                     const uint4* __restrict__ wih, const uint4* __restrict__ whh,
                     const float* __restrict__ biasf, const float* __restrict__ biasb,
                     float* __restrict__ sentpres)
{
    extern __shared__ __align__(16) float smf[];
    float* sh_h  = smf + OFF_HH;    // [32][132]
    float* sh_g  = smf + OFF_GG;    // [32][520]
    float* sbias = smf + OFF_BIAS;  // [512]

    int dir = blockIdx.y;
    int r0 = blockIdx.x << 5;
    const uint4* wih0 = wih + dir * 13 * 64 * 32;
    const uint4* whh0 = whh + dir * 8 * 64 * 32;
    const float* bias = dir ? biasb : biasf;

    int tid = threadIdx.x, lane = tid & 31, w = tid >> 5;
    int gid = lane >> 2, qk = (lane & 3) << 1;
    int ur = tid >> 3, uj = (tid & 7) << 4;

    float c_reg[16], hs[16];
#pragma unroll
    for (int i = 0; i < 16; i++) { c_reg[i] = 0.f; hs[i] = 0.f; }
    for (int i = tid; i < 32 * SH_STR; i += 256) sh_h[i] = 0.f;
    for (int i = tid; i < 512; i += 256) sbias[i] = bias[i];

    // preload doc tile for step 0 into sd buffer 0
    {
        int t0 = dir ? (T_ - 1) : 0;
        for (int idx = tid; idx < 32 * 52; idx += 256) {
            int rr = idx / 52, c4 = idx - rr * 52;
            int k = c4 << 2;
            float4 v = (k < WD_)
                ? *(const float4*)(doc + ((size_t)(r0 + rr) * T_ + t0) * WD_ + k)
                : make_float4(0.f, 0.f, 0.f, 0.f);
            *(float4*)&smf[OFF_SD0 + rr * SD_STR + k] = v;
        }
    }
    __syncthreads();

    int buf = 0;
    for (int s = 0; s < T_; s++) {
        const float* sd = smf + (buf ? OFF_SD1 : OFF_SD0);

        // init acc with bias
        float acc[2][8][4];
#pragma unroll
        for (int mt = 0; mt < 2; mt++)
#pragma unroll
            for (int nt = 0; nt < 8; nt++) {
                int col = w * 64 + nt * 8 + qk;
                float b0 = sbias[col], b1 = sbias[col + 1];
                acc[mt][nt][0] = b0; acc[mt][nt][1] = b1;
                acc[mt][nt][2] = b0; acc[mt][nt][3] = b1;
            }

        // unified pipelined loop: kt 0..12 = x-proj (sd), kt 13..20 = h-proj (sh_h)
        uint4 wv0[8], wv1[8];
        {
            const uint4* p = wih0 + (w * 8) * 32 + lane;   // kt = 0
#pragma unroll
            for (int nt = 0; nt < 8; nt++) wv0[nt] = p[nt * 32];
        }

#define LOADW(dst, ktv) do { \
            int _kt = (ktv); \
            const uint4* _p = (_kt < 13) ? (wih0 + (_kt * 64 + w * 8) * 32 + lane) \
                                         : (whh0 + ((_kt - 13) * 64 + w * 8) * 32 + lane); \
            _Pragma("unroll") \
            for (int nt = 0; nt < 8; nt++) dst[nt] = _p[nt * 32]; \
        } while (0)

#define COMPUTE(ktv, wv) do { \
            int _kt = (ktv); \
            const float* _ab = (_kt < 13) ? sd : sh_h; \
            int _astr = (_kt < 13) ? SD_STR : SH_STR; \
            int _kc = (_kt < 13) ? (_kt << 4) : ((_kt - 13) << 4); \
            unsigned _af[2][2][4]; \
            _Pragma("unroll") \
            for (int mt = 0; mt < 2; mt++) { \
                lda_frag(_af[mt][0], _ab, _astr, mt * 16, _kc, lane); \
                lda_frag(_af[mt][1], _ab, _astr, mt * 16, _kc + 8, lane); \
            } \
            _Pragma("unroll") \
            for (int nt = 0; nt < 8; nt++) { \
                unsigned _b0[2] = { wv[nt].x, wv[nt].y }; \
                unsigned _b1[2] = { wv[nt].z, wv[nt].w }; \
                _Pragma("unroll") \
                for (int mt = 0; mt < 2; mt++) { \
                    MMA_TF32(acc[mt][nt], _af[mt][0], _b0); \
                    MMA_TF32(acc[mt][nt], _af[mt][1], _b1); \
                } \
            } \
        } while (0)

#pragma unroll 1
        for (int k2 = 0; k2 < 20; k2 += 2) {
            LOADW(wv1, k2 + 1);
            COMPUTE(k2, wv0);
            LOADW(wv0, k2 + 2);
            COMPUTE(k2 + 1, wv1);
        }
        COMPUTE(20, wv0);
#undef LOADW
#undef COMPUTE

        // scatter gates for cross-warp exchange
#pragma unroll
        for (int mt = 0; mt < 2; mt++)
#pragma unroll
            for (int nt = 0; nt < 8; nt++) {
                int lrow = mt * 16 + gid;
                int col = w * 64 + nt * 8 + qk;
                *(float2*)&sh_g[lrow * 520 + col] = make_float2(acc[mt][nt][0], acc[mt][nt][1]);
                *(float2*)&sh_g[(lrow + 8) * 520 + col] = make_float2(acc[mt][nt][2], acc[mt][nt][3]);
            }

        // prefetch doc tile for step s+1 into the other buffer (overlaps cell + syncs)
        if (s + 1 < T_) {
            int tn = dir ? (T_ - 2 - s) : (s + 1);
            float* sdn = smf + (buf ? OFF_SD0 : OFF_SD1);
            for (int idx = tid; idx < 32 * 52; idx += 256) {
                int rr = idx / 52, c4 = idx - rr * 52;
                int k = c4 << 2;
                float4 v = (k < WD_)
                    ? *(const float4*)(doc + ((size_t)(r0 + rr) * T_ + tn) * WD_ + k)
                    : make_float4(0.f, 0.f, 0.f, 0.f);
                *(float4*)&sdn[rr * SD_STR + k] = v;
            }
        }
        __syncthreads();

        // LSTM cell update (thread owns row ur, cols uj..uj+15)
#pragma unroll
        for (int jj = 0; jj < 16; jj++) {
            int j = uj + jj;
            float ig = sh_g[ur * 520 + j];
            float fg = sh_g[ur * 520 + 128 + j];
            float gg = sh_g[ur * 520 + 256 + j];
            float og = sh_g[ur * 520 + 384 + j];
            float cv = sigf(fg) * c_reg[jj] + sigf(ig) * tanhf(gg);
            c_reg[jj] = cv;
            float h = sigf(og) * tanhf(cv);
            hs[jj] += h;
            sh_h[ur * SH_STR + j] = h;
        }
        __syncthreads();
        buf ^= 1;
    }
#pragma unroll
    for (int jj = 0; jj < 16; jj++)
        sentpres[(r0 + ur) * 256 + dir * 128 + uj + jj] = tanhf(hs[jj] * (1.0f / T_));
}

// ================== generic tiled SGEMM (small GEMMs, fp32) ==================
__global__ void sgemm_k(const float* __restrict__ A, const float* __restrict__ W,
                        const float* __restrict__ bias, float* __restrict__ C,
                        int M, int K, int G, int amode, int relu)
{
    __shared__ float As[8][64];
    __shared__ float Ws[8][64];
    int tid = threadIdx.x;
    int mb = blockIdx.y << 6;
    int gb = blockIdx.x << 6;
    int tx = tid & 15, ty = tid >> 4;
    int mi = tid & 63;
    int kh = (tid >> 6) << 1;

    int m = mb + mi;
    long arow;
    if (amode == 0) arow = (long)m * K;
    else { int b = m & 31; int n = m >> 5; arow = (long)((b << 6) + n) * K; }
    long wrow = (long)(gb + mi) * K;

    float acc[4][4];
#pragma unroll
    for (int i = 0; i < 4; i++)
#pragma unroll
        for (int j = 0; j < 4; j++) acc[i][j] = 0.0f;

    for (int k0 = 0; k0 < K; k0 += 8) {
        float2 av = *(const float2*)(A + arow + k0 + kh);
        float2 wv = *(const float2*)(W + wrow + k0 + kh);
        __syncthreads();
        As[kh][mi] = av.x; As[kh + 1][mi] = av.y;
        Ws[kh][mi] = wv.x; Ws[kh + 1][mi] = wv.y;
        __syncthreads();
#pragma unroll
        for (int kk = 0; kk < 8; kk++) {
            float4 a = *(float4*)(&As[kk][ty << 2]);
            float4 w = *(float4*)(&Ws[kk][tx << 2]);
            float aa[4] = {a.x, a.y, a.z, a.w};
            float ww[4] = {w.x, w.y, w.z, w.w};
#pragma unroll
            for (int i = 0; i < 4; i++)
#pragma unroll
                for (int j = 0; j < 4; j++) acc[i][j] += aa[i] * ww[j];
        }
    }

    float4 b4 = *(const float4*)(bias + gb + (tx << 2));
    float bb[4] = {b4.x, b4.y, b4.z, b4.w};
#pragma unroll
    for (int i = 0; i < 4; i++) {
        float4 r;
        r.x = acc[i][0] + bb[0];
        r.y = acc[i][1] + bb[1];
        r.z = acc[i][2] + bb[2];
        r.w = acc[i][3] + bb[3];
        if (relu) {
            r.x = fmaxf(r.x, 0.f); r.y = fmaxf(r.y, 0.f);
            r.z = fmaxf(r.z, 0.f); r.w = fmaxf(r.w, 0.f);
        }
        *(float4*)(C + (size_t)(mb + (ty << 2) + i) * G + gb + (tx << 2)) = r;
    }
}

// ================== persistent tag BiLSTM ==================
#define TAGP_SMEM ((4096 + 8192 + 2048) * 4)
__global__ void lstm_tag_pers(const float* __restrict__ Gt, const float* __restrict__ whhT,
                              float* __restrict__ h_buf, float* __restrict__ tag_out)
{
    extern __shared__ float sm[];
    float* sh_h = sm;
    float* sh_w = sm + 4096;
    float* sh_g = sh_w + 8192;

    int dir = blockIdx.y;
    int jb = blockIdx.x << 4;
    const float* wT = whhT + dir * 65536;
    int tid = threadIdx.x;

    for (int i = tid; i < 8192; i += 256) {
        int k = i >> 6; int col = i & 63; int grp = col >> 4; int jj = col & 15;
        sh_w[i] = wT[k * 512 + grp * 128 + jb + jj];
    }
    int r = tid >> 3;
    int c0 = (tid & 7) << 3;
    float creg[2] = {0.f, 0.f};

    for (int s = 0; s < 64; s++) {
        int n = dir ? (63 - s) : s;
        const float* G = Gt + ((size_t)dir * 2048 + n * 32) * 512;
        const float* hprev = h_buf + ((s & 1) * 2 + dir) * 4096;
        float* hnext = h_buf + (((s + 1) & 1) * 2 + dir) * 4096;

        if (s == 0) {
            for (int i = tid; i < 4096; i += 256) sh_h[i] = 0.f;
        } else {
            for (int i = tid; i < 4096; i += 256) sh_h[i] = __ldcg(&hprev[i]);
        }
        __syncthreads();

        float acc[8];
#pragma unroll
        for (int q = 0; q < 8; q++) {
            int col = c0 + q; int grp = col >> 4; int jj = col & 15;
            acc[q] = G[r * 512 + grp * 128 + jb + jj];
        }
        for (int k = 0; k < 128; k++) {
            float hv = sh_h[r * 128 + k];
            float4 wa = *(float4*)&sh_w[k * 64 + c0];
            float4 wb4 = *(float4*)&sh_w[k * 64 + c0 + 4];
            acc[0] += hv * wa.x;  acc[1] += hv * wa.y;
            acc[2] += hv * wa.z;  acc[3] += hv * wa.w;
            acc[4] += hv * wb4.x; acc[5] += hv * wb4.y;
            acc[6] += hv * wb4.z; acc[7] += hv * wb4.w;
        }
#pragma unroll
        for (int q = 0; q < 8; q++) sh_g[r * 64 + c0 + q] = acc[q];
        __syncthreads();

#pragma unroll
        for (int u = 0; u < 2; u++) {
            int e = tid * 2 + u;
            int ru = e >> 4; int jj = e & 15; int j = jb + jj;
            float ig = sh_g[ru * 64 + jj];
            float fg = sh_g[ru * 64 + 16 + jj];
            float gg = sh_g[ru * 64 + 32 + jj];
            float og = sh_g[ru * 64 + 48 + jj];
            float cn = sigf(fg) * creg[u] + sigf(ig) * tanhf(gg);
            creg[u] = cn;
            float h = sigf(og) * tanhf(cn);
            hnext[ru * 128 + j] = h;
            tag_out[(size_t)(ru * 64 + n) * 256 + dir * 128 + j] = tanhf(h);
        }

        if (s < 63) {
            __threadfence();
            __syncthreads();
            if (tid == 0) {
                atomicAdd(&tag_bar[dir], 1);
                while (atomicAdd(&tag_bar[dir], 0) < 8 * (s + 1)) { }
            }
            __syncthreads();
        }
    }
}

// ================== SPP ==================
__global__ void spp_kernel(const float* __restrict__ q, const float* __restrict__ k,
                           float* __restrict__ out)
{
    int bn = blockIdx.x;
    int b = bn >> 6;
    __shared__ float shq[256];
    __shared__ float att[64];
    __shared__ float e8[8];
    int tid = threadIdx.x;
    for (int l = tid; l < 256; l += 64) shq[l] = q[(size_t)bn * 256 + l];
    __syncthreads();
    const float* kr = k + (size_t)(b * 64 + tid) * 256;
    float s = 0.f;
    for (int l = 0; l < 256; l += 4) {
        float4 qa = *(float4*)&shq[l];
        float4 ka = *(const float4*)&kr[l];
        s += qa.x * ka.x + qa.y * ka.y + qa.z * ka.z + qa.w * ka.w;
    }
    att[tid] = s * 0.0625f;
    __syncthreads();
    if (tid < 8) {
        float m = att[tid * 8];
#pragma unroll
        for (int l = 1; l < 8; l++) m = fmaxf(m, att[tid * 8 + l]);
        e8[tid] = m;
    }
    __syncthreads();
    if (tid == 0) {
        float q4[4];
#pragma unroll
        for (int l = 0; l < 4; l++) q4[l] = fmaxf(e8[2 * l], e8[2 * l + 1]);
        float h2a = fmaxf(q4[0], q4[1]);
        float h2b = fmaxf(q4[2], q4[3]);
        float* o = out + bn * 15;
        o[0] = fmaxf(h2a, h2b);
        o[1] = h2a; o[2] = h2b;
        o[3] = q4[0]; o[4] = q4[1]; o[5] = q4[2]; o[6] = q4[3];
#pragma unroll
        for (int l = 0; l < 8; l++) o[7 + l] = e8[l];
    }
}

// ================== GCN ==================
#define GCN_SMEM ((64 * 256 + 64 * 64 + 64) * 4)
__global__ void gcn_kernel(const float* __restrict__ x, float* __restrict__ agg)
{
    extern __shared__ float gs[];
    float* shx = gs;
    float* shc = gs + 16384;
    float* shn = gs + 20480;
    int b = blockIdx.x;
    int tid = threadIdx.x;
    for (int l = tid; l < 16384; l += 256) shx[l] = x[(size_t)b * 16384 + l];
    __syncthreads();
    if (tid < 64) {
        float s = 0.f;
        for (int l = 0; l < 256; l++) { float v = shx[tid * 256 + l]; s += v * v; }
        shn[tid] = sqrtf(s) + 1e-8f;
    }
    __syncthreads();
    for (int p = tid; p < 4096; p += 256) {
        int i = p >> 6, j = p & 63;
        float s = 0.f;
        for (int l = 0; l < 256; l++) s += shx[i * 256 + l] * shx[j * 256 + l];
        shc[p] = s / (shn[i] * shn[j]);
    }
    __syncthreads();
    for (int p = tid; p < 16384; p += 256) {
        int i = p >> 8, d = p & 255;
        float s = 2.0f * shx[i * 256 + d];
        for (int j = 0; j < 64; j++) s += shc[i * 64 + j] * shx[j * 256 + d];
        agg[(size_t)b * 16384 + p] = s * (1.0f / 66.0f);
    }
}

// ================== classifier + log_softmax ==================
__global__ void cls_kernel(const float* __restrict__ tago, const float* __restrict__ sFt,
                           const float* __restrict__ rFt, const float* __restrict__ W,
                           const float* __restrict__ bias, float* __restrict__ out)
{
    int bn = blockIdx.x;
    int c = threadIdx.x;
    __shared__ float sh[8];
    if (c < 8) {
        const float* w = W + c * 286;
        float s = bias[c];
        const float* t = tago + (size_t)bn * 256;
        for (int l = 0; l < 256; l++) s += t[l] * w[l];
        const float* sf = sFt + bn * 15;
        for (int l = 0; l < 15; l++) s += sf[l] * w[256 + l];
        const float* rf = rFt + bn * 15;
        for (int l = 0; l < 15; l++) s += rf[l] * w[271 + l];
        sh[c] = s;
    }
    __syncthreads();
    if (c < 8) {
        float m = sh[0];
#pragma unroll
        for (int l = 1; l < 8; l++) m = fmaxf(m, sh[l]);
        float se = 0.f;
#pragma unroll
        for (int l = 0; l < 8; l++) se += expf(sh[l] - m);
        out[bn * 8 + c] = sh[c] - m - logf(se);
    }
}

// ================== launch ==================
extern "C" void kernel_launch(void* const* d_in, const int* in_sizes, int n_in,
                              void* d_out, int out_size)
{
    const float* documents = (const float*)d_in[0];
    const float* sw_ih_f = (const float*)d_in[1];
    const float* sw_hh_f = (const float*)d_in[2];
    const float* sb_f    = (const float*)d_in[3];
    const float* sw_ih_b = (const float*)d_in[4];
    const float* sw_hh_b = (const float*)d_in[5];
    const float* sb_b    = (const float*)d_in[6];
    const float* sf_Wq = (const float*)d_in[7];
    const float* sf_bq = (const float*)d_in[8];
    const float* sf_Wk = (const float*)d_in[9];
    const float* sf_bk = (const float*)d_in[10];
    const float* rf_Wq = (const float*)d_in[11];
    const float* rf_bq = (const float*)d_in[12];
    const float* rf_Wk = (const float*)d_in[13];
    const float* rf_bk = (const float*)d_in[14];
    const float* tw_ih_f = (const float*)d_in[15];
    const float* tw_hh_f = (const float*)d_in[16];
    const float* tb_f    = (const float*)d_in[17];
    const float* tw_ih_b = (const float*)d_in[18];
    const float* tw_hh_b = (const float*)d_in[19];
    const float* tb_b    = (const float*)d_in[20];
    const float* sage_W = (const float*)d_in[21];
    const float* sage_b = (const float*)d_in[22];
    const float* cls_W  = (const float*)d_in[23];
    const float* cls_b  = (const float*)d_in[24];

    float* out = (float*)d_out;
    float* result_out = out;
    float* gcn_out = out + B_ * N_ * C_;

    float *whhT_t, *sentpres, *qb, *kb, *sFt, *rFt, *gtag, *htag, *tago, *agg;
    uint4 *wihp, *whhp;
    int* barp;
    cudaGetSymbolAddress((void**)&wihp, wih_pk_buf);
    cudaGetSymbolAddress((void**)&whhp, whh_pk_buf);
    cudaGetSymbolAddress((void**)&whhT_t, whhT_tag_buf);
    cudaGetSymbolAddress((void**)&sentpres, sentpres_buf);
    cudaGetSymbolAddress((void**)&qb, q_buf);
    cudaGetSymbolAddress((void**)&kb, k_buf);
    cudaGetSymbolAddress((void**)&sFt, sentFt_buf);
    cudaGetSymbolAddress((void**)&rFt, roleFt_buf);
    cudaGetSymbolAddress((void**)&gtag, g_tag_buf);
    cudaGetSymbolAddress((void**)&htag, h_tag_buf);
    cudaGetSymbolAddress((void**)&tago, tag_out_buf);
    cudaGetSymbolAddress((void**)&agg, agg_buf);
    cudaGetSymbolAddress((void**)&barp, tag_bar);

    cudaFuncSetAttribute(lstm_sent_fused, cudaFuncAttributeMaxDynamicSharedMemorySize, FUSED_SMEM);
    cudaFuncSetAttribute(lstm_tag_pers, cudaFuncAttributeMaxDynamicSharedMemorySize, TAGP_SMEM);
    cudaFuncSetAttribute(gcn_kernel, cudaFuncAttributeMaxDynamicSharedMemorySize, GCN_SMEM);

    // prep (launch indices 0-2)
    pack_wih_tf32<<<(2 * 13 * 64 * 32 + 255) / 256, 256>>>(sw_ih_f, sw_ih_b, wihp);
    pack_whh_tf32<<<128, 256>>>(sw_hh_f, sw_hh_b, whhp);
    transpose_whh<<<dim3(64, 2), 256>>>(tw_hh_f, tw_hh_b, whhT_t);

    // FUSED sentence BiLSTM (index 3 — ncu capture slot)
    lstm_sent_fused<<<dim3(64, 2), 256, FUSED_SMEM>>>(documents, wihp, whhp, sb_f, sb_b, sentpres);

    // sentFt SPP
    sgemm_k<<<dim3(4, 32), 256>>>(sentpres, sf_Wq, sf_bq, qb, BN_, D2_, D2_, 0, 0);
    sgemm_k<<<dim3(4, 32), 256>>>(sentpres, sf_Wk, sf_bk, kb, BN_, D2_, D2_, 0, 0);
    spp_kernel<<<2048, 64>>>(qb, kb, sFt);

    // Tag LSTM input projections
    sgemm_k<<<dim3(8, 32), 256>>>(sentpres, tw_ih_f, tb_f, gtag,             BN_, D2_, G4_, 1, 0);
    sgemm_k<<<dim3(8, 32), 256>>>(sentpres, tw_ih_b, tb_b, gtag + BN_ * G4_, BN_, D2_, G4_, 1, 0);

    // Persistent tag BiLSTM
    cudaMemsetAsync(barp, 0, 2 * sizeof(int));
    lstm_tag_pers<<<dim3(8, 2), 256, TAGP_SMEM>>>(gtag, whhT_t, htag, tago);

    // GCN
    gcn_kernel<<<32, 256, GCN_SMEM>>>(tago, agg);
    sgemm_k<<<dim3(4, 32), 256>>>(agg, sage_W, sage_b, gcn_out, BN_, D2_, D2_, 0, 1);

    // roleFt SPP
    sgemm_k<<<dim3(4, 32), 256>>>(tago, rf_Wq, rf_bq, qb, BN_, D2_, D2_, 0, 0);
    sgemm_k<<<dim3(4, 32), 256>>>(tago, rf_Wk, rf_bk, kb, BN_, D2_, D2_, 0, 0);
    spp_kernel<<<2048, 64>>>(qb, kb, rFt);

    cls_kernel<<<2048, 32>>>(tago, sFt, rFt, cls_W, cls_b, result_out);

    (void)in_sizes; (void)n_in; (void)out_size;
}

// round 8
// speedup vs baseline: 3.4982x; 1.1919x over previous
#include <cuda_runtime.h>
#include <cuda_bf16.h>
#include <stdint.h>
#include <math.h>

// ---------------- problem constants ----------------
#define B_    32
#define N_    64
#define T_    50
#define WD_   200
#define H_    128
#define G4_   512
#define D2_   256
#define BN_   2048
#define C_    8

// ---------------- scratch ----------------
__device__ uint4 wih_pk_buf[2 * 13 * 64 * 32];   // packed W_ih tf32 B-frags [dir][kt][ng][lane]
__device__ uint4 whh_pk_buf[2 * 8 * 64 * 32];    // packed sent W_hh tf32 B-frags
__device__ uint4 whh_tag_pk_buf[2 * 8 * 64 * 32];// packed tag  W_hh tf32 B-frags
__device__ float sentpres_buf[BN_ * D2_];
__device__ float q_buf[BN_ * D2_];
__device__ float k_buf[BN_ * D2_];
__device__ float sentFt_buf[BN_ * 15];
__device__ float roleFt_buf[BN_ * 15];
__device__ float g_tag_buf[2 * BN_ * G4_];
__device__ float tag_out_buf[BN_ * D2_];
__device__ float agg_buf[BN_ * D2_];

__device__ __forceinline__ float sigf(float x) { return __fdividef(1.0f, 1.0f + __expf(-x)); }

#define MMA_TF32(d, a, b) \
    asm volatile("mma.sync.aligned.m16n8k8.row.col.f32.tf32.tf32.f32 " \
                 "{%0,%1,%2,%3},{%4,%5,%6,%7},{%8,%9},{%0,%1,%2,%3};\n" \
                 : "+f"(d[0]), "+f"(d[1]), "+f"(d[2]), "+f"(d[3]) \
                 : "r"(a[0]), "r"(a[1]), "r"(a[2]), "r"(a[3]), "r"(b[0]), "r"(b[1]))

__device__ __forceinline__ void ldsm_x4(unsigned& r0, unsigned& r1, unsigned& r2, unsigned& r3,
                                        const float* p)
{
    unsigned addr = (unsigned)__cvta_generic_to_shared(p);
    asm volatile("ldmatrix.sync.aligned.m8n8.x4.shared.b16 {%0,%1,%2,%3}, [%4];"
                 : "=r"(r0), "=r"(r1), "=r"(r2), "=r"(r3) : "r"(addr));
}

__device__ __forceinline__ void lda_frag(unsigned af[4], const float* base, int stride,
                                         int mrow0, int kcol0, int lane)
{
    int tile = lane >> 3, rin = lane & 7;
    int row = mrow0 + ((tile & 1) << 3) + rin;
    int col = kcol0 + ((tile >> 1) << 2);
    ldsm_x4(af[0], af[1], af[2], af[3], base + row * stride + col);
}

// ================== pack W_ih (512x200) into tf32 B-fragments ==================
__global__ void pack_wih_tf32(const float* __restrict__ wf, const float* __restrict__ wb,
                              uint4* __restrict__ out)
{
    int i = blockIdx.x * 256 + threadIdx.x;
    if (i >= 2 * 13 * 64 * 32) return;
    const int per = 13 * 64 * 32;
    int dir = i / per, rem = i % per;
    int kt = rem >> 11, ng = (rem >> 5) & 63, lane = rem & 31;
    const float* w = dir ? wb : wf;
    int n = ng * 8 + (lane >> 2);
    int k = kt * 16 + (lane & 3);
    uint4 v;
    v.x = (k      < WD_) ? __float_as_uint(w[n * WD_ + k])      : 0u;
    v.y = (k + 4  < WD_) ? __float_as_uint(w[n * WD_ + k + 4])  : 0u;
    v.z = (k + 8  < WD_) ? __float_as_uint(w[n * WD_ + k + 8])  : 0u;
    v.w = (k + 12 < WD_) ? __float_as_uint(w[n * WD_ + k + 12]) : 0u;
    out[i] = v;
}

// ================== pack a 512x128 W_hh into tf32 B-fragments ==================
__global__ void pack_whh_tf32(const float* __restrict__ wf, const float* __restrict__ wb,
                              uint4* __restrict__ out)
{
    int i = blockIdx.x * 256 + threadIdx.x;
    if (i >= 2 * 8 * 64 * 32) return;
    int lane = i & 31, ng = (i >> 5) & 63, kt = (i >> 11) & 7, dir = i >> 14;
    const float* w = dir ? wb : wf;
    int n = ng * 8 + (lane >> 2);
    int k = kt * 16 + (lane & 3);
    uint4 v;
    v.x = __float_as_uint(w[n * 128 + k]);
    v.y = __float_as_uint(w[n * 128 + k + 4]);
    v.z = __float_as_uint(w[n * 128 + k + 8]);
    v.w = __float_as_uint(w[n * 128 + k + 12]);
    out[i] = v;
}

// ================== FUSED sentence BiLSTM: pipelined tf32 mma ==================
#define SD_STR 212
#define SH_STR 132
#define OFF_SD0   0
#define OFF_SD1   6784
#define OFF_HH    13568
#define OFF_GG    17792
#define OFF_BIAS  34432
#define FUSED_SMEM ((34432 + 512) * 4)

__global__ __launch_bounds__(256, 1)
void lstm_sent_fused(const float* __restrict__ doc,
                     const uint4* __restrict__ wih, const uint4* __restrict__ whh,
                     const float* __restrict__ biasf, const float* __restrict__ biasb,
                     float* __restrict__ sentpres)
{
    extern __shared__ __align__(16) float smf[];
    float* sh_h  = smf + OFF_HH;    // [32][132]
    float* sh_g  = smf + OFF_GG;    // [32][520]
    float* sbias = smf + OFF_BIAS;  // [512]

    int dir = blockIdx.y;
    int r0 = blockIdx.x << 5;
    const uint4* wih0 = wih + dir * 13 * 64 * 32;
    const uint4* whh0 = whh + dir * 8 * 64 * 32;
    const float* bias = dir ? biasb : biasf;

    int tid = threadIdx.x, lane = tid & 31, w = tid >> 5;
    int gid = lane >> 2, qk = (lane & 3) << 1;
    int ur = tid >> 3, uj = (tid & 7) << 4;

    float c_reg[16], hs[16];
#pragma unroll
    for (int i = 0; i < 16; i++) { c_reg[i] = 0.f; hs[i] = 0.f; }
    for (int i = tid; i < 32 * SH_STR; i += 256) sh_h[i] = 0.f;
    for (int i = tid; i < 512; i += 256) sbias[i] = bias[i];

    {
        int t0 = dir ? (T_ - 1) : 0;
        for (int idx = tid; idx < 32 * 52; idx += 256) {
            int rr = idx / 52, c4 = idx - rr * 52;
            int k = c4 << 2;
            float4 v = (k < WD_)
                ? *(const float4*)(doc + ((size_t)(r0 + rr) * T_ + t0) * WD_ + k)
                : make_float4(0.f, 0.f, 0.f, 0.f);
            *(float4*)&smf[OFF_SD0 + rr * SD_STR + k] = v;
        }
    }
    __syncthreads();

    int buf = 0;
    for (int s = 0; s < T_; s++) {
        const float* sd = smf + (buf ? OFF_SD1 : OFF_SD0);

        float acc[2][8][4];
#pragma unroll
        for (int mt = 0; mt < 2; mt++)
#pragma unroll
            for (int nt = 0; nt < 8; nt++) {
                int col = w * 64 + nt * 8 + qk;
                float b0 = sbias[col], b1 = sbias[col + 1];
                acc[mt][nt][0] = b0; acc[mt][nt][1] = b1;
                acc[mt][nt][2] = b0; acc[mt][nt][3] = b1;
            }

        uint4 wv0[8], wv1[8];
        {
            const uint4* p = wih0 + (w * 8) * 32 + lane;
#pragma unroll
            for (int nt = 0; nt < 8; nt++) wv0[nt] = p[nt * 32];
        }

#define LOADW(dst, ktv) do { \
            int _kt = (ktv); \
            const uint4* _p = (_kt < 13) ? (wih0 + (_kt * 64 + w * 8) * 32 + lane) \
                                         : (whh0 + ((_kt - 13) * 64 + w * 8) * 32 + lane); \
            _Pragma("unroll") \
            for (int nt = 0; nt < 8; nt++) dst[nt] = _p[nt * 32]; \
        } while (0)

#define COMPUTE(ktv, wv) do { \
            int _kt = (ktv); \
            const float* _ab = (_kt < 13) ? sd : sh_h; \
            int _astr = (_kt < 13) ? SD_STR : SH_STR; \
            int _kc = (_kt < 13) ? (_kt << 4) : ((_kt - 13) << 4); \
            unsigned _af[2][2][4]; \
            _Pragma("unroll") \
            for (int mt = 0; mt < 2; mt++) { \
                lda_frag(_af[mt][0], _ab, _astr, mt * 16, _kc, lane); \
                lda_frag(_af[mt][1], _ab, _astr, mt * 16, _kc + 8, lane); \
            } \
            _Pragma("unroll") \
            for (int nt = 0; nt < 8; nt++) { \
                unsigned _b0[2] = { wv[nt].x, wv[nt].y }; \
                unsigned _b1[2] = { wv[nt].z, wv[nt].w }; \
                _Pragma("unroll") \
                for (int mt = 0; mt < 2; mt++) { \
                    MMA_TF32(acc[mt][nt], _af[mt][0], _b0); \
                    MMA_TF32(acc[mt][nt], _af[mt][1], _b1); \
                } \
            } \
        } while (0)

#pragma unroll 1
        for (int k2 = 0; k2 < 20; k2 += 2) {
            LOADW(wv1, k2 + 1);
            COMPUTE(k2, wv0);
            LOADW(wv0, k2 + 2);
            COMPUTE(k2 + 1, wv1);
        }
        COMPUTE(20, wv0);
#undef LOADW
#undef COMPUTE

#pragma unroll
        for (int mt = 0; mt < 2; mt++)
#pragma unroll
            for (int nt = 0; nt < 8; nt++) {
                int lrow = mt * 16 + gid;
                int col = w * 64 + nt * 8 + qk;
                *(float2*)&sh_g[lrow * 520 + col] = make_float2(acc[mt][nt][0], acc[mt][nt][1]);
                *(float2*)&sh_g[(lrow + 8) * 520 + col] = make_float2(acc[mt][nt][2], acc[mt][nt][3]);
            }

        if (s + 1 < T_) {
            int tn = dir ? (T_ - 2 - s) : (s + 1);
            float* sdn = smf + (buf ? OFF_SD0 : OFF_SD1);
            for (int idx = tid; idx < 32 * 52; idx += 256) {
                int rr = idx / 52, c4 = idx - rr * 52;
                int k = c4 << 2;
                float4 v = (k < WD_)
                    ? *(const float4*)(doc + ((size_t)(r0 + rr) * T_ + tn) * WD_ + k)
                    : make_float4(0.f, 0.f, 0.f, 0.f);
                *(float4*)&sdn[rr * SD_STR + k] = v;
            }
        }
        __syncthreads();

#pragma unroll
        for (int jj = 0; jj < 16; jj++) {
            int j = uj + jj;
            float ig = sh_g[ur * 520 + j];
            float fg = sh_g[ur * 520 + 128 + j];
            float gg = sh_g[ur * 520 + 256 + j];
            float og = sh_g[ur * 520 + 384 + j];
            float cv = sigf(fg) * c_reg[jj] + sigf(ig) * tanhf(gg);
            c_reg[jj] = cv;
            float h = sigf(og) * tanhf(cv);
            hs[jj] += h;
            sh_h[ur * SH_STR + j] = h;
        }
        __syncthreads();
        buf ^= 1;
    }
#pragma unroll
    for (int jj = 0; jj < 16; jj++)
        sentpres[(r0 + ur) * 256 + dir * 128 + uj + jj] = tanhf(hs[jj] * (1.0f / T_));
}

// ================== FUSED tag BiLSTM: one block per direction, tf32 mma ==================
// grid (2), 512 threads / 16 warps. M=32 batch, N=512 gates, K=128. No cross-block sync.
#define TAG2_SMEM ((32 * SH_STR + 32 * 520) * 4)
__global__ __launch_bounds__(512, 1)
void lstm_tag_fused(const float* __restrict__ Gt, const uint4* __restrict__ whhtag,
                    float* __restrict__ tag_out)
{
    extern __shared__ __align__(16) float smt[];
    float* sh_h = smt;                 // [32][132]
    float* sh_g = smt + 32 * SH_STR;   // [32][520]

    int dir = blockIdx.x;
    const uint4* wp0 = whhtag + dir * 8 * 64 * 32;
    const float* G0 = Gt + (size_t)dir * 2048 * 512;

    int tid = threadIdx.x, lane = tid & 31, w = tid >> 5;   // w: 0..15
    int gid = lane >> 2, qk = (lane & 3) << 1;
    int ur = tid >> 4, uj = (tid & 15) << 3;                // cell: row ur, cols uj..uj+7

    float c_reg[8];
#pragma unroll
    for (int i = 0; i < 8; i++) c_reg[i] = 0.f;
    for (int i = tid; i < 32 * SH_STR; i += 512) sh_h[i] = 0.f;
    __syncthreads();

    for (int s = 0; s < 64; s++) {
        int n = dir ? (63 - s) : s;
        const float* Gn = G0 + (size_t)(n * 32) * 512;

        // init acc from precomputed input projection (includes bias)
        float acc[2][4][4];
#pragma unroll
        for (int mt = 0; mt < 2; mt++) {
            const float* gr  = Gn + (size_t)(mt * 16 + gid) * 512;
            const float* gr8 = Gn + (size_t)(mt * 16 + gid + 8) * 512;
#pragma unroll
            for (int nt = 0; nt < 4; nt++) {
                int col = w * 32 + nt * 8 + qk;
                float2 v0 = *(const float2*)(gr + col);
                float2 v1 = *(const float2*)(gr8 + col);
                acc[mt][nt][0] = v0.x; acc[mt][nt][1] = v0.y;
                acc[mt][nt][2] = v1.x; acc[mt][nt][3] = v1.y;
            }
        }

        // h @ W_hh^T over 8 k-tiles, double-buffered W fragments
        uint4 wv0[4], wv1[4];
        {
            const uint4* p = wp0 + (w * 4) * 32 + lane;   // kt = 0
#pragma unroll
            for (int nt = 0; nt < 4; nt++) wv0[nt] = p[nt * 32];
        }
#pragma unroll 1
        for (int kt = 0; kt < 8; kt += 2) {
            {
                const uint4* p = wp0 + ((kt + 1) * 64 + w * 4) * 32 + lane;
#pragma unroll
                for (int nt = 0; nt < 4; nt++) wv1[nt] = p[nt * 32];
            }
            {
                unsigned af[2][2][4];
#pragma unroll
                for (int mt = 0; mt < 2; mt++) {
                    lda_frag(af[mt][0], sh_h, SH_STR, mt * 16, kt * 16,     lane);
                    lda_frag(af[mt][1], sh_h, SH_STR, mt * 16, kt * 16 + 8, lane);
                }
#pragma unroll
                for (int nt = 0; nt < 4; nt++) {
                    unsigned b0[2] = { wv0[nt].x, wv0[nt].y };
                    unsigned b1[2] = { wv0[nt].z, wv0[nt].w };
#pragma unroll
                    for (int mt = 0; mt < 2; mt++) {
                        MMA_TF32(acc[mt][nt], af[mt][0], b0);
                        MMA_TF32(acc[mt][nt], af[mt][1], b1);
                    }
                }
            }
            if (kt + 2 < 8) {
                const uint4* p = wp0 + ((kt + 2) * 64 + w * 4) * 32 + lane;
#pragma unroll
                for (int nt = 0; nt < 4; nt++) wv0[nt] = p[nt * 32];
            }
            {
                unsigned af[2][2][4];
#pragma unroll
                for (int mt = 0; mt < 2; mt++) {
                    lda_frag(af[mt][0], sh_h, SH_STR, mt * 16, (kt + 1) * 16,     lane);
                    lda_frag(af[mt][1], sh_h, SH_STR, mt * 16, (kt + 1) * 16 + 8, lane);
                }
#pragma unroll
                for (int nt = 0; nt < 4; nt++) {
                    unsigned b0[2] = { wv1[nt].x, wv1[nt].y };
                    unsigned b1[2] = { wv1[nt].z, wv1[nt].w };
#pragma unroll
                    for (int mt = 0; mt < 2; mt++) {
                        MMA_TF32(acc[mt][nt], af[mt][0], b0);
                        MMA_TF32(acc[mt][nt], af[mt][1], b1);
                    }
                }
            }
        }

        // scatter gates
#pragma unroll
        for (int mt = 0; mt < 2; mt++)
#pragma unroll
            for (int nt = 0; nt < 4; nt++) {
                int lrow = mt * 16 + gid;
                int col = w * 32 + nt * 8 + qk;
                *(float2*)&sh_g[lrow * 520 + col] = make_float2(acc[mt][nt][0], acc[mt][nt][1]);
                *(float2*)&sh_g[(lrow + 8) * 520 + col] = make_float2(acc[mt][nt][2], acc[mt][nt][3]);
            }
        __syncthreads();

        // cell update: thread owns (ur, uj..uj+7)
#pragma unroll
        for (int jj = 0; jj < 8; jj++) {
            int j = uj + jj;
            float ig = sh_g[ur * 520 + j];
            float fg = sh_g[ur * 520 + 128 + j];
            float gg = sh_g[ur * 520 + 256 + j];
            float og = sh_g[ur * 520 + 384 + j];
            float cv = sigf(fg) * c_reg[jj] + sigf(ig) * tanhf(gg);
            c_reg[jj] = cv;
            float h = sigf(og) * tanhf(cv);
            sh_h[ur * SH_STR + j] = h;
            tag_out[(size_t)(ur * 64 + n) * 256 + dir * 128 + j] = tanhf(h);
        }
        __syncthreads();
    }
}

// ================== generic tiled SGEMM (small GEMMs, fp32) ==================
__global__ void sgemm_k(const float* __restrict__ A, const float* __restrict__ W,
                        const float* __restrict__ bias, float* __restrict__ C,
                        int M, int K, int G, int amode, int relu)
{
    __shared__ float As[8][64];
    __shared__ float Ws[8][64];
    int tid = threadIdx.x;
    int mb = blockIdx.y << 6;
    int gb = blockIdx.x << 6;
    int tx = tid & 15, ty = tid >> 4;
    int mi = tid & 63;
    int kh = (tid >> 6) << 1;

    int m = mb + mi;
    long arow;
    if (amode == 0) arow = (long)m * K;
    else { int b = m & 31; int n = m >> 5; arow = (long)((b << 6) + n) * K; }
    long wrow = (long)(gb + mi) * K;

    float acc[4][4];
#pragma unroll
    for (int i = 0; i < 4; i++)
#pragma unroll
        for (int j = 0; j < 4; j++) acc[i][j] = 0.0f;

    for (int k0 = 0; k0 < K; k0 += 8) {
        float2 av = *(const float2*)(A + arow + k0 + kh);
        float2 wv = *(const float2*)(W + wrow + k0 + kh);
        __syncthreads();
        As[kh][mi] = av.x; As[kh + 1][mi] = av.y;
        Ws[kh][mi] = wv.x; Ws[kh + 1][mi] = wv.y;
        __syncthreads();
#pragma unroll
        for (int kk = 0; kk < 8; kk++) {
            float4 a = *(float4*)(&As[kk][ty << 2]);
            float4 w = *(float4*)(&Ws[kk][tx << 2]);
            float aa[4] = {a.x, a.y, a.z, a.w};
            float ww[4] = {w.x, w.y, w.z, w.w};
#pragma unroll
            for (int i = 0; i < 4; i++)
#pragma unroll
                for (int j = 0; j < 4; j++) acc[i][j] += aa[i] * ww[j];
        }
    }

    float4 b4 = *(const float4*)(bias + gb + (tx << 2));
    float bb[4] = {b4.x, b4.y, b4.z, b4.w};
#pragma unroll
    for (int i = 0; i < 4; i++) {
        float4 r;
        r.x = acc[i][0] + bb[0];
        r.y = acc[i][1] + bb[1];
        r.z = acc[i][2] + bb[2];
        r.w = acc[i][3] + bb[3];
        if (relu) {
            r.x = fmaxf(r.x, 0.f); r.y = fmaxf(r.y, 0.f);
            r.z = fmaxf(r.z, 0.f); r.w = fmaxf(r.w, 0.f);
        }
        *(float4*)(C + (size_t)(mb + (ty << 2) + i) * G + gb + (tx << 2)) = r;
    }
}

// ================== SPP ==================
__global__ void spp_kernel(const float* __restrict__ q, const float* __restrict__ k,
                           float* __restrict__ out)
{
    int bn = blockIdx.x;
    int b = bn >> 6;
    __shared__ float shq[256];
    __shared__ float att[64];
    __shared__ float e8[8];
    int tid = threadIdx.x;
    for (int l = tid; l < 256; l += 64) shq[l] = q[(size_t)bn * 256 + l];
    __syncthreads();
    const float* kr = k + (size_t)(b * 64 + tid) * 256;
    float s = 0.f;
    for (int l = 0; l < 256; l += 4) {
        float4 qa = *(float4*)&shq[l];
        float4 ka = *(const float4*)&kr[l];
        s += qa.x * ka.x + qa.y * ka.y + qa.z * ka.z + qa.w * ka.w;
    }
    att[tid] = s * 0.0625f;
    __syncthreads();
    if (tid < 8) {
        float m = att[tid * 8];
#pragma unroll
        for (int l = 1; l < 8; l++) m = fmaxf(m, att[tid * 8 + l]);
        e8[tid] = m;
    }
    __syncthreads();
    if (tid == 0) {
        float q4[4];
#pragma unroll
        for (int l = 0; l < 4; l++) q4[l] = fmaxf(e8[2 * l], e8[2 * l + 1]);
        float h2a = fmaxf(q4[0], q4[1]);
        float h2b = fmaxf(q4[2], q4[3]);
        float* o = out + bn * 15;
        o[0] = fmaxf(h2a, h2b);
        o[1] = h2a; o[2] = h2b;
        o[3] = q4[0]; o[4] = q4[1]; o[5] = q4[2]; o[6] = q4[3];
#pragma unroll
        for (int l = 0; l < 8; l++) o[7 + l] = e8[l];
    }
}

// ================== GCN ==================
#define GCN_SMEM ((64 * 256 + 64 * 64 + 64) * 4)
__global__ void gcn_kernel(const float* __restrict__ x, float* __restrict__ agg)
{
    extern __shared__ float gs[];
    float* shx = gs;
    float* shc = gs + 16384;
    float* shn = gs + 20480;
    int b = blockIdx.x;
    int tid = threadIdx.x;
    for (int l = tid; l < 16384; l += 256) shx[l] = x[(size_t)b * 16384 + l];
    __syncthreads();
    if (tid < 64) {
        float s = 0.f;
        for (int l = 0; l < 256; l++) { float v = shx[tid * 256 + l]; s += v * v; }
        shn[tid] = sqrtf(s) + 1e-8f;
    }
    __syncthreads();
    for (int p = tid; p < 4096; p += 256) {
        int i = p >> 6, j = p & 63;
        float s = 0.f;
        for (int l = 0; l < 256; l++) s += shx[i * 256 + l] * shx[j * 256 + l];
        shc[p] = s / (shn[i] * shn[j]);
    }
    __syncthreads();
    for (int p = tid; p < 16384; p += 256) {
        int i = p >> 8, d = p & 255;
        float s = 2.0f * shx[i * 256 + d];
        for (int j = 0; j < 64; j++) s += shc[i * 64 + j] * shx[j * 256 + d];
        agg[(size_t)b * 16384 + p] = s * (1.0f / 66.0f);
    }
}

// ================== classifier + log_softmax ==================
__global__ void cls_kernel(const float* __restrict__ tago, const float* __restrict__ sFt,
                           const float* __restrict__ rFt, const float* __restrict__ W,
                           const float* __restrict__ bias, float* __restrict__ out)
{
    int bn = blockIdx.x;
    int c = threadIdx.x;
    __shared__ float sh[8];
    if (c < 8) {
        const float* w = W + c * 286;
        float s = bias[c];
        const float* t = tago + (size_t)bn * 256;
        for (int l = 0; l < 256; l++) s += t[l] * w[l];
        const float* sf = sFt + bn * 15;
        for (int l = 0; l < 15; l++) s += sf[l] * w[256 + l];
        const float* rf = rFt + bn * 15;
        for (int l = 0; l < 15; l++) s += rf[l] * w[271 + l];
        sh[c] = s;
    }
    __syncthreads();
    if (c < 8) {
        float m = sh[0];
#pragma unroll
        for (int l = 1; l < 8; l++) m = fmaxf(m, sh[l]);
        float se = 0.f;
#pragma unroll
        for (int l = 0; l < 8; l++) se += expf(sh[l] - m);
        out[bn * 8 + c] = sh[c] - m - logf(se);
    }
}

// ================== launch ==================
extern "C" void kernel_launch(void* const* d_in, const int* in_sizes, int n_in,
                              void* d_out, int out_size)
{
    const float* documents = (const float*)d_in[0];
    const float* sw_ih_f = (const float*)d_in[1];
    const float* sw_hh_f = (const float*)d_in[2];
    const float* sb_f    = (const float*)d_in[3];
    const float* sw_ih_b = (const float*)d_in[4];
    const float* sw_hh_b = (const float*)d_in[5];
    const float* sb_b    = (const float*)d_in[6];
    const float* sf_Wq = (const float*)d_in[7];
    const float* sf_bq = (const float*)d_in[8];
    const float* sf_Wk = (const float*)d_in[9];
    const float* sf_bk = (const float*)d_in[10];
    const float* rf_Wq = (const float*)d_in[11];
    const float* rf_bq = (const float*)d_in[12];
    const float* rf_Wk = (const float*)d_in[13];
    const float* rf_bk = (const float*)d_in[14];
    const float* tw_ih_f = (const float*)d_in[15];
    const float* tw_hh_f = (const float*)d_in[16];
    const float* tb_f    = (const float*)d_in[17];
    const float* tw_ih_b = (const float*)d_in[18];
    const float* tw_hh_b = (const float*)d_in[19];
    const float* tb_b    = (const float*)d_in[20];
    const float* sage_W = (const float*)d_in[21];
    const float* sage_b = (const float*)d_in[22];
    const float* cls_W  = (const float*)d_in[23];
    const float* cls_b  = (const float*)d_in[24];

    float* out = (float*)d_out;
    float* result_out = out;
    float* gcn_out = out + B_ * N_ * C_;

    float *sentpres, *qb, *kb, *sFt, *rFt, *gtag, *tago, *agg;
    uint4 *wihp, *whhp, *whhtagp;
    cudaGetSymbolAddress((void**)&wihp, wih_pk_buf);
    cudaGetSymbolAddress((void**)&whhp, whh_pk_buf);
    cudaGetSymbolAddress((void**)&whhtagp, whh_tag_pk_buf);
    cudaGetSymbolAddress((void**)&sentpres, sentpres_buf);
    cudaGetSymbolAddress((void**)&qb, q_buf);
    cudaGetSymbolAddress((void**)&kb, k_buf);
    cudaGetSymbolAddress((void**)&sFt, sentFt_buf);
    cudaGetSymbolAddress((void**)&rFt, roleFt_buf);
    cudaGetSymbolAddress((void**)&gtag, g_tag_buf);
    cudaGetSymbolAddress((void**)&tago, tag_out_buf);
    cudaGetSymbolAddress((void**)&agg, agg_buf);

    cudaFuncSetAttribute(lstm_sent_fused, cudaFuncAttributeMaxDynamicSharedMemorySize, FUSED_SMEM);
    cudaFuncSetAttribute(lstm_tag_fused, cudaFuncAttributeMaxDynamicSharedMemorySize, TAG2_SMEM);
    cudaFuncSetAttribute(gcn_kernel, cudaFuncAttributeMaxDynamicSharedMemorySize, GCN_SMEM);

    // prep
    pack_wih_tf32<<<(2 * 13 * 64 * 32 + 255) / 256, 256>>>(sw_ih_f, sw_ih_b, wihp);
    pack_whh_tf32<<<128, 256>>>(sw_hh_f, sw_hh_b, whhp);
    pack_whh_tf32<<<128, 256>>>(tw_hh_f, tw_hh_b, whhtagp);

    // FUSED sentence BiLSTM (index 3 — ncu capture slot)
    lstm_sent_fused<<<dim3(64, 2), 256, FUSED_SMEM>>>(documents, wihp, whhp, sb_f, sb_b, sentpres);

    // sentFt SPP
    sgemm_k<<<dim3(4, 32), 256>>>(sentpres, sf_Wq, sf_bq, qb, BN_, D2_, D2_, 0, 0);
    sgemm_k<<<dim3(4, 32), 256>>>(sentpres, sf_Wk, sf_bk, kb, BN_, D2_, D2_, 0, 0);
    spp_kernel<<<2048, 64>>>(qb, kb, sFt);

    // Tag LSTM input projections (rows m = n*32 + b gathered from sentpres; bias folded in)
    sgemm_k<<<dim3(8, 32), 256>>>(sentpres, tw_ih_f, tb_f, gtag,             BN_, D2_, G4_, 1, 0);
    sgemm_k<<<dim3(8, 32), 256>>>(sentpres, tw_ih_b, tb_b, gtag + BN_ * G4_, BN_, D2_, G4_, 1, 0);

    // FUSED tag BiLSTM — one block per direction, no cross-block sync
    lstm_tag_fused<<<2, 512, TAG2_SMEM>>>(gtag, whhtagp, tago);

    // GCN
    gcn_kernel<<<32, 256, GCN_SMEM>>>(tago, agg);
    sgemm_k<<<dim3(4, 32), 256>>>(agg, sage_W, sage_b, gcn_out, BN_, D2_, D2_, 0, 1);

    // roleFt SPP
    sgemm_k<<<dim3(4, 32), 256>>>(tago, rf_Wq, rf_bq, qb, BN_, D2_, D2_, 0, 0);
    sgemm_k<<<dim3(4, 32), 256>>>(tago, rf_Wk, rf_bk, kb, BN_, D2_, D2_, 0, 0);
    spp_kernel<<<2048, 64>>>(qb, kb, rFt);

    cls_kernel<<<2048, 32>>>(tago, sFt, rFt, cls_W, cls_b, result_out);

    (void)in_sizes; (void)n_in; (void)out_size;
}